// round 10
// baseline (speedup 1.0000x reference)
#include <cuda_runtime.h>
#include <cuda_fp16.h>
#include <math.h>
#include <stdint.h>

// ---------------------------------------------------------------------------
// Problem constants
// ---------------------------------------------------------------------------
static constexpr int B_    = 4;
static constexpr int NTOK  = 1040;   // 512 + 512 + 16
static constexpr int D_    = 1024;
static constexpr int H_    = 16;
static constexpr int DH_   = 64;
static constexpr int L_    = 4;
static constexpr int FF_   = 2730;
static constexpr int FF2_  = 5460;
static constexpr int ROWS  = B_ * NTOK;   // 4160
static constexpr int ACTLD = 2752;        // act cols (43 blocks x 64), padded

// ---------------------------------------------------------------------------
// Device scratch
// ---------------------------------------------------------------------------
__device__ float  g_tokens[B_ * NTOK * D_];
__device__ float2 g_stats [ROWS];                 // per-row (mu, rstd)
__device__ float  g_sim   [B_ * H_ * 4 * NTOK];   // pool sim only
__device__ float  g_poolq [4 * D_];
__device__ float  g_poolao[B_ * 4 * D_];
__device__ __half h_tok   [ROWS * D_];            // fp16 copy of residual stream
__device__ __half h_qkv   [ROWS * 3 * D_];
__device__ __half h_kv    [ROWS * 2 * D_];        // pool kv
__device__ __half h_ao    [ROWS * D_];
__device__ __half h_act   [(long long)ROWS * ACTLD];
// transposed fp16 weights (gamma folded where the A operand is LN'd)
__device__ __half h_wqkvT[(long long)L_ * 3 * D_ * D_];
__device__ __half h_woT  [L_ * D_ * D_];
__device__ __half h_ff1T [(long long)L_ * FF2_ * D_];
__device__ __half h_ff2T [(long long)L_ * D_ * ACTLD];   // pad rows stay zero
__device__ __half h_pkvT [2 * D_ * D_];

// ---------------------------------------------------------------------------
// Helpers
// ---------------------------------------------------------------------------
__device__ __forceinline__ uint32_t smem_u32(const void* p) {
    uint32_t a;
    asm("{ .reg .u64 t; cvta.to.shared.u64 t, %1; cvt.u32.u64 %0, t; }"
        : "=r"(a) : "l"(p));
    return a;
}

__device__ __forceinline__ void mma_f16(float* c, const uint32_t* a, const uint32_t* b) {
    asm volatile(
        "mma.sync.aligned.m16n8k16.row.col.f32.f16.f16.f32 "
        "{%0,%1,%2,%3}, {%4,%5,%6,%7}, {%8,%9}, {%0,%1,%2,%3};"
        : "+f"(c[0]), "+f"(c[1]), "+f"(c[2]), "+f"(c[3])
        : "r"(a[0]), "r"(a[1]), "r"(a[2]), "r"(a[3]), "r"(b[0]), "r"(b[1]));
}

#define LDSM4(d, addr)                                                         \
    asm volatile("ldmatrix.sync.aligned.m8n8.x4.shared.b16 {%0,%1,%2,%3}, [%4];" \
        : "=r"((d)[0]), "=r"((d)[1]), "=r"((d)[2]), "=r"((d)[3]) : "r"(addr))
#define LDSM4T(d, addr)                                                        \
    asm volatile("ldmatrix.sync.aligned.m8n8.x4.trans.shared.b16 {%0,%1,%2,%3}, [%4];" \
        : "=r"((d)[0]), "=r"((d)[1]), "=r"((d)[2]), "=r"((d)[3]) : "r"(addr))

__device__ __forceinline__ void cp16h(uint32_t dst, const __half* src, int bytes) {
    asm volatile("cp.async.cg.shared.global [%0], [%1], 16, %2;"
                 :: "r"(dst), "l"(src), "r"(bytes));
}
#define CP_COMMIT() asm volatile("cp.async.commit_group;" ::: "memory")
#define CP_WAIT1()  asm volatile("cp.async.wait_group 1;" ::: "memory")
#define CP_WAIT0()  asm volatile("cp.async.wait_group 0;" ::: "memory")

__device__ __forceinline__ uint32_t packh2(float x, float y) {
    __half2 h = __floats2half2_rn(x, y);
    return *(uint32_t*)&h;
}
__device__ __forceinline__ float gelu_exact(float g) {
    return 0.5f * g * (1.0f + erff(g * 0.70710678118654752f));
}

// ---------------------------------------------------------------------------
// Flash attention (block-masked).  qkv: [B*NTOK][3072] fp16 (q pre-scaled),
// ao: [B*NTOK][1024] fp16.  grid (17, 1, B*H), 128 threads.
// ---------------------------------------------------------------------------
__global__ void __launch_bounds__(128, 2)
flash_kernel(const __half* __restrict__ qkv, __half* __restrict__ ao) {
    constexpr int LDS_ = 72;
    constexpr int QOFF = 0;
    constexpr int KOFF = 64 * LDS_;
    constexpr int VOFF = KOFF + 2 * 128 * LDS_;
    extern __shared__ __half sm[];
    const uint32_t sb = smem_u32(sm);

    const int tid = threadIdx.x;
    const int w = tid >> 5, lane = tid & 31;
    const int g = lane >> 2, t4 = lane & 3;
    const int q8 = lane >> 3, r8 = lane & 7;

    const int bh = blockIdx.z;
    const int b = bh >> 4, h = bh & 15;
    const int qb = blockIdx.x;
    int q0, c0, clen, qrows;
    if (qb < 16) { q0 = qb * 64; c0 = (qb < 8) ? 0 : 512; clen = 512; qrows = 64; }
    else         { q0 = 1024;  c0 = 0;  clen = NTOK;  qrows = 16; }

    const __half* qb_g = qkv + ((long)b * NTOK) * 3072 + h * 64;
    const __half* kb_g = qkv + ((long)b * NTOK) * 3072 + 1024 + h * 64;
    const __half* vb_g = qkv + ((long)b * NTOK) * 3072 + 2048 + h * 64;

    {
        int row = tid >> 1;
        int gr = q0 + row;
        int bytes = (row < qrows) ? 16 : 0;
        const __half* src = qb_g + (long)(bytes ? gr : 0) * 3072 + (tid & 1) * 32;
        uint32_t dst = sb + (QOFF + row * LDS_ + (tid & 1) * 32) * 2;
        #pragma unroll
        for (int e = 0; e < 4; e++)
            cp16h(dst + e * 16, src + e * 8, bytes);
    }

    const int T = (clen + 127) >> 7;
    int issued = 0;
    auto issueKV = [&](int t) {
        int buf = t & 1;
        int j = c0 + t * 128 + tid;
        int bytes = (j < c0 + clen) ? 16 : 0;
        const __half* ks = kb_g + (long)(bytes ? j : 0) * 3072;
        const __half* vs = vb_g + (long)(bytes ? j : 0) * 3072;
        uint32_t kd = sb + (KOFF + buf * 128 * LDS_ + tid * LDS_) * 2;
        uint32_t vd = sb + (VOFF + buf * 128 * LDS_ + tid * LDS_) * 2;
        #pragma unroll
        for (int ch = 0; ch < 8; ch++) cp16h(kd + ch * 16, ks + ch * 8, bytes);
        #pragma unroll
        for (int ch = 0; ch < 8; ch++) cp16h(vd + ch * 16, vs + ch * 8, bytes);
        CP_COMMIT();
        issued++;
    };
    issueKV(0);
    if (T > 1) issueKV(1);

    float m0 = -1e30f, m1 = -1e30f, l0 = 0.f, l1 = 0.f;
    float o[8][4];
    #pragma unroll
    for (int i = 0; i < 8; i++)
        #pragma unroll
        for (int q = 0; q < 4; q++) o[i][q] = 0.f;

    const int aIdx = (w * 16 + (q8 & 1) * 8 + r8) * LDS_ + (q8 >> 1) * 8;
    const int kIdx = ((q8 >> 1) * 8 + r8) * LDS_ + (q8 & 1) * 8;
    const int vIdx = ((q8 & 1) * 8 + r8) * LDS_ + (q8 >> 1) * 8;

    for (int t = 0; t < T; t++) {
        if (issued - (t + 1) >= 1) { CP_WAIT1(); } else { CP_WAIT0(); }
        __syncthreads();

        const uint32_t kb_s = sb + (KOFF + (t & 1) * 128 * LDS_) * 2;
        const uint32_t vb_s = sb + (VOFF + (t & 1) * 128 * LDS_) * 2;
        const uint32_t qs = sb + QOFF * 2;

        float s[16][4];
        #pragma unroll
        for (int i = 0; i < 16; i++)
            #pragma unroll
            for (int q = 0; q < 4; q++) s[i][q] = 0.f;

        #pragma unroll
        for (int ks = 0; ks < 4; ks++) {
            uint32_t af[4];
            LDSM4(af, qs + (aIdx + ks * 16) * 2);
            #pragma unroll
            for (int p = 0; p < 8; p++) {
                uint32_t d[4];
                LDSM4(d, kb_s + (kIdx + p * 16 * LDS_ + ks * 16) * 2);
                mma_f16(s[2 * p], af, d);
                mma_f16(s[2 * p + 1], af, d + 2);
            }
        }

        int lim = clen - t * 128;
        if (lim < 128) {
            #pragma unroll
            for (int nt = 0; nt < 16; nt++) {
                int cc = nt * 8 + 2 * t4;
                if (cc >= lim)     { s[nt][0] = -1e30f; s[nt][2] = -1e30f; }
                if (cc + 1 >= lim) { s[nt][1] = -1e30f; s[nt][3] = -1e30f; }
            }
        }

        float tm0 = -1e30f, tm1 = -1e30f;
        #pragma unroll
        for (int nt = 0; nt < 16; nt++) {
            tm0 = fmaxf(tm0, fmaxf(s[nt][0], s[nt][1]));
            tm1 = fmaxf(tm1, fmaxf(s[nt][2], s[nt][3]));
        }
        tm0 = fmaxf(tm0, __shfl_xor_sync(0xffffffffu, tm0, 1));
        tm0 = fmaxf(tm0, __shfl_xor_sync(0xffffffffu, tm0, 2));
        tm1 = fmaxf(tm1, __shfl_xor_sync(0xffffffffu, tm1, 1));
        tm1 = fmaxf(tm1, __shfl_xor_sync(0xffffffffu, tm1, 2));

        float nm0 = fmaxf(m0, tm0), nm1 = fmaxf(m1, tm1);
        float sc0 = __expf(m0 - nm0), sc1 = __expf(m1 - nm1);
        m0 = nm0; m1 = nm1;
        l0 *= sc0; l1 *= sc1;
        #pragma unroll
        for (int nt = 0; nt < 8; nt++) {
            o[nt][0] *= sc0; o[nt][1] *= sc0;
            o[nt][2] *= sc1; o[nt][3] *= sc1;
        }

        uint32_t pf[16][2];
        #pragma unroll
        for (int nt = 0; nt < 16; nt++) {
            float p0 = __expf(s[nt][0] - m0);
            float p1 = __expf(s[nt][1] - m0);
            float p2 = __expf(s[nt][2] - m1);
            float p3 = __expf(s[nt][3] - m1);
            l0 += p0 + p1; l1 += p2 + p3;
            pf[nt][0] = packh2(p0, p1);
            pf[nt][1] = packh2(p2, p3);
        }

        #pragma unroll
        for (int kv = 0; kv < 8; kv++) {
            uint32_t a[4] = { pf[2 * kv][0], pf[2 * kv][1],
                              pf[2 * kv + 1][0], pf[2 * kv + 1][1] };
            #pragma unroll
            for (int p = 0; p < 4; p++) {
                uint32_t d[4];
                LDSM4T(d, vb_s + (vIdx + kv * 16 * LDS_ + p * 16) * 2);
                mma_f16(o[2 * p], a, d);
                mma_f16(o[2 * p + 1], a, d + 2);
            }
        }

        __syncthreads();
        if (t + 2 < T) issueKV(t + 2);
    }

    l0 += __shfl_xor_sync(0xffffffffu, l0, 1);
    l0 += __shfl_xor_sync(0xffffffffu, l0, 2);
    l1 += __shfl_xor_sync(0xffffffffu, l1, 1);
    l1 += __shfl_xor_sync(0xffffffffu, l1, 2);
    float inv0 = 1.0f / l0, inv1 = 1.0f / l1;

    int lr0 = w * 16 + g, lr1 = lr0 + 8;
    __half* aob = ao + ((long)b * NTOK) * 1024 + h * 64;
    if (lr0 < qrows) {
        __half* rp = aob + (long)(q0 + lr0) * 1024 + 2 * t4;
        #pragma unroll
        for (int nt = 0; nt < 8; nt++)
            *(__half2*)(rp + nt * 8) = __floats2half2_rn(o[nt][0] * inv0, o[nt][1] * inv0);
    }
    if (lr1 < qrows) {
        __half* rp = aob + (long)(q0 + lr1) * 1024 + 2 * t4;
        #pragma unroll
        for (int nt = 0; nt < 8; nt++)
            *(__half2*)(rp + nt * 8) = __floats2half2_rn(o[nt][2] * inv1, o[nt][3] * inv1);
    }
}

// ---------------------------------------------------------------------------
// fp16 mma.sync GEMM: BM=128, BN=128, BK=32, warp tile 64x64,
// 128 threads (4 warps), 2 CTAs/SM, 3-stage cp.async + ldmatrix.
//   LNA=true: A operand is the raw fp16 token copy; per-row (mu, rstd) from
//   `stats` applied to A-fragments in registers (gamma pre-folded into B).
//   GEGLU=true: FF1 weight-column remap + fused gelu(gate)*val epilogue.
//   C16 (nullable): secondary fp16 output (residual stream copy).
// ---------------------------------------------------------------------------
template<bool OUTH, bool GEGLU, bool LNA>
__global__ void __launch_bounds__(128, 2)
hgemm(const __half* __restrict__ A, const __half* __restrict__ Bm,
      void* __restrict__ Cv, const float* __restrict__ Res,
      const float2* __restrict__ stats, __half* __restrict__ C16,
      int M, int N, int K, int lda, int ldb, int ldc,
      float alpha, int resRowMod, int ldres) {
    constexpr int MT = 4;          // 64 / 16
    constexpr int NT = 8;          // 64 / 8
    constexpr int A_ST_H = 128 * 40;
    constexpr int B_ST_H = 128 * 40;
    constexpr int ST_H   = A_ST_H + B_ST_H;

    extern __shared__ __align__(16) __half smem[];
    const uint32_t sb = smem_u32(smem);

    const int tid = threadIdx.x;
    const int wid = tid >> 5, lane = tid & 31;
    const int g = lane >> 2, t4 = lane & 3;
    const int wm = wid >> 1, wn = wid & 1;
    const int q8 = lane >> 3, r8 = lane & 7;

    const int rowBase = blockIdx.y * 128;
    const int colBase = blockIdx.x * 128;
    const int KC = (K + 31) >> 5;

    const int chA = tid & 3;
    const __half* aSrc[4];
    uint32_t aOff[4];
    bool aOk[4];
    #pragma unroll
    for (int e = 0; e < 4; e++) {
        int m = (tid >> 2) + 32 * e;
        int gr = rowBase + m;
        aOk[e] = gr < M;
        aSrc[e] = A + (long)(aOk[e] ? gr : 0) * lda + chA * 8;
        aOff[e] = (uint32_t)((m * 40 + chA * 8) * 2);
    }
    const __half* bSrc[4];
    uint32_t bOff[4];
    int bOkA[4];
    #pragma unroll
    for (int e = 0; e < 4; e++) {
        int n = (tid >> 2) + 32 * e;
        int gn = colBase + n;
        int srcRow;
        if (GEGLU) {
            int j = gn >> 4, ww = gn & 15;
            int f8 = j * 8 + (ww & 7);
            bOkA[e] = (f8 < FF_) ? 1 : 0;
            srcRow = (ww < 8) ? f8 : (FF_ + f8);
        } else {
            bOkA[e] = (gn < N) ? 1 : 0;
            srcRow = gn;
        }
        bSrc[e] = Bm + (long)(bOkA[e] ? srcRow : 0) * ldb + chA * 8;
        bOff[e] = (uint32_t)((n * 40 + chA * 8) * 2);
    }

    auto issue = [&](int c, int st) {
        const uint32_t stb = sb + (uint32_t)(st * ST_H * 2);
        int krem = K - (c << 5);
        int kb = (krem - chA * 8) * 2;
        kb = kb < 0 ? 0 : (kb > 16 ? 16 : kb);
        #pragma unroll
        for (int e = 0; e < 4; e++) {
            int bytes = aOk[e] ? kb : 0;
            cp16h(stb + aOff[e], bytes ? aSrc[e] : A, bytes);
            aSrc[e] += 32;
        }
        const uint32_t bstb = stb + (uint32_t)(A_ST_H * 2);
        #pragma unroll
        for (int e = 0; e < 4; e++) {
            int bytes = bOkA[e] ? kb : 0;
            cp16h(bstb + bOff[e], bytes ? bSrc[e] : Bm, bytes);
            bSrc[e] += 32;
        }
        CP_COMMIT();
    };

    // per-fragment LN constants (rows r0 = rowBase + wm*64 + mt*16 + g, r0+8)
    __half2 lnS[MT][2], lnB[MT][2];
    if (LNA) {
        #pragma unroll
        for (int mt = 0; mt < MT; mt++) {
            int r0 = rowBase + wm * 64 + mt * 16 + g;
            int r1 = r0 + 8;
            float2 s0 = stats[r0 < M ? r0 : (M - 1)];
            float2 s1 = stats[r1 < M ? r1 : (M - 1)];
            lnS[mt][0] = __float2half2_rn(s0.y);
            lnB[mt][0] = __float2half2_rn(-s0.x * s0.y);
            lnS[mt][1] = __float2half2_rn(s1.y);
            lnB[mt][1] = __float2half2_rn(-s1.x * s1.y);
        }
    }

    float acc[MT][NT][4];
    #pragma unroll
    for (int i = 0; i < MT; i++)
        #pragma unroll
        for (int j = 0; j < NT; j++)
            #pragma unroll
            for (int q = 0; q < 4; q++) acc[i][j][q] = 0.0f;

    const int aIdx0 = (wm * 64 + (q8 & 1) * 8 + r8) * 40 + (q8 >> 1) * 8;
    const int bIdx0 = (wn * 64 + (q8 >> 1) * 8 + r8) * 40 + (q8 & 1) * 8;

    issue(0, 0);
    issue(1, 1);

    int st = 0;
    for (int c = 0; c < KC; c++) {
        CP_WAIT1();
        __syncthreads();
        if (c + 2 < KC) issue(c + 2, (st + 2) % 3);
        else CP_COMMIT();

        const uint32_t aStB = sb + (uint32_t)(st * ST_H * 2);
        const uint32_t bStB = aStB + (uint32_t)(A_ST_H * 2);

        #pragma unroll
        for (int ks = 0; ks < 2; ks++) {
            uint32_t af[MT][4], bf[NT][2];
            #pragma unroll
            for (int mt = 0; mt < MT; mt++) {
                LDSM4(af[mt], aStB + (uint32_t)((aIdx0 + mt * 16 * 40 + ks * 16) * 2));
                if (LNA) {
                    __half2* ah = (__half2*)af[mt];
                    ah[0] = __hfma2(ah[0], lnS[mt][0], lnB[mt][0]);
                    ah[1] = __hfma2(ah[1], lnS[mt][1], lnB[mt][1]);
                    ah[2] = __hfma2(ah[2], lnS[mt][0], lnB[mt][0]);
                    ah[3] = __hfma2(ah[3], lnS[mt][1], lnB[mt][1]);
                }
            }
            #pragma unroll
            for (int p = 0; p < NT / 2; p++) {
                uint32_t d[4];
                LDSM4(d, bStB + (uint32_t)((bIdx0 + p * 16 * 40 + ks * 16) * 2));
                bf[2 * p][0] = d[0]; bf[2 * p][1] = d[1];
                bf[2 * p + 1][0] = d[2]; bf[2 * p + 1][1] = d[3];
            }
            #pragma unroll
            for (int mt = 0; mt < MT; mt++)
                #pragma unroll
                for (int nt = 0; nt < NT; nt++)
                    mma_f16(acc[mt][nt], af[mt], bf[nt]);
        }
        st++; if (st == 3) st = 0;
    }

    if (GEGLU) {
        __half* act = (__half*)Cv;
        const int actBase = (colBase >> 1) + wn * 32;
        #pragma unroll
        for (int mt = 0; mt < MT; mt++) {
            int r0 = rowBase + wm * 64 + mt * 16 + g;
            #pragma unroll
            for (int p = 0; p < NT / 2; p++) {
                int col = actBase + p * 8 + t4 * 2;
                #pragma unroll
                for (int hh = 0; hh < 2; hh++) {
                    int rr = r0 + hh * 8;
                    if (rr >= M) continue;
                    float v0 = acc[mt][2 * p][hh * 2];
                    float v1 = acc[mt][2 * p][hh * 2 + 1];
                    float g0 = acc[mt][2 * p + 1][hh * 2];
                    float g1 = acc[mt][2 * p + 1][hh * 2 + 1];
                    *(__half2*)(act + (long)rr * ldc + col) =
                        __floats2half2_rn(gelu_exact(g0) * v0, gelu_exact(g1) * v1);
                }
            }
        }
        return;
    }

    #pragma unroll
    for (int mt = 0; mt < MT; mt++) {
        int r0 = rowBase + wm * 64 + mt * 16 + g;
        #pragma unroll
        for (int nt = 0; nt < NT; nt++) {
            int col = colBase + wn * 64 + nt * 8 + t4 * 2;
            if (col >= N) continue;
            #pragma unroll
            for (int hh = 0; hh < 2; hh++) {
                int rr = r0 + hh * 8;
                if (rr >= M) continue;
                float vx = alpha * acc[mt][nt][hh * 2];
                float vy = alpha * acc[mt][nt][hh * 2 + 1];
                if (Res) {
                    int rx = resRowMod ? (rr % resRowMod) : rr;
                    float2 rv = *(const float2*)(Res + (long)rx * ldres + col);
                    vx += rv.x; vy += rv.y;
                }
                if (OUTH) {
                    *(__half2*)((__half*)Cv + (long)rr * ldc + col) = __floats2half2_rn(vx, vy);
                } else {
                    float2 v; v.x = vx; v.y = vy;
                    *(float2*)((float*)Cv + (long)rr * ldc + col) = v;
                    if (C16)
                        *(__half2*)(C16 + (long)rr * ldc + col) = __floats2half2_rn(vx, vy);
                }
            }
        }
    }
}

// ---------------------------------------------------------------------------
// Weight transpose: dst[z][n][k] = (half)(scale * rowScale[z*rsZ + k] * src[z][k][n])
// ---------------------------------------------------------------------------
__global__ void transpose_kernel(const float* __restrict__ src,
                                 __half* __restrict__ dst,
                                 int K, int N, int ldd,
                                 long srcZ, long dstZ, float scale,
                                 const float* __restrict__ rowScale, long rsZ) {
    __shared__ float tile[64][33];
    int k0 = blockIdx.y * 64, n0 = blockIdx.x * 32;
    long zS = (long)blockIdx.z * srcZ;
    long zD = (long)blockIdx.z * dstZ;
    const float* rs = rowScale ? rowScale + (long)blockIdx.z * rsZ : nullptr;
    int tx = threadIdx.x, ty = threadIdx.y;   // 32 x 8
    #pragma unroll
    for (int i = ty; i < 64; i += 8) {
        int k = k0 + i, n = n0 + tx;
        if (k < K && n < N) tile[i][tx] = src[zS + (long)k * N + n];
    }
    __syncthreads();
    #pragma unroll
    for (int i = ty; i < 32; i += 8) {
        int n = n0 + i, k = k0 + tx * 2;
        if (n < N && k + 1 < K) {
            float g0 = rs ? rs[k] : 1.0f;
            float g1 = rs ? rs[k + 1] : 1.0f;
            *(__half2*)(dst + zD + (long)n * ldd + k) =
                __floats2half2_rn(scale * g0 * tile[tx * 2][i],
                                  scale * g1 * tile[tx * 2 + 1][i]);
        }
    }
}

// ---------------------------------------------------------------------------
// Small SIMT GEMM (pool)
// ---------------------------------------------------------------------------
template<typename T>
__device__ __forceinline__ float ldf(const T* p) { return (float)*p; }
template<>
__device__ __forceinline__ float ldf<__half>(const __half* p) { return __half2float(*p); }

template<int BM, int BN, int BK, int TM, int TN, bool TB, typename TAT, typename TBT>
__global__ void __launch_bounds__((BM / TM) * (BN / TN))
gemm_kernel(const TAT* __restrict__ A, const TBT* __restrict__ Bm,
            float* __restrict__ C, const float* __restrict__ Res,
            int M, int Nn, int K,
            int lda, int ldb, int ldc,
            long sAb, long sAh, long sBb, long sBh, long sCb, long sCh, int Hdiv,
            float alpha, int resRowMod, int ldres) {
    constexpr int THREADS = (BM / TM) * (BN / TN);
    constexpr int AELEM = BM * BK / THREADS;
    constexpr int BELEM = BK * BN / THREADS;

    int z = blockIdx.z;
    int zb = z / Hdiv, zh = z - zb * Hdiv;
    A  += (long)zb * sAb + (long)zh * sAh;
    Bm += (long)zb * sBb + (long)zh * sBh;
    C  += (long)zb * sCb + (long)zh * sCh;

    __shared__ __align__(16) float As[BK][BM + 4];
    __shared__ __align__(16) float Bs[BK][BN + 4];

    int tid = threadIdx.x;
    int tcol = tid % (BN / TN);
    int trow = tid / (BN / TN);
    int rowBase = blockIdx.y * BM;
    int colBase = blockIdx.x * BN;

    float acc[TM][TN] = {};

    for (int k0 = 0; k0 < K; k0 += BK) {
        #pragma unroll
        for (int e = 0; e < AELEM; e++) {
            int idx = tid + e * THREADS;
            int m = idx / BK, kk = idx % BK;
            int gr = rowBase + m, gc = k0 + kk;
            As[kk][m] = (gr < M && gc < K) ? ldf(A + (long)gr * lda + gc) : 0.0f;
        }
        #pragma unroll
        for (int e = 0; e < BELEM; e++) {
            int idx = tid + e * THREADS;
            int kk, n;
            if (!TB) { kk = idx / BN; n = idx % BN; }
            else     { n = idx / BK;  kk = idx % BK; }
            int gc = colBase + n, gk = k0 + kk;
            float v = 0.0f;
            if (gc < Nn && gk < K)
                v = TB ? ldf(Bm + (long)gc * ldb + gk) : ldf(Bm + (long)gk * ldb + gc);
            Bs[kk][n] = v;
        }
        __syncthreads();

        #pragma unroll
        for (int kk = 0; kk < BK; kk++) {
            float a[TM], bb[TN];
            #pragma unroll
            for (int i = 0; i < TM; i++) a[i] = As[kk][trow * TM + i];
            #pragma unroll
            for (int j = 0; j < TN; j++) bb[j] = Bs[kk][tcol * TN + j];
            #pragma unroll
            for (int i = 0; i < TM; i++)
                #pragma unroll
                for (int j = 0; j < TN; j++)
                    acc[i][j] += a[i] * bb[j];
        }
        __syncthreads();
    }

    #pragma unroll
    for (int i = 0; i < TM; i++) {
        int r = rowBase + trow * TM + i;
        if (r >= M) continue;
        #pragma unroll
        for (int j = 0; j < TN; j++) {
            int c = colBase + tcol * TN + j;
            if (c >= Nn) continue;
            float v = alpha * acc[i][j];
            if (Res) {
                int rr = resRowMod ? (r % resRowMod) : r;
                v += Res[(long)rr * ldres + c];
            }
            C[(long)r * ldc + c] = v;
        }
    }
}

// ---------------------------------------------------------------------------
// Elementwise / reduction kernels
// ---------------------------------------------------------------------------
__device__ __forceinline__ float blk_reduce(float v, bool ismax) {
    __shared__ float red[9];
    #pragma unroll
    for (int o = 16; o; o >>= 1) {
        float u = __shfl_xor_sync(0xffffffffu, v, o);
        v = ismax ? fmaxf(v, u) : (v + u);
    }
    if ((threadIdx.x & 31) == 0) red[threadIdx.x >> 5] = v;
    __syncthreads();
    if (threadIdx.x == 0) {
        float r = red[0];
        int nw = blockDim.x >> 5;
        for (int w = 1; w < nw; w++) r = ismax ? fmaxf(r, red[w]) : (r + red[w]);
        red[8] = r;
    }
    __syncthreads();
    float r = red[8];
    __syncthreads();
    return r;
}

__device__ __forceinline__ int token_type(int j) {
    return j < 512 ? 0 : (j < 1024 ? 1 : 2);
}

// Concat: write fp32 tokens + fp16 copy
__global__ void concat_kernel(const float4* __restrict__ m0,
                              const float4* __restrict__ m1,
                              const float4* __restrict__ fus,
                              float4* __restrict__ tokens,
                              uint2* __restrict__ tok16) {
    int idx = blockIdx.x * blockDim.x + threadIdx.x;
    const int D4 = D_ / 4;
    int total = B_ * NTOK * D4;
    if (idx >= total) return;
    int d = idx % D4;
    int t = (idx / D4) % NTOK;
    int b = idx / (D4 * NTOK);
    float4 v;
    if (t < 512)       v = m0[((long)b * 512 + t) * D4 + d];
    else if (t < 1024) v = m1[((long)b * 512 + (t - 512)) * D4 + d];
    else               v = fus[(long)(t - 1024) * D4 + d];
    tokens[idx] = v;
    __half2 h0 = __floats2half2_rn(v.x, v.y);
    __half2 h1 = __floats2half2_rn(v.z, v.w);
    tok16[idx] = make_uint2(*(uint32_t*)&h0, *(uint32_t*)&h1);
}

// LN stats from fp16 token copy: stats[row] = (mu, rstd)
__global__ void ln_stats_kernel(const __half* __restrict__ x,
                                float2* __restrict__ stats) {
    long row = blockIdx.x;
    const __half2* xr = (const __half2*)(x + row * D_);
    float s = 0.f, s2 = 0.f;
    #pragma unroll
    for (int e = 0; e < 2; e++) {
        __half2 h = xr[threadIdx.x * 2 + e];
        float a = __low2float(h), b = __high2float(h);
        s += a + b;
        s2 += a * a + b * b;
    }
    s  = blk_reduce(s, false);
    s2 = blk_reduce(s2, false);
    if (threadIdx.x == 0) {
        float mu = s * (1.0f / D_);
        float var = s2 * (1.0f / D_) - mu * mu;
        stats[row] = make_float2(mu, rsqrtf(var + 1e-5f));
    }
}

__global__ void softmax_pool_kernel(float* __restrict__ sim) {
    long row = blockIdx.x;
    float* p = sim + row * NTOK;
    int r = (int)(row % 4);
    int tid = threadIdx.x;

    float vals[5];
    float mx = -3.4e38f;
    #pragma unroll
    for (int it = 0; it < 5; it++) {
        int j = tid + it * 256;
        float v = -3.4e38f;
        if (j < NTOK) {
            bool ok = (r == 3) || (token_type(j) == r);
            v = ok ? p[j] : -3.4e38f;
        }
        vals[it] = v;
        mx = fmaxf(mx, v);
    }
    mx = blk_reduce(mx, true);

    float e[5];
    float s = 0.0f;
    #pragma unroll
    for (int it = 0; it < 5; it++) {
        float ex = __expf(vals[it] - mx);
        e[it] = ex;
        s += ex;
    }
    s = blk_reduce(s, false);
    float inv = 1.0f / s;
    #pragma unroll
    for (int it = 0; it < 5; it++) {
        int j = tid + it * 256;
        if (j < NTOK) p[j] = e[it] * inv;
    }
}

// ---------------------------------------------------------------------------
// Host side
// ---------------------------------------------------------------------------
static constexpr int SM_H128  = 3 * (128 * 40 + 128 * 40) * 2;   // 61440
static constexpr int SM_FLASH = (64 * 72 + 4 * 128 * 72) * 2;    // 82944

extern "C" void kernel_launch(void* const* d_in, const int* in_sizes, int n_in,
                              void* d_out, int out_size) {
    const float* m0        = (const float*)d_in[0];
    const float* m1        = (const float*)d_in[1];
    const float* fusion    = (const float*)d_in[2];
    const float* ret_tok   = (const float*)d_in[3];
    const float* ln_gamma  = (const float*)d_in[4];
    const float* wq        = (const float*)d_in[5];
    const float* wkv       = (const float*)d_in[6];
    const float* wo        = (const float*)d_in[7];
    const float* ff_w1     = (const float*)d_in[8];
    const float* ff_w2     = (const float*)d_in[9];
    const float* pool_wq   = (const float*)d_in[10];
    const float* pool_wkv  = (const float*)d_in[11];
    const float* pool_wo   = (const float*)d_in[12];
    const float* final_g   = (const float*)d_in[13];
    float* out = (float*)d_out;

    cudaFuncSetAttribute(hgemm<true, false, true>,
                         cudaFuncAttributeMaxDynamicSharedMemorySize, SM_H128);
    cudaFuncSetAttribute(hgemm<true, false, false>,
                         cudaFuncAttributeMaxDynamicSharedMemorySize, SM_H128);
    cudaFuncSetAttribute(hgemm<false, false, false>,
                         cudaFuncAttributeMaxDynamicSharedMemorySize, SM_H128);
    cudaFuncSetAttribute(hgemm<true, true, true>,
                         cudaFuncAttributeMaxDynamicSharedMemorySize, SM_H128);
    cudaFuncSetAttribute(flash_kernel,
                         cudaFuncAttributeMaxDynamicSharedMemorySize, SM_FLASH);

    float *tokens, *simbuf, *poolq, *poolao;
    float2* stats;
    __half *tok16, *qkvbuf, *kvbuf, *aobuf, *actbuf;
    __half *wqkvT, *woT, *ff1T, *ff2T, *pkvT;
    cudaGetSymbolAddress((void**)&tokens, g_tokens);
    cudaGetSymbolAddress((void**)&stats,  g_stats);
    cudaGetSymbolAddress((void**)&simbuf, g_sim);
    cudaGetSymbolAddress((void**)&poolq,  g_poolq);
    cudaGetSymbolAddress((void**)&poolao, g_poolao);
    cudaGetSymbolAddress((void**)&tok16,  h_tok);
    cudaGetSymbolAddress((void**)&qkvbuf, h_qkv);
    cudaGetSymbolAddress((void**)&kvbuf,  h_kv);
    cudaGetSymbolAddress((void**)&aobuf,  h_ao);
    cudaGetSymbolAddress((void**)&actbuf, h_act);
    cudaGetSymbolAddress((void**)&wqkvT,  h_wqkvT);
    cudaGetSymbolAddress((void**)&woT,    h_woT);
    cudaGetSymbolAddress((void**)&ff1T,   h_ff1T);
    cudaGetSymbolAddress((void**)&ff2T,   h_ff2T);
    cudaGetSymbolAddress((void**)&pkvT,   h_pkvT);

    const float scale = 0.125f;

    // --- weight pre-transposes (fp32 -> fp16; LN gamma + q-scale folded) ---
    {
        dim3 thr(32, 8);
        const long zq = (long)3 * D_ * D_;
        transpose_kernel<<<dim3(32, 16, 4),  thr>>>(wq,  wqkvT, 1024, 1024, 1024,
                                                    (long)D_ * D_, zq, scale,
                                                    ln_gamma, D_);
        transpose_kernel<<<dim3(64, 16, 4),  thr>>>(wkv, wqkvT + (long)D_ * D_,
                                                    1024, 2048, 1024,
                                                    (long)2 * D_ * D_, zq, 1.0f,
                                                    ln_gamma, D_);
        transpose_kernel<<<dim3(32, 16, 4),  thr>>>(wo, woT, 1024, 1024, 1024,
                                                    (long)D_ * D_, (long)D_ * D_, 1.0f,
                                                    nullptr, 0);
        transpose_kernel<<<dim3(171, 16, 4), thr>>>(ff_w1, ff1T, 1024, 5460, 1024,
                                                    (long)D_ * FF2_, (long)FF2_ * D_, 1.0f,
                                                    ln_gamma, D_);
        transpose_kernel<<<dim3(32, 43, 4),  thr>>>(ff_w2, ff2T, 2730, 1024, ACTLD,
                                                    (long)FF_ * D_, (long)D_ * ACTLD, 1.0f,
                                                    nullptr, 0);
        transpose_kernel<<<dim3(64, 16, 1),  thr>>>(pool_wkv, pkvT, 1024, 2048, 1024,
                                                    0, 0, 1.0f, final_g, 0);
    }

    {
        int total = B_ * NTOK * (D_ / 4);
        concat_kernel<<<(total + 255) / 256, 256>>>(
            (const float4*)m0, (const float4*)m1, (const float4*)fusion,
            (float4*)tokens, (uint2*)tok16);
    }

    const long sKVB = (long)NTOK * 2 * D_;

    for (int l = 0; l < L_; l++) {
        const __half* wqkvT_l = wqkvT + (long)l * 3 * D_ * D_;
        const __half* woT_l   = woT   + (long)l * D_ * D_;
        const __half* w1T_l   = ff1T  + (long)l * FF2_ * D_;
        const __half* w2T_l   = ff2T  + (long)l * D_ * ACTLD;

        // attention block: stats -> QKV(LN fused) -> flash -> WO(+res, +fp16 copy)
        ln_stats_kernel<<<ROWS, 256>>>(tok16, stats);
        hgemm<true, false, true><<<dim3(24, 33, 1), 128, SM_H128>>>(
            tok16, wqkvT_l, qkvbuf, nullptr, stats, nullptr,
            ROWS, 3 * D_, D_, D_, D_, 3 * D_, 1.0f, 0, 0);
        flash_kernel<<<dim3(17, 1, B_ * H_), 128, SM_FLASH>>>(qkvbuf, aobuf);
        hgemm<false, false, false><<<dim3(8, 33, 1), 128, SM_H128>>>(
            aobuf, woT_l, tokens, tokens, nullptr, tok16,
            ROWS, D_, D_, D_, D_, D_, 1.0f, 0, D_);

        // feed-forward block: stats -> FF1+GEGLU(LN fused) -> FF2(+res, +fp16)
        ln_stats_kernel<<<ROWS, 256>>>(tok16, stats);
        hgemm<true, true, true><<<dim3(2 * ACTLD / 128, 33, 1), 128, SM_H128>>>(
            tok16, w1T_l, actbuf, nullptr, stats, nullptr,
            ROWS, 2 * ACTLD, D_, D_, D_, ACTLD, 1.0f, 0, 0);
        hgemm<false, false, false><<<dim3(8, 33, 1), 128, SM_H128>>>(
            actbuf, w2T_l, tokens, tokens, nullptr, tok16,
            ROWS, D_, FF_, ACTLD, ACTLD, D_, 1.0f, 0, D_);
    }

    // --- final LN (stats only; gamma folded into pkvT) + attention pooling ---
    ln_stats_kernel<<<ROWS, 256>>>(tok16, stats);

    gemm_kernel<64, 64, 16, 4, 4, false, float, float>
        <<<dim3(16, 1, 1), 256>>>(
        ret_tok, pool_wq, poolq, nullptr, 4, D_, D_, D_, D_, D_,
        0, 0, 0, 0, 0, 0, 1, scale, 0, 0);

    hgemm<true, false, true><<<dim3(16, 33, 1), 128, SM_H128>>>(
        tok16, pkvT, kvbuf, nullptr, stats, nullptr,
        ROWS, 2 * D_, D_, D_, D_, 2 * D_, 1.0f, 0, 0);

    gemm_kernel<64, 64, 16, 4, 4, true, float, __half>
        <<<dim3((NTOK + 63) / 64, 1, B_ * H_), 256>>>(
        poolq, kvbuf, simbuf, nullptr,
        4, NTOK, DH_, D_, 2 * D_, NTOK,
        0L, DH_, sKVB, DH_,
        (long)H_ * 4 * NTOK, (long)4 * NTOK, H_,
        1.0f, 0, 0);

    softmax_pool_kernel<<<B_ * H_ * 4, 256>>>(simbuf);

    gemm_kernel<64, 64, 16, 4, 4, false, float, __half>
        <<<dim3(1, 1, B_ * H_), 256>>>(
        simbuf, kvbuf + D_, poolao, nullptr,
        4, DH_, NTOK, NTOK, 2 * D_, D_,
        (long)H_ * 4 * NTOK, (long)4 * NTOK,
        sKVB, DH_,
        (long)4 * D_, DH_, H_,
        1.0f, 0, 0);

    gemm_kernel<64, 64, 16, 4, 4, false, float, float>
        <<<dim3(16, 1, 1), 256>>>(
        poolao, pool_wo, out, ret_tok, B_ * 4, D_, D_, D_, D_, D_,
        0, 0, 0, 0, 0, 0, 1, 1.0f, /*resRowMod=*/4, /*ldres=*/D_);
}

// round 11
// speedup vs baseline: 1.0125x; 1.0125x over previous
#include <cuda_runtime.h>
#include <cuda_fp16.h>
#include <math.h>
#include <stdint.h>

// ---------------------------------------------------------------------------
// Problem constants
// ---------------------------------------------------------------------------
static constexpr int B_    = 4;
static constexpr int NTOK  = 1040;   // 512 + 512 + 16
static constexpr int D_    = 1024;
static constexpr int H_    = 16;
static constexpr int DH_   = 64;
static constexpr int L_    = 4;
static constexpr int FF_   = 2730;
static constexpr int FF2_  = 5460;
static constexpr int ROWS  = B_ * NTOK;   // 4160
static constexpr int ACTLD = 2752;        // act cols (43 blocks x 64), padded

// ---------------------------------------------------------------------------
// Device scratch
// ---------------------------------------------------------------------------
__device__ float  g_tokens[B_ * NTOK * D_];
__device__ float  g_sim   [B_ * H_ * 4 * NTOK];   // pool sim only
__device__ float  g_poolq [4 * D_];
__device__ float  g_poolao[B_ * 4 * D_];
__device__ __half h_h     [ROWS * D_];
__device__ __half h_qkv   [ROWS * 3 * D_];
__device__ __half h_kv    [ROWS * 2 * D_];        // pool kv
__device__ __half h_ao    [ROWS * D_];
__device__ __half h_act   [(long long)ROWS * ACTLD];
// transposed fp16 weights
__device__ __half h_wqkvT[(long long)L_ * 3 * D_ * D_];
__device__ __half h_woT  [L_ * D_ * D_];
__device__ __half h_ff1T [(long long)L_ * FF2_ * D_];
__device__ __half h_ff2T [(long long)L_ * D_ * ACTLD];   // pad rows stay zero
__device__ __half h_pkvT [2 * D_ * D_];

// ---------------------------------------------------------------------------
// Helpers
// ---------------------------------------------------------------------------
__device__ __forceinline__ uint32_t smem_u32(const void* p) {
    uint32_t a;
    asm("{ .reg .u64 t; cvta.to.shared.u64 t, %1; cvt.u32.u64 %0, t; }"
        : "=r"(a) : "l"(p));
    return a;
}

__device__ __forceinline__ void mma_f16(float* c, const uint32_t* a, const uint32_t* b) {
    asm volatile(
        "mma.sync.aligned.m16n8k16.row.col.f32.f16.f16.f32 "
        "{%0,%1,%2,%3}, {%4,%5,%6,%7}, {%8,%9}, {%0,%1,%2,%3};"
        : "+f"(c[0]), "+f"(c[1]), "+f"(c[2]), "+f"(c[3])
        : "r"(a[0]), "r"(a[1]), "r"(a[2]), "r"(a[3]), "r"(b[0]), "r"(b[1]));
}

#define LDSM4(d, addr)                                                         \
    asm volatile("ldmatrix.sync.aligned.m8n8.x4.shared.b16 {%0,%1,%2,%3}, [%4];" \
        : "=r"((d)[0]), "=r"((d)[1]), "=r"((d)[2]), "=r"((d)[3]) : "r"(addr))
#define LDSM4T(d, addr)                                                        \
    asm volatile("ldmatrix.sync.aligned.m8n8.x4.trans.shared.b16 {%0,%1,%2,%3}, [%4];" \
        : "=r"((d)[0]), "=r"((d)[1]), "=r"((d)[2]), "=r"((d)[3]) : "r"(addr))

__device__ __forceinline__ void cp16h(uint32_t dst, const __half* src, int bytes) {
    asm volatile("cp.async.cg.shared.global [%0], [%1], 16, %2;"
                 :: "r"(dst), "l"(src), "r"(bytes));
}
#define CP_COMMIT() asm volatile("cp.async.commit_group;" ::: "memory")
#define CP_WAIT1()  asm volatile("cp.async.wait_group 1;" ::: "memory")
#define CP_WAIT0()  asm volatile("cp.async.wait_group 0;" ::: "memory")

__device__ __forceinline__ uint32_t packh2(float x, float y) {
    __half2 h = __floats2half2_rn(x, y);
    return *(uint32_t*)&h;
}
__device__ __forceinline__ float gelu_exact(float g) {
    return 0.5f * g * (1.0f + erff(g * 0.70710678118654752f));
}

// ---------------------------------------------------------------------------
// Flash attention (block-masked).  qkv: [B*NTOK][3072] fp16 (q pre-scaled),
// ao: [B*NTOK][1024] fp16.  grid (17, 1, B*H), 128 threads.
// ---------------------------------------------------------------------------
__global__ void __launch_bounds__(128, 2)
flash_kernel(const __half* __restrict__ qkv, __half* __restrict__ ao) {
    constexpr int LDS_ = 72;
    constexpr int QOFF = 0;
    constexpr int KOFF = 64 * LDS_;
    constexpr int VOFF = KOFF + 2 * 128 * LDS_;
    extern __shared__ __half sm[];
    const uint32_t sb = smem_u32(sm);

    const int tid = threadIdx.x;
    const int w = tid >> 5, lane = tid & 31;
    const int g = lane >> 2, t4 = lane & 3;
    const int q8 = lane >> 3, r8 = lane & 7;

    const int bh = blockIdx.z;
    const int b = bh >> 4, h = bh & 15;
    const int qb = blockIdx.x;
    int q0, c0, clen, qrows;
    if (qb < 16) { q0 = qb * 64; c0 = (qb < 8) ? 0 : 512; clen = 512; qrows = 64; }
    else         { q0 = 1024;  c0 = 0;  clen = NTOK;  qrows = 16; }

    const __half* qb_g = qkv + ((long)b * NTOK) * 3072 + h * 64;
    const __half* kb_g = qkv + ((long)b * NTOK) * 3072 + 1024 + h * 64;
    const __half* vb_g = qkv + ((long)b * NTOK) * 3072 + 2048 + h * 64;

    {
        int row = tid >> 1;
        int gr = q0 + row;
        int bytes = (row < qrows) ? 16 : 0;
        const __half* src = qb_g + (long)(bytes ? gr : 0) * 3072 + (tid & 1) * 32;
        uint32_t dst = sb + (QOFF + row * LDS_ + (tid & 1) * 32) * 2;
        #pragma unroll
        for (int e = 0; e < 4; e++)
            cp16h(dst + e * 16, src + e * 8, bytes);
    }

    const int T = (clen + 127) >> 7;
    int issued = 0;
    auto issueKV = [&](int t) {
        int buf = t & 1;
        int j = c0 + t * 128 + tid;
        int bytes = (j < c0 + clen) ? 16 : 0;
        const __half* ks = kb_g + (long)(bytes ? j : 0) * 3072;
        const __half* vs = vb_g + (long)(bytes ? j : 0) * 3072;
        uint32_t kd = sb + (KOFF + buf * 128 * LDS_ + tid * LDS_) * 2;
        uint32_t vd = sb + (VOFF + buf * 128 * LDS_ + tid * LDS_) * 2;
        #pragma unroll
        for (int ch = 0; ch < 8; ch++) cp16h(kd + ch * 16, ks + ch * 8, bytes);
        #pragma unroll
        for (int ch = 0; ch < 8; ch++) cp16h(vd + ch * 16, vs + ch * 8, bytes);
        CP_COMMIT();
        issued++;
    };
    issueKV(0);
    if (T > 1) issueKV(1);

    float m0 = -1e30f, m1 = -1e30f, l0 = 0.f, l1 = 0.f;
    float o[8][4];
    #pragma unroll
    for (int i = 0; i < 8; i++)
        #pragma unroll
        for (int q = 0; q < 4; q++) o[i][q] = 0.f;

    const int aIdx = (w * 16 + (q8 & 1) * 8 + r8) * LDS_ + (q8 >> 1) * 8;
    const int kIdx = ((q8 >> 1) * 8 + r8) * LDS_ + (q8 & 1) * 8;
    const int vIdx = ((q8 & 1) * 8 + r8) * LDS_ + (q8 >> 1) * 8;

    for (int t = 0; t < T; t++) {
        if (issued - (t + 1) >= 1) { CP_WAIT1(); } else { CP_WAIT0(); }
        __syncthreads();

        const uint32_t kb_s = sb + (KOFF + (t & 1) * 128 * LDS_) * 2;
        const uint32_t vb_s = sb + (VOFF + (t & 1) * 128 * LDS_) * 2;
        const uint32_t qs = sb + QOFF * 2;

        float s[16][4];
        #pragma unroll
        for (int i = 0; i < 16; i++)
            #pragma unroll
            for (int q = 0; q < 4; q++) s[i][q] = 0.f;

        #pragma unroll
        for (int ks = 0; ks < 4; ks++) {
            uint32_t af[4];
            LDSM4(af, qs + (aIdx + ks * 16) * 2);
            #pragma unroll
            for (int p = 0; p < 8; p++) {
                uint32_t d[4];
                LDSM4(d, kb_s + (kIdx + p * 16 * LDS_ + ks * 16) * 2);
                mma_f16(s[2 * p], af, d);
                mma_f16(s[2 * p + 1], af, d + 2);
            }
        }

        int lim = clen - t * 128;
        if (lim < 128) {
            #pragma unroll
            for (int nt = 0; nt < 16; nt++) {
                int cc = nt * 8 + 2 * t4;
                if (cc >= lim)     { s[nt][0] = -1e30f; s[nt][2] = -1e30f; }
                if (cc + 1 >= lim) { s[nt][1] = -1e30f; s[nt][3] = -1e30f; }
            }
        }

        float tm0 = -1e30f, tm1 = -1e30f;
        #pragma unroll
        for (int nt = 0; nt < 16; nt++) {
            tm0 = fmaxf(tm0, fmaxf(s[nt][0], s[nt][1]));
            tm1 = fmaxf(tm1, fmaxf(s[nt][2], s[nt][3]));
        }
        tm0 = fmaxf(tm0, __shfl_xor_sync(0xffffffffu, tm0, 1));
        tm0 = fmaxf(tm0, __shfl_xor_sync(0xffffffffu, tm0, 2));
        tm1 = fmaxf(tm1, __shfl_xor_sync(0xffffffffu, tm1, 1));
        tm1 = fmaxf(tm1, __shfl_xor_sync(0xffffffffu, tm1, 2));

        float nm0 = fmaxf(m0, tm0), nm1 = fmaxf(m1, tm1);
        float sc0 = __expf(m0 - nm0), sc1 = __expf(m1 - nm1);
        m0 = nm0; m1 = nm1;
        l0 *= sc0; l1 *= sc1;
        #pragma unroll
        for (int nt = 0; nt < 8; nt++) {
            o[nt][0] *= sc0; o[nt][1] *= sc0;
            o[nt][2] *= sc1; o[nt][3] *= sc1;
        }

        uint32_t pf[16][2];
        #pragma unroll
        for (int nt = 0; nt < 16; nt++) {
            float p0 = __expf(s[nt][0] - m0);
            float p1 = __expf(s[nt][1] - m0);
            float p2 = __expf(s[nt][2] - m1);
            float p3 = __expf(s[nt][3] - m1);
            l0 += p0 + p1; l1 += p2 + p3;
            pf[nt][0] = packh2(p0, p1);
            pf[nt][1] = packh2(p2, p3);
        }

        #pragma unroll
        for (int kv = 0; kv < 8; kv++) {
            uint32_t a[4] = { pf[2 * kv][0], pf[2 * kv][1],
                              pf[2 * kv + 1][0], pf[2 * kv + 1][1] };
            #pragma unroll
            for (int p = 0; p < 4; p++) {
                uint32_t d[4];
                LDSM4T(d, vb_s + (vIdx + kv * 16 * LDS_ + p * 16) * 2);
                mma_f16(o[2 * p], a, d);
                mma_f16(o[2 * p + 1], a, d + 2);
            }
        }

        __syncthreads();
        if (t + 2 < T) issueKV(t + 2);
    }

    l0 += __shfl_xor_sync(0xffffffffu, l0, 1);
    l0 += __shfl_xor_sync(0xffffffffu, l0, 2);
    l1 += __shfl_xor_sync(0xffffffffu, l1, 1);
    l1 += __shfl_xor_sync(0xffffffffu, l1, 2);
    float inv0 = 1.0f / l0, inv1 = 1.0f / l1;

    int lr0 = w * 16 + g, lr1 = lr0 + 8;
    __half* aob = ao + ((long)b * NTOK) * 1024 + h * 64;
    if (lr0 < qrows) {
        __half* rp = aob + (long)(q0 + lr0) * 1024 + 2 * t4;
        #pragma unroll
        for (int nt = 0; nt < 8; nt++)
            *(__half2*)(rp + nt * 8) = __floats2half2_rn(o[nt][0] * inv0, o[nt][1] * inv0);
    }
    if (lr1 < qrows) {
        __half* rp = aob + (long)(q0 + lr1) * 1024 + 2 * t4;
        #pragma unroll
        for (int nt = 0; nt < 8; nt++)
            *(__half2*)(rp + nt * 8) = __floats2half2_rn(o[nt][2] * inv1, o[nt][3] * inv1);
    }
}

// ---------------------------------------------------------------------------
// fp16 mma.sync GEMM: BM=128, BN=128, BK=64, warp tile 64x64,
// 128 threads (4 warps), 2 CTAs/SM, 3-stage cp.async + ldmatrix.
//   GEGLU=true: FF1 weight-column remap (8 val | 8 gate per 16) + fused
//   gelu(gate)*val epilogue writing fp16 act (ldc = ACTLD).
// Producer indices recomputed per issue (keeps register state small).
// ---------------------------------------------------------------------------
template<bool OUTH, bool GEGLU>
__global__ void __launch_bounds__(128, 2)
hgemm(const __half* __restrict__ A, const __half* __restrict__ Bm,
      void* __restrict__ Cv, const float* __restrict__ Res,
      int M, int N, int K, int lda, int ldb, int ldc,
      float alpha, int resRowMod, int ldres) {
    constexpr int MT = 4;          // 64 / 16
    constexpr int NT = 8;          // 64 / 8
    constexpr int A_ST_H = 128 * 72;
    constexpr int ST_H   = 2 * A_ST_H;      // halves per stage

    extern __shared__ __align__(16) __half smem[];
    const uint32_t sb = smem_u32(smem);

    const int tid = threadIdx.x;
    const int wid = tid >> 5, lane = tid & 31;
    const int g = lane >> 2, t4 = lane & 3;
    const int wm = wid >> 1, wn = wid & 1;
    const int q8 = lane >> 3, r8 = lane & 7;

    const int rowBase = blockIdx.y * 128;
    const int colBase = blockIdx.x * 128;
    const int KC = (K + 63) >> 6;

    const int chA = tid & 7;           // 8-half (16B) chunk within 64-half row
    const int rb8 = tid >> 3;          // row 0..15

    // B source rows (precomputed: small int state)
    int bRow[8];
    #pragma unroll
    for (int e = 0; e < 8; e++) {
        int n = rb8 + 16 * e;
        int gn = colBase + n;
        if (GEGLU) {
            int j = gn >> 4, ww = gn & 15;
            int f8 = j * 8 + (ww & 7);
            bRow[e] = (f8 < FF_) ? ((ww < 8) ? f8 : (FF_ + f8)) : -1;
        } else {
            bRow[e] = (gn < N) ? gn : -1;
        }
    }

    auto issue = [&](int c, int st) {
        const uint32_t stb = sb + (uint32_t)(st * ST_H * 2);
        const int k0 = c << 6;
        int krem = K - k0;
        int kb = (krem - chA * 8) * 2;
        kb = kb < 0 ? 0 : (kb > 16 ? 16 : kb);
        const int colOff = k0 + chA * 8;
        #pragma unroll
        for (int e = 0; e < 8; e++) {
            int m = rb8 + 16 * e;
            int gr = rowBase + m;
            int bytes = (gr < M) ? kb : 0;
            cp16h(stb + (uint32_t)((m * 72 + chA * 8) * 2),
                  bytes ? (A + (long)gr * lda + colOff) : A, bytes);
        }
        const uint32_t bstb = stb + (uint32_t)(A_ST_H * 2);
        #pragma unroll
        for (int e = 0; e < 8; e++) {
            int m = rb8 + 16 * e;
            int bytes = (bRow[e] >= 0) ? kb : 0;
            cp16h(bstb + (uint32_t)((m * 72 + chA * 8) * 2),
                  bytes ? (Bm + (long)bRow[e] * ldb + colOff) : Bm, bytes);
        }
        CP_COMMIT();
    };

    float acc[MT][NT][4];
    #pragma unroll
    for (int i = 0; i < MT; i++)
        #pragma unroll
        for (int j = 0; j < NT; j++)
            #pragma unroll
            for (int q = 0; q < 4; q++) acc[i][j][q] = 0.0f;

    const int aIdx0 = (wm * 64 + (q8 & 1) * 8 + r8) * 72 + (q8 >> 1) * 8;
    const int bIdx0 = (wn * 64 + (q8 >> 1) * 8 + r8) * 72 + (q8 & 1) * 8;

    issue(0, 0);
    issue(1, 1);

    int st = 0;
    for (int c = 0; c < KC; c++) {
        CP_WAIT1();
        __syncthreads();
        if (c + 2 < KC) issue(c + 2, (st + 2) % 3);
        else CP_COMMIT();

        const uint32_t aStB = sb + (uint32_t)(st * ST_H * 2);
        const uint32_t bStB = aStB + (uint32_t)(A_ST_H * 2);

        #pragma unroll
        for (int ks = 0; ks < 4; ks++) {
            uint32_t af[MT][4], bf[NT][2];
            #pragma unroll
            for (int mt = 0; mt < MT; mt++)
                LDSM4(af[mt], aStB + (uint32_t)((aIdx0 + mt * 16 * 72 + ks * 16) * 2));
            #pragma unroll
            for (int p = 0; p < NT / 2; p++) {
                uint32_t d[4];
                LDSM4(d, bStB + (uint32_t)((bIdx0 + p * 16 * 72 + ks * 16) * 2));
                bf[2 * p][0] = d[0]; bf[2 * p][1] = d[1];
                bf[2 * p + 1][0] = d[2]; bf[2 * p + 1][1] = d[3];
            }
            #pragma unroll
            for (int mt = 0; mt < MT; mt++)
                #pragma unroll
                for (int nt = 0; nt < NT; nt++)
                    mma_f16(acc[mt][nt], af[mt], bf[nt]);
        }
        st++; if (st == 3) st = 0;
    }

    if (GEGLU) {
        __half* act = (__half*)Cv;
        const int actBase = (colBase >> 1) + wn * 32;
        #pragma unroll
        for (int mt = 0; mt < MT; mt++) {
            int r0 = rowBase + wm * 64 + mt * 16 + g;
            #pragma unroll
            for (int p = 0; p < NT / 2; p++) {
                int col = actBase + p * 8 + t4 * 2;
                #pragma unroll
                for (int hh = 0; hh < 2; hh++) {
                    int rr = r0 + hh * 8;
                    if (rr >= M) continue;
                    float v0 = acc[mt][2 * p][hh * 2];
                    float v1 = acc[mt][2 * p][hh * 2 + 1];
                    float g0 = acc[mt][2 * p + 1][hh * 2];
                    float g1 = acc[mt][2 * p + 1][hh * 2 + 1];
                    *(__half2*)(act + (long)rr * ldc + col) =
                        __floats2half2_rn(gelu_exact(g0) * v0, gelu_exact(g1) * v1);
                }
            }
        }
        return;
    }

    #pragma unroll
    for (int mt = 0; mt < MT; mt++) {
        int r0 = rowBase + wm * 64 + mt * 16 + g;
        #pragma unroll
        for (int nt = 0; nt < NT; nt++) {
            int col = colBase + wn * 64 + nt * 8 + t4 * 2;
            if (col >= N) continue;
            #pragma unroll
            for (int hh = 0; hh < 2; hh++) {
                int rr = r0 + hh * 8;
                if (rr >= M) continue;
                float vx = alpha * acc[mt][nt][hh * 2];
                float vy = alpha * acc[mt][nt][hh * 2 + 1];
                if (Res) {
                    int rx = resRowMod ? (rr % resRowMod) : rr;
                    float2 rv = *(const float2*)(Res + (long)rx * ldres + col);
                    vx += rv.x; vy += rv.y;
                }
                if (OUTH) {
                    *(__half2*)((__half*)Cv + (long)rr * ldc + col) = __floats2half2_rn(vx, vy);
                } else {
                    float2 v; v.x = vx; v.y = vy;
                    *(float2*)((float*)Cv + (long)rr * ldc + col) = v;
                }
            }
        }
    }
}

// ---------------------------------------------------------------------------
// Weight transpose: dst[z][n][k] = (half)(scale * src[z][k][n])
// ---------------------------------------------------------------------------
__global__ void transpose_kernel(const float* __restrict__ src,
                                 __half* __restrict__ dst,
                                 int K, int N, int ldd,
                                 long srcZ, long dstZ, float scale) {
    __shared__ float tile[64][33];
    int k0 = blockIdx.y * 64, n0 = blockIdx.x * 32;
    long zS = (long)blockIdx.z * srcZ;
    long zD = (long)blockIdx.z * dstZ;
    int tx = threadIdx.x, ty = threadIdx.y;   // 32 x 8
    #pragma unroll
    for (int i = ty; i < 64; i += 8) {
        int k = k0 + i, n = n0 + tx;
        if (k < K && n < N) tile[i][tx] = src[zS + (long)k * N + n];
    }
    __syncthreads();
    #pragma unroll
    for (int i = ty; i < 32; i += 8) {
        int n = n0 + i, k = k0 + tx * 2;
        if (n < N && k + 1 < K)
            *(__half2*)(dst + zD + (long)n * ldd + k) =
                __floats2half2_rn(scale * tile[tx * 2][i], scale * tile[tx * 2 + 1][i]);
    }
}

// ---------------------------------------------------------------------------
// Small SIMT GEMM (pool)
// ---------------------------------------------------------------------------
template<typename T>
__device__ __forceinline__ float ldf(const T* p) { return (float)*p; }
template<>
__device__ __forceinline__ float ldf<__half>(const __half* p) { return __half2float(*p); }

template<int BM, int BN, int BK, int TM, int TN, bool TB, typename TAT, typename TBT>
__global__ void __launch_bounds__((BM / TM) * (BN / TN))
gemm_kernel(const TAT* __restrict__ A, const TBT* __restrict__ Bm,
            float* __restrict__ C, const float* __restrict__ Res,
            int M, int Nn, int K,
            int lda, int ldb, int ldc,
            long sAb, long sAh, long sBb, long sBh, long sCb, long sCh, int Hdiv,
            float alpha, int resRowMod, int ldres) {
    constexpr int THREADS = (BM / TM) * (BN / TN);
    constexpr int AELEM = BM * BK / THREADS;
    constexpr int BELEM = BK * BN / THREADS;

    int z = blockIdx.z;
    int zb = z / Hdiv, zh = z - zb * Hdiv;
    A  += (long)zb * sAb + (long)zh * sAh;
    Bm += (long)zb * sBb + (long)zh * sBh;
    C  += (long)zb * sCb + (long)zh * sCh;

    __shared__ __align__(16) float As[BK][BM + 4];
    __shared__ __align__(16) float Bs[BK][BN + 4];

    int tid = threadIdx.x;
    int tcol = tid % (BN / TN);
    int trow = tid / (BN / TN);
    int rowBase = blockIdx.y * BM;
    int colBase = blockIdx.x * BN;

    float acc[TM][TN] = {};

    for (int k0 = 0; k0 < K; k0 += BK) {
        #pragma unroll
        for (int e = 0; e < AELEM; e++) {
            int idx = tid + e * THREADS;
            int m = idx / BK, kk = idx % BK;
            int gr = rowBase + m, gc = k0 + kk;
            As[kk][m] = (gr < M && gc < K) ? ldf(A + (long)gr * lda + gc) : 0.0f;
        }
        #pragma unroll
        for (int e = 0; e < BELEM; e++) {
            int idx = tid + e * THREADS;
            int kk, n;
            if (!TB) { kk = idx / BN; n = idx % BN; }
            else     { n = idx / BK;  kk = idx % BK; }
            int gc = colBase + n, gk = k0 + kk;
            float v = 0.0f;
            if (gc < Nn && gk < K)
                v = TB ? ldf(Bm + (long)gc * ldb + gk) : ldf(Bm + (long)gk * ldb + gc);
            Bs[kk][n] = v;
        }
        __syncthreads();

        #pragma unroll
        for (int kk = 0; kk < BK; kk++) {
            float a[TM], bb[TN];
            #pragma unroll
            for (int i = 0; i < TM; i++) a[i] = As[kk][trow * TM + i];
            #pragma unroll
            for (int j = 0; j < TN; j++) bb[j] = Bs[kk][tcol * TN + j];
            #pragma unroll
            for (int i = 0; i < TM; i++)
                #pragma unroll
                for (int j = 0; j < TN; j++)
                    acc[i][j] += a[i] * bb[j];
        }
        __syncthreads();
    }

    #pragma unroll
    for (int i = 0; i < TM; i++) {
        int r = rowBase + trow * TM + i;
        if (r >= M) continue;
        #pragma unroll
        for (int j = 0; j < TN; j++) {
            int c = colBase + tcol * TN + j;
            if (c >= Nn) continue;
            float v = alpha * acc[i][j];
            if (Res) {
                int rr = resRowMod ? (r % resRowMod) : r;
                v += Res[(long)rr * ldres + c];
            }
            C[(long)r * ldc + c] = v;
        }
    }
}

// ---------------------------------------------------------------------------
// Elementwise / reduction kernels
// ---------------------------------------------------------------------------
__device__ __forceinline__ float blk_reduce(float v, bool ismax) {
    __shared__ float red[9];
    #pragma unroll
    for (int o = 16; o; o >>= 1) {
        float u = __shfl_xor_sync(0xffffffffu, v, o);
        v = ismax ? fmaxf(v, u) : (v + u);
    }
    if ((threadIdx.x & 31) == 0) red[threadIdx.x >> 5] = v;
    __syncthreads();
    if (threadIdx.x == 0) {
        float r = red[0];
        int nw = blockDim.x >> 5;
        for (int w = 1; w < nw; w++) r = ismax ? fmaxf(r, red[w]) : (r + red[w]);
        red[8] = r;
    }
    __syncthreads();
    float r = red[8];
    __syncthreads();
    return r;
}

__device__ __forceinline__ int token_type(int j) {
    return j < 512 ? 0 : (j < 1024 ? 1 : 2);
}

__global__ void concat_kernel(const float4* __restrict__ m0,
                              const float4* __restrict__ m1,
                              const float4* __restrict__ fus,
                              float4* __restrict__ tokens) {
    int idx = blockIdx.x * blockDim.x + threadIdx.x;
    const int D4 = D_ / 4;
    int total = B_ * NTOK * D4;
    if (idx >= total) return;
    int d = idx % D4;
    int t = (idx / D4) % NTOK;
    int b = idx / (D4 * NTOK);
    float4 v;
    if (t < 512)       v = m0[((long)b * 512 + t) * D4 + d];
    else if (t < 1024) v = m1[((long)b * 512 + (t - 512)) * D4 + d];
    else               v = fus[(long)(t - 1024) * D4 + d];
    tokens[idx] = v;
}

__global__ void ln_kernel(const float* __restrict__ x,
                          const float* __restrict__ gamma,
                          __half* __restrict__ out) {
    long row = blockIdx.x;
    const float4* xr = (const float4*)(x + row * D_);
    float4 v = xr[threadIdx.x];
    float s = v.x + v.y + v.z + v.w;
    float mean = blk_reduce(s, false) * (1.0f / D_);
    float dx = v.x - mean, dy = v.y - mean, dz = v.z - mean, dw = v.w - mean;
    float s2 = dx * dx + dy * dy + dz * dz + dw * dw;
    float var = blk_reduce(s2, false) * (1.0f / D_);
    float inv = rsqrtf(var + 1e-5f);
    float4 g = ((const float4*)gamma)[threadIdx.x];
    __half2* o = (__half2*)(out + row * D_);
    o[2 * threadIdx.x]     = __floats2half2_rn(dx * inv * g.x, dy * inv * g.y);
    o[2 * threadIdx.x + 1] = __floats2half2_rn(dz * inv * g.z, dw * inv * g.w);
}

__global__ void softmax_pool_kernel(float* __restrict__ sim) {
    long row = blockIdx.x;
    float* p = sim + row * NTOK;
    int r = (int)(row % 4);
    int tid = threadIdx.x;

    float vals[5];
    float mx = -3.4e38f;
    #pragma unroll
    for (int it = 0; it < 5; it++) {
        int j = tid + it * 256;
        float v = -3.4e38f;
        if (j < NTOK) {
            bool ok = (r == 3) || (token_type(j) == r);
            v = ok ? p[j] : -3.4e38f;
        }
        vals[it] = v;
        mx = fmaxf(mx, v);
    }
    mx = blk_reduce(mx, true);

    float e[5];
    float s = 0.0f;
    #pragma unroll
    for (int it = 0; it < 5; it++) {
        float ex = __expf(vals[it] - mx);
        e[it] = ex;
        s += ex;
    }
    s = blk_reduce(s, false);
    float inv = 1.0f / s;
    #pragma unroll
    for (int it = 0; it < 5; it++) {
        int j = tid + it * 256;
        if (j < NTOK) p[j] = e[it] * inv;
    }
}

// ---------------------------------------------------------------------------
// Host side
// ---------------------------------------------------------------------------
static constexpr int SM_H128  = 3 * (2 * 128 * 72) * 2;          // 110592
static constexpr int SM_FLASH = (64 * 72 + 4 * 128 * 72) * 2;    // 82944

static inline void hg(const __half* A, const __half* Bt, void* C, const float* Res,
                      int M, int Nn, int K, int lda, int ldbT, int ldc, float alpha,
                      bool outh, int resRowMod = 0, int ldres = 0) {
    dim3 grid((Nn + 127) / 128, (M + 127) / 128, 1);
    if (outh)
        hgemm<true, false><<<grid, 128, SM_H128>>>(
            A, Bt, C, Res, M, Nn, K, lda, ldbT, ldc, alpha, resRowMod, ldres);
    else
        hgemm<false, false><<<grid, 128, SM_H128>>>(
            A, Bt, C, Res, M, Nn, K, lda, ldbT, ldc, alpha, resRowMod, ldres);
}

extern "C" void kernel_launch(void* const* d_in, const int* in_sizes, int n_in,
                              void* d_out, int out_size) {
    const float* m0        = (const float*)d_in[0];
    const float* m1        = (const float*)d_in[1];
    const float* fusion    = (const float*)d_in[2];
    const float* ret_tok   = (const float*)d_in[3];
    const float* ln_gamma  = (const float*)d_in[4];
    const float* wq        = (const float*)d_in[5];
    const float* wkv       = (const float*)d_in[6];
    const float* wo        = (const float*)d_in[7];
    const float* ff_w1     = (const float*)d_in[8];
    const float* ff_w2     = (const float*)d_in[9];
    const float* pool_wq   = (const float*)d_in[10];
    const float* pool_wkv  = (const float*)d_in[11];
    const float* pool_wo   = (const float*)d_in[12];
    const float* final_g   = (const float*)d_in[13];
    float* out = (float*)d_out;

    cudaFuncSetAttribute(hgemm<true, false>,
                         cudaFuncAttributeMaxDynamicSharedMemorySize, SM_H128);
    cudaFuncSetAttribute(hgemm<false, false>,
                         cudaFuncAttributeMaxDynamicSharedMemorySize, SM_H128);
    cudaFuncSetAttribute(hgemm<true, true>,
                         cudaFuncAttributeMaxDynamicSharedMemorySize, SM_H128);
    cudaFuncSetAttribute(flash_kernel,
                         cudaFuncAttributeMaxDynamicSharedMemorySize, SM_FLASH);

    float *tokens, *simbuf, *poolq, *poolao;
    __half *hbuf, *qkvbuf, *kvbuf, *aobuf, *actbuf;
    __half *wqkvT, *woT, *ff1T, *ff2T, *pkvT;
    cudaGetSymbolAddress((void**)&tokens, g_tokens);
    cudaGetSymbolAddress((void**)&simbuf, g_sim);
    cudaGetSymbolAddress((void**)&poolq,  g_poolq);
    cudaGetSymbolAddress((void**)&poolao, g_poolao);
    cudaGetSymbolAddress((void**)&hbuf,   h_h);
    cudaGetSymbolAddress((void**)&qkvbuf, h_qkv);
    cudaGetSymbolAddress((void**)&kvbuf,  h_kv);
    cudaGetSymbolAddress((void**)&aobuf,  h_ao);
    cudaGetSymbolAddress((void**)&actbuf, h_act);
    cudaGetSymbolAddress((void**)&wqkvT,  h_wqkvT);
    cudaGetSymbolAddress((void**)&woT,    h_woT);
    cudaGetSymbolAddress((void**)&ff1T,   h_ff1T);
    cudaGetSymbolAddress((void**)&ff2T,   h_ff2T);
    cudaGetSymbolAddress((void**)&pkvT,   h_pkvT);

    const float scale = 0.125f;

    // --- weight pre-transposes (fp32 -> fp16; q-scale folded into wq) ---
    {
        dim3 thr(32, 8);
        const long zq = (long)3 * D_ * D_;
        transpose_kernel<<<dim3(32, 16, 4),  thr>>>(wq,  wqkvT, 1024, 1024, 1024,
                                                    (long)D_ * D_, zq, scale);
        transpose_kernel<<<dim3(64, 16, 4),  thr>>>(wkv, wqkvT + (long)D_ * D_,
                                                    1024, 2048, 1024,
                                                    (long)2 * D_ * D_, zq, 1.0f);
        transpose_kernel<<<dim3(32, 16, 4),  thr>>>(wo, woT, 1024, 1024, 1024,
                                                    (long)D_ * D_, (long)D_ * D_, 1.0f);
        transpose_kernel<<<dim3(171, 16, 4), thr>>>(ff_w1, ff1T, 1024, 5460, 1024,
                                                    (long)D_ * FF2_, (long)FF2_ * D_, 1.0f);
        transpose_kernel<<<dim3(32, 43, 4),  thr>>>(ff_w2, ff2T, 2730, 1024, ACTLD,
                                                    (long)FF_ * D_, (long)D_ * ACTLD, 1.0f);
        transpose_kernel<<<dim3(64, 16, 1),  thr>>>(pool_wkv, pkvT, 1024, 2048, 1024,
                                                    0, 0, 1.0f);
    }

    {
        int total = B_ * NTOK * (D_ / 4);
        concat_kernel<<<(total + 255) / 256, 256>>>(
            (const float4*)m0, (const float4*)m1, (const float4*)fusion,
            (float4*)tokens);
    }

    const long sKVB = (long)NTOK * 2 * D_;

    for (int l = 0; l < L_; l++) {
        const __half* wqkvT_l = wqkvT + (long)l * 3 * D_ * D_;
        const __half* woT_l   = woT   + (long)l * D_ * D_;
        const __half* w1T_l   = ff1T  + (long)l * FF2_ * D_;
        const __half* w2T_l   = ff2T  + (long)l * D_ * ACTLD;
        const float*  g_l     = ln_gamma + (long)l * D_;

        // attention block
        ln_kernel<<<ROWS, 256>>>(tokens, g_l, hbuf);
        hg(hbuf, wqkvT_l, qkvbuf, nullptr, ROWS, 3 * D_, D_, D_, D_, 3 * D_, 1.0f, true);
        flash_kernel<<<dim3(17, 1, B_ * H_), 128, SM_FLASH>>>(qkvbuf, aobuf);
        hg(aobuf, woT_l, tokens, tokens, ROWS, D_, D_, D_, D_, D_, 1.0f, false, 0, D_);

        // feed-forward block: FF1 + GEGLU fused
        ln_kernel<<<ROWS, 256>>>(tokens, g_l, hbuf);
        hgemm<true, true><<<dim3(2 * ACTLD / 128, (ROWS + 127) / 128, 1),
                            128, SM_H128>>>(
            hbuf, w1T_l, actbuf, nullptr,
            ROWS, 2 * ACTLD, D_, D_, D_, ACTLD, 1.0f, 0, 0);
        hg(actbuf, w2T_l, tokens, tokens, ROWS, D_, FF_, ACTLD, ACTLD, D_, 1.0f, false, 0, D_);
    }

    // --- final LN + attention pooling ---
    ln_kernel<<<ROWS, 256>>>(tokens, final_g, hbuf);

    gemm_kernel<64, 64, 16, 4, 4, false, float, float>
        <<<dim3(16, 1, 1), 256>>>(
        ret_tok, pool_wq, poolq, nullptr, 4, D_, D_, D_, D_, D_,
        0, 0, 0, 0, 0, 0, 1, scale, 0, 0);

    hg(hbuf, pkvT, kvbuf, nullptr, ROWS, 2 * D_, D_, D_, D_, 2 * D_, 1.0f, true);

    gemm_kernel<64, 64, 16, 4, 4, true, float, __half>
        <<<dim3((NTOK + 63) / 64, 1, B_ * H_), 256>>>(
        poolq, kvbuf, simbuf, nullptr,
        4, NTOK, DH_, D_, 2 * D_, NTOK,
        0L, DH_, sKVB, DH_,
        (long)H_ * 4 * NTOK, (long)4 * NTOK, H_,
        1.0f, 0, 0);

    softmax_pool_kernel<<<B_ * H_ * 4, 256>>>(simbuf);

    gemm_kernel<64, 64, 16, 4, 4, false, float, __half>
        <<<dim3(1, 1, B_ * H_), 256>>>(
        simbuf, kvbuf + D_, poolao, nullptr,
        4, DH_, NTOK, NTOK, 2 * D_, D_,
        (long)H_ * 4 * NTOK, (long)4 * NTOK,
        sKVB, DH_,
        (long)4 * D_, DH_, H_,
        1.0f, 0, 0);

    gemm_kernel<64, 64, 16, 4, 4, false, float, float>
        <<<dim3(16, 1, 1), 256>>>(
        poolao, pool_wo, out, ret_tok, B_ * 4, D_, D_, D_, D_, D_,
        0, 0, 0, 0, 0, 0, 1, 1.0f, /*resRowMod=*/4, /*ldres=*/D_);
}

// round 12
// speedup vs baseline: 1.0813x; 1.0679x over previous
#include <cuda_runtime.h>
#include <cuda_fp16.h>
#include <math.h>
#include <stdint.h>

// ---------------------------------------------------------------------------
// Problem constants
// ---------------------------------------------------------------------------
static constexpr int B_    = 4;
static constexpr int NTOK  = 1040;   // 512 + 512 + 16
static constexpr int D_    = 1024;
static constexpr int H_    = 16;
static constexpr int DH_   = 64;
static constexpr int L_    = 4;
static constexpr int FF_   = 2730;
static constexpr int FF2_  = 5460;
static constexpr int ROWS  = B_ * NTOK;   // 4160
static constexpr int ACTLD = 2752;        // act cols (43 blocks x 64), padded

// ---------------------------------------------------------------------------
// Device scratch
// ---------------------------------------------------------------------------
__device__ float  g_tokens[B_ * NTOK * D_];
__device__ float  g_poolq [4 * D_];
__device__ float  g_poolao[B_ * 4 * D_];
__device__ __half h_tok   [ROWS * D_];            // fp16 residual copy (LN input)
__device__ __half h_h     [ROWS * D_];
__device__ __half h_qkv   [ROWS * 3 * D_];
__device__ __half h_kv    [ROWS * 2 * D_];        // pool kv
__device__ __half h_ao    [ROWS * D_];
__device__ __half h_act   [(long long)ROWS * ACTLD];
// transposed fp16 weights
__device__ __half h_wqkvT[(long long)L_ * 3 * D_ * D_];
__device__ __half h_woT  [L_ * D_ * D_];
__device__ __half h_ff1T [(long long)L_ * FF2_ * D_];
__device__ __half h_ff2T [(long long)L_ * D_ * ACTLD];   // pad rows stay zero
__device__ __half h_pkvT [2 * D_ * D_];

// ---------------------------------------------------------------------------
// Helpers
// ---------------------------------------------------------------------------
__device__ __forceinline__ uint32_t smem_u32(const void* p) {
    uint32_t a;
    asm("{ .reg .u64 t; cvta.to.shared.u64 t, %1; cvt.u32.u64 %0, t; }"
        : "=r"(a) : "l"(p));
    return a;
}

__device__ __forceinline__ void mma_f16(float* c, const uint32_t* a, const uint32_t* b) {
    asm volatile(
        "mma.sync.aligned.m16n8k16.row.col.f32.f16.f16.f32 "
        "{%0,%1,%2,%3}, {%4,%5,%6,%7}, {%8,%9}, {%0,%1,%2,%3};"
        : "+f"(c[0]), "+f"(c[1]), "+f"(c[2]), "+f"(c[3])
        : "r"(a[0]), "r"(a[1]), "r"(a[2]), "r"(a[3]), "r"(b[0]), "r"(b[1]));
}

#define LDSM4(d, addr)                                                         \
    asm volatile("ldmatrix.sync.aligned.m8n8.x4.shared.b16 {%0,%1,%2,%3}, [%4];" \
        : "=r"((d)[0]), "=r"((d)[1]), "=r"((d)[2]), "=r"((d)[3]) : "r"(addr))
#define LDSM4T(d, addr)                                                        \
    asm volatile("ldmatrix.sync.aligned.m8n8.x4.trans.shared.b16 {%0,%1,%2,%3}, [%4];" \
        : "=r"((d)[0]), "=r"((d)[1]), "=r"((d)[2]), "=r"((d)[3]) : "r"(addr))

__device__ __forceinline__ void cp16h(uint32_t dst, const __half* src, int bytes) {
    asm volatile("cp.async.cg.shared.global [%0], [%1], 16, %2;"
                 :: "r"(dst), "l"(src), "r"(bytes));
}
#define CP_COMMIT() asm volatile("cp.async.commit_group;" ::: "memory")
#define CP_WAIT1()  asm volatile("cp.async.wait_group 1;" ::: "memory")
#define CP_WAIT0()  asm volatile("cp.async.wait_group 0;" ::: "memory")

__device__ __forceinline__ uint32_t packh2(float x, float y) {
    __half2 h = __floats2half2_rn(x, y);
    return *(uint32_t*)&h;
}
__device__ __forceinline__ float gelu_exact(float g) {
    return 0.5f * g * (1.0f + erff(g * 0.70710678118654752f));
}

// ---------------------------------------------------------------------------
// Flash attention (block-masked).  qkv: [B*NTOK][3072] fp16 (q pre-scaled),
// ao: [B*NTOK][1024] fp16.  grid (17, 1, B*H), 128 threads.  (R9 exact)
// ---------------------------------------------------------------------------
__global__ void __launch_bounds__(128, 2)
flash_kernel(const __half* __restrict__ qkv, __half* __restrict__ ao) {
    constexpr int LDS_ = 72;
    constexpr int QOFF = 0;
    constexpr int KOFF = 64 * LDS_;
    constexpr int VOFF = KOFF + 2 * 128 * LDS_;
    extern __shared__ __half sm[];
    const uint32_t sb = smem_u32(sm);

    const int tid = threadIdx.x;
    const int w = tid >> 5, lane = tid & 31;
    const int g = lane >> 2, t4 = lane & 3;
    const int q8 = lane >> 3, r8 = lane & 7;

    const int bh = blockIdx.z;
    const int b = bh >> 4, h = bh & 15;
    const int qb = blockIdx.x;
    int q0, c0, clen, qrows;
    if (qb < 16) { q0 = qb * 64; c0 = (qb < 8) ? 0 : 512; clen = 512; qrows = 64; }
    else         { q0 = 1024;  c0 = 0;  clen = NTOK;  qrows = 16; }

    const __half* qb_g = qkv + ((long)b * NTOK) * 3072 + h * 64;
    const __half* kb_g = qkv + ((long)b * NTOK) * 3072 + 1024 + h * 64;
    const __half* vb_g = qkv + ((long)b * NTOK) * 3072 + 2048 + h * 64;

    {
        int row = tid >> 1;
        int gr = q0 + row;
        int bytes = (row < qrows) ? 16 : 0;
        const __half* src = qb_g + (long)(bytes ? gr : 0) * 3072 + (tid & 1) * 32;
        uint32_t dst = sb + (QOFF + row * LDS_ + (tid & 1) * 32) * 2;
        #pragma unroll
        for (int e = 0; e < 4; e++)
            cp16h(dst + e * 16, src + e * 8, bytes);
    }

    const int T = (clen + 127) >> 7;
    int issued = 0;
    auto issueKV = [&](int t) {
        int buf = t & 1;
        int j = c0 + t * 128 + tid;
        int bytes = (j < c0 + clen) ? 16 : 0;
        const __half* ks = kb_g + (long)(bytes ? j : 0) * 3072;
        const __half* vs = vb_g + (long)(bytes ? j : 0) * 3072;
        uint32_t kd = sb + (KOFF + buf * 128 * LDS_ + tid * LDS_) * 2;
        uint32_t vd = sb + (VOFF + buf * 128 * LDS_ + tid * LDS_) * 2;
        #pragma unroll
        for (int ch = 0; ch < 8; ch++) cp16h(kd + ch * 16, ks + ch * 8, bytes);
        #pragma unroll
        for (int ch = 0; ch < 8; ch++) cp16h(vd + ch * 16, vs + ch * 8, bytes);
        CP_COMMIT();
        issued++;
    };
    issueKV(0);
    if (T > 1) issueKV(1);

    float m0 = -1e30f, m1 = -1e30f, l0 = 0.f, l1 = 0.f;
    float o[8][4];
    #pragma unroll
    for (int i = 0; i < 8; i++)
        #pragma unroll
        for (int q = 0; q < 4; q++) o[i][q] = 0.f;

    const int aIdx = (w * 16 + (q8 & 1) * 8 + r8) * LDS_ + (q8 >> 1) * 8;
    const int kIdx = ((q8 >> 1) * 8 + r8) * LDS_ + (q8 & 1) * 8;
    const int vIdx = ((q8 & 1) * 8 + r8) * LDS_ + (q8 >> 1) * 8;

    for (int t = 0; t < T; t++) {
        if (issued - (t + 1) >= 1) { CP_WAIT1(); } else { CP_WAIT0(); }
        __syncthreads();

        const uint32_t kb_s = sb + (KOFF + (t & 1) * 128 * LDS_) * 2;
        const uint32_t vb_s = sb + (VOFF + (t & 1) * 128 * LDS_) * 2;
        const uint32_t qs = sb + QOFF * 2;

        float s[16][4];
        #pragma unroll
        for (int i = 0; i < 16; i++)
            #pragma unroll
            for (int q = 0; q < 4; q++) s[i][q] = 0.f;

        #pragma unroll
        for (int ks = 0; ks < 4; ks++) {
            uint32_t af[4];
            LDSM4(af, qs + (aIdx + ks * 16) * 2);
            #pragma unroll
            for (int p = 0; p < 8; p++) {
                uint32_t d[4];
                LDSM4(d, kb_s + (kIdx + p * 16 * LDS_ + ks * 16) * 2);
                mma_f16(s[2 * p], af, d);
                mma_f16(s[2 * p + 1], af, d + 2);
            }
        }

        int lim = clen - t * 128;
        if (lim < 128) {
            #pragma unroll
            for (int nt = 0; nt < 16; nt++) {
                int cc = nt * 8 + 2 * t4;
                if (cc >= lim)     { s[nt][0] = -1e30f; s[nt][2] = -1e30f; }
                if (cc + 1 >= lim) { s[nt][1] = -1e30f; s[nt][3] = -1e30f; }
            }
        }

        float tm0 = -1e30f, tm1 = -1e30f;
        #pragma unroll
        for (int nt = 0; nt < 16; nt++) {
            tm0 = fmaxf(tm0, fmaxf(s[nt][0], s[nt][1]));
            tm1 = fmaxf(tm1, fmaxf(s[nt][2], s[nt][3]));
        }
        tm0 = fmaxf(tm0, __shfl_xor_sync(0xffffffffu, tm0, 1));
        tm0 = fmaxf(tm0, __shfl_xor_sync(0xffffffffu, tm0, 2));
        tm1 = fmaxf(tm1, __shfl_xor_sync(0xffffffffu, tm1, 1));
        tm1 = fmaxf(tm1, __shfl_xor_sync(0xffffffffu, tm1, 2));

        float nm0 = fmaxf(m0, tm0), nm1 = fmaxf(m1, tm1);
        float sc0 = __expf(m0 - nm0), sc1 = __expf(m1 - nm1);
        m0 = nm0; m1 = nm1;
        l0 *= sc0; l1 *= sc1;
        #pragma unroll
        for (int nt = 0; nt < 8; nt++) {
            o[nt][0] *= sc0; o[nt][1] *= sc0;
            o[nt][2] *= sc1; o[nt][3] *= sc1;
        }

        uint32_t pf[16][2];
        #pragma unroll
        for (int nt = 0; nt < 16; nt++) {
            float p0 = __expf(s[nt][0] - m0);
            float p1 = __expf(s[nt][1] - m0);
            float p2 = __expf(s[nt][2] - m1);
            float p3 = __expf(s[nt][3] - m1);
            l0 += p0 + p1; l1 += p2 + p3;
            pf[nt][0] = packh2(p0, p1);
            pf[nt][1] = packh2(p2, p3);
        }

        #pragma unroll
        for (int kv = 0; kv < 8; kv++) {
            uint32_t a[4] = { pf[2 * kv][0], pf[2 * kv][1],
                              pf[2 * kv + 1][0], pf[2 * kv + 1][1] };
            #pragma unroll
            for (int p = 0; p < 4; p++) {
                uint32_t d[4];
                LDSM4T(d, vb_s + (vIdx + kv * 16 * LDS_ + p * 16) * 2);
                mma_f16(o[2 * p], a, d);
                mma_f16(o[2 * p + 1], a, d + 2);
            }
        }

        __syncthreads();
        if (t + 2 < T) issueKV(t + 2);
    }

    l0 += __shfl_xor_sync(0xffffffffu, l0, 1);
    l0 += __shfl_xor_sync(0xffffffffu, l0, 2);
    l1 += __shfl_xor_sync(0xffffffffu, l1, 1);
    l1 += __shfl_xor_sync(0xffffffffu, l1, 2);
    float inv0 = 1.0f / l0, inv1 = 1.0f / l1;

    int lr0 = w * 16 + g, lr1 = lr0 + 8;
    __half* aob = ao + ((long)b * NTOK) * 1024 + h * 64;
    if (lr0 < qrows) {
        __half* rp = aob + (long)(q0 + lr0) * 1024 + 2 * t4;
        #pragma unroll
        for (int nt = 0; nt < 8; nt++)
            *(__half2*)(rp + nt * 8) = __floats2half2_rn(o[nt][0] * inv0, o[nt][1] * inv0);
    }
    if (lr1 < qrows) {
        __half* rp = aob + (long)(q0 + lr1) * 1024 + 2 * t4;
        #pragma unroll
        for (int nt = 0; nt < 8; nt++)
            *(__half2*)(rp + nt * 8) = __floats2half2_rn(o[nt][2] * inv1, o[nt][3] * inv1);
    }
}

// ---------------------------------------------------------------------------
// fp16 mma.sync GEMM (R9 exact mainloop): BM=128, BN=128, BK=32,
// warp tile 64x64, 128 threads, 2 CTAs/SM, 3-stage cp.async + ldmatrix.
//   GEGLU: FF1 weight-column remap + fused gelu(gate)*val epilogue.
//   C16EN: OUTH=false epilogue also stores fp16 copy to C16.
// ---------------------------------------------------------------------------
template<bool OUTH, bool GEGLU, bool C16EN>
__global__ void __launch_bounds__(128, 2)
hgemm(const __half* __restrict__ A, const __half* __restrict__ Bm,
      void* __restrict__ Cv, const float* __restrict__ Res,
      __half* __restrict__ C16,
      int M, int N, int K, int lda, int ldb, int ldc,
      float alpha, int resRowMod, int ldres) {
    constexpr int MT = 4;
    constexpr int NT = 8;
    constexpr int A_ST_H = 128 * 40;
    constexpr int B_ST_H = 128 * 40;
    constexpr int ST_H   = A_ST_H + B_ST_H;

    extern __shared__ __align__(16) __half smem[];
    const uint32_t sb = smem_u32(smem);

    const int tid = threadIdx.x;
    const int wid = tid >> 5, lane = tid & 31;
    const int g = lane >> 2, t4 = lane & 3;
    const int wm = wid >> 1, wn = wid & 1;
    const int q8 = lane >> 3, r8 = lane & 7;

    const int rowBase = blockIdx.y * 128;
    const int colBase = blockIdx.x * 128;
    const int KC = (K + 31) >> 5;

    const int chA = tid & 3;
    const __half* aSrc[4];
    uint32_t aOff[4];
    bool aOk[4];
    #pragma unroll
    for (int e = 0; e < 4; e++) {
        int m = (tid >> 2) + 32 * e;
        int gr = rowBase + m;
        aOk[e] = gr < M;
        aSrc[e] = A + (long)(aOk[e] ? gr : 0) * lda + chA * 8;
        aOff[e] = (uint32_t)((m * 40 + chA * 8) * 2);
    }
    const __half* bSrc[4];
    uint32_t bOff[4];
    int bOkA[4];
    #pragma unroll
    for (int e = 0; e < 4; e++) {
        int n = (tid >> 2) + 32 * e;
        int gn = colBase + n;
        int srcRow;
        if (GEGLU) {
            int j = gn >> 4, ww = gn & 15;
            int f8 = j * 8 + (ww & 7);
            bOkA[e] = (f8 < FF_) ? 1 : 0;
            srcRow = (ww < 8) ? f8 : (FF_ + f8);
        } else {
            bOkA[e] = (gn < N) ? 1 : 0;
            srcRow = gn;
        }
        bSrc[e] = Bm + (long)(bOkA[e] ? srcRow : 0) * ldb + chA * 8;
        bOff[e] = (uint32_t)((n * 40 + chA * 8) * 2);
    }

    auto issue = [&](int c, int st) {
        const uint32_t stb = sb + (uint32_t)(st * ST_H * 2);
        int krem = K - (c << 5);
        int kb = (krem - chA * 8) * 2;
        kb = kb < 0 ? 0 : (kb > 16 ? 16 : kb);
        #pragma unroll
        for (int e = 0; e < 4; e++) {
            int bytes = aOk[e] ? kb : 0;
            cp16h(stb + aOff[e], bytes ? aSrc[e] : A, bytes);
            aSrc[e] += 32;
        }
        const uint32_t bstb = stb + (uint32_t)(A_ST_H * 2);
        #pragma unroll
        for (int e = 0; e < 4; e++) {
            int bytes = bOkA[e] ? kb : 0;
            cp16h(bstb + bOff[e], bytes ? bSrc[e] : Bm, bytes);
            bSrc[e] += 32;
        }
        CP_COMMIT();
    };

    float acc[MT][NT][4];
    #pragma unroll
    for (int i = 0; i < MT; i++)
        #pragma unroll
        for (int j = 0; j < NT; j++)
            #pragma unroll
            for (int q = 0; q < 4; q++) acc[i][j][q] = 0.0f;

    const int aIdx0 = (wm * 64 + (q8 & 1) * 8 + r8) * 40 + (q8 >> 1) * 8;
    const int bIdx0 = (wn * 64 + (q8 >> 1) * 8 + r8) * 40 + (q8 & 1) * 8;

    issue(0, 0);
    issue(1, 1);

    int st = 0;
    for (int c = 0; c < KC; c++) {
        CP_WAIT1();
        __syncthreads();
        if (c + 2 < KC) issue(c + 2, (st + 2) % 3);
        else CP_COMMIT();

        const uint32_t aStB = sb + (uint32_t)(st * ST_H * 2);
        const uint32_t bStB = aStB + (uint32_t)(A_ST_H * 2);

        #pragma unroll
        for (int ks = 0; ks < 2; ks++) {
            uint32_t af[MT][4], bf[NT][2];
            #pragma unroll
            for (int mt = 0; mt < MT; mt++)
                LDSM4(af[mt], aStB + (uint32_t)((aIdx0 + mt * 16 * 40 + ks * 16) * 2));
            #pragma unroll
            for (int p = 0; p < NT / 2; p++) {
                uint32_t d[4];
                LDSM4(d, bStB + (uint32_t)((bIdx0 + p * 16 * 40 + ks * 16) * 2));
                bf[2 * p][0] = d[0]; bf[2 * p][1] = d[1];
                bf[2 * p + 1][0] = d[2]; bf[2 * p + 1][1] = d[3];
            }
            #pragma unroll
            for (int mt = 0; mt < MT; mt++)
                #pragma unroll
                for (int nt = 0; nt < NT; nt++)
                    mma_f16(acc[mt][nt], af[mt], bf[nt]);
        }
        st++; if (st == 3) st = 0;
    }

    if (GEGLU) {
        __half* act = (__half*)Cv;
        const int actBase = (colBase >> 1) + wn * 32;
        #pragma unroll
        for (int mt = 0; mt < MT; mt++) {
            int r0 = rowBase + wm * 64 + mt * 16 + g;
            #pragma unroll
            for (int p = 0; p < NT / 2; p++) {
                int col = actBase + p * 8 + t4 * 2;
                #pragma unroll
                for (int hh = 0; hh < 2; hh++) {
                    int rr = r0 + hh * 8;
                    if (rr >= M) continue;
                    float v0 = acc[mt][2 * p][hh * 2];
                    float v1 = acc[mt][2 * p][hh * 2 + 1];
                    float g0 = acc[mt][2 * p + 1][hh * 2];
                    float g1 = acc[mt][2 * p + 1][hh * 2 + 1];
                    *(__half2*)(act + (long)rr * ldc + col) =
                        __floats2half2_rn(gelu_exact(g0) * v0, gelu_exact(g1) * v1);
                }
            }
        }
        return;
    }

    #pragma unroll
    for (int mt = 0; mt < MT; mt++) {
        int r0 = rowBase + wm * 64 + mt * 16 + g;
        #pragma unroll
        for (int nt = 0; nt < NT; nt++) {
            int col = colBase + wn * 64 + nt * 8 + t4 * 2;
            if (col >= N) continue;
            #pragma unroll
            for (int hh = 0; hh < 2; hh++) {
                int rr = r0 + hh * 8;
                if (rr >= M) continue;
                float vx = alpha * acc[mt][nt][hh * 2];
                float vy = alpha * acc[mt][nt][hh * 2 + 1];
                if (Res) {
                    int rx = resRowMod ? (rr % resRowMod) : rr;
                    float2 rv = *(const float2*)(Res + (long)rx * ldres + col);
                    vx += rv.x; vy += rv.y;
                }
                if (OUTH) {
                    *(__half2*)((__half*)Cv + (long)rr * ldc + col) = __floats2half2_rn(vx, vy);
                } else {
                    float2 v; v.x = vx; v.y = vy;
                    *(float2*)((float*)Cv + (long)rr * ldc + col) = v;
                    if (C16EN)
                        *(__half2*)(C16 + (long)rr * ldc + col) = __floats2half2_rn(vx, vy);
                }
            }
        }
    }
}

// ---------------------------------------------------------------------------
// Weight transpose: dst[z][n][k] = (half)(scale * src[z][k][n])  (R9 exact)
// ---------------------------------------------------------------------------
__global__ void transpose_kernel(const float* __restrict__ src,
                                 __half* __restrict__ dst,
                                 int K, int N, int ldd,
                                 long srcZ, long dstZ, float scale) {
    __shared__ float tile[64][33];
    int k0 = blockIdx.y * 64, n0 = blockIdx.x * 32;
    long zS = (long)blockIdx.z * srcZ;
    long zD = (long)blockIdx.z * dstZ;
    int tx = threadIdx.x, ty = threadIdx.y;   // 32 x 8
    #pragma unroll
    for (int i = ty; i < 64; i += 8) {
        int k = k0 + i, n = n0 + tx;
        if (k < K && n < N) tile[i][tx] = src[zS + (long)k * N + n];
    }
    __syncthreads();
    #pragma unroll
    for (int i = ty; i < 32; i += 8) {
        int n = n0 + i, k = k0 + tx * 2;
        if (n < N && k + 1 < K)
            *(__half2*)(dst + zD + (long)n * ldd + k) =
                __floats2half2_rn(scale * tile[tx * 2][i], scale * tile[tx * 2 + 1][i]);
    }
}

// ---------------------------------------------------------------------------
// Small SIMT GEMM (pool q / final projection)
// ---------------------------------------------------------------------------
template<int BM, int BN, int BK, int TM, int TN>
__global__ void __launch_bounds__((BM / TM) * (BN / TN))
gemm_small_kernel(const float* __restrict__ A, const float* __restrict__ Bm,
                  float* __restrict__ C, const float* __restrict__ Res,
                  int M, int Nn, int K, int lda, int ldb, int ldc,
                  float alpha, int resRowMod, int ldres) {
    constexpr int THREADS = (BM / TM) * (BN / TN);
    constexpr int AELEM = BM * BK / THREADS;
    constexpr int BELEM = BK * BN / THREADS;

    __shared__ __align__(16) float As[BK][BM + 4];
    __shared__ __align__(16) float Bs[BK][BN + 4];

    int tid = threadIdx.x;
    int tcol = tid % (BN / TN);
    int trow = tid / (BN / TN);
    int rowBase = blockIdx.y * BM;
    int colBase = blockIdx.x * BN;

    float acc[TM][TN] = {};

    for (int k0 = 0; k0 < K; k0 += BK) {
        #pragma unroll
        for (int e = 0; e < AELEM; e++) {
            int idx = tid + e * THREADS;
            int m = idx / BK, kk = idx % BK;
            int gr = rowBase + m, gc = k0 + kk;
            As[kk][m] = (gr < M && gc < K) ? A[(long)gr * lda + gc] : 0.0f;
        }
        #pragma unroll
        for (int e = 0; e < BELEM; e++) {
            int idx = tid + e * THREADS;
            int kk = idx / BN, n = idx % BN;
            int gc = colBase + n, gk = k0 + kk;
            Bs[kk][n] = (gc < Nn && gk < K) ? Bm[(long)gk * ldb + gc] : 0.0f;
        }
        __syncthreads();

        #pragma unroll
        for (int kk = 0; kk < BK; kk++) {
            float a[TM], bb[TN];
            #pragma unroll
            for (int i = 0; i < TM; i++) a[i] = As[kk][trow * TM + i];
            #pragma unroll
            for (int j = 0; j < TN; j++) bb[j] = Bs[kk][tcol * TN + j];
            #pragma unroll
            for (int i = 0; i < TM; i++)
                #pragma unroll
                for (int j = 0; j < TN; j++)
                    acc[i][j] += a[i] * bb[j];
        }
        __syncthreads();
    }

    #pragma unroll
    for (int i = 0; i < TM; i++) {
        int r = rowBase + trow * TM + i;
        if (r >= M) continue;
        #pragma unroll
        for (int j = 0; j < TN; j++) {
            int c = colBase + tcol * TN + j;
            if (c >= Nn) continue;
            float v = alpha * acc[i][j];
            if (Res) {
                int rr = resRowMod ? (r % resRowMod) : r;
                v += Res[(long)rr * ldres + c];
            }
            C[(long)r * ldc + c] = v;
        }
    }
}

// ---------------------------------------------------------------------------
// Reductions / elementwise
// ---------------------------------------------------------------------------
__device__ __forceinline__ float blk_reduce(float v, bool ismax) {
    __shared__ float red[9];
    #pragma unroll
    for (int o = 16; o; o >>= 1) {
        float u = __shfl_xor_sync(0xffffffffu, v, o);
        v = ismax ? fmaxf(v, u) : (v + u);
    }
    if ((threadIdx.x & 31) == 0) red[threadIdx.x >> 5] = v;
    __syncthreads();
    if (threadIdx.x == 0) {
        float r = red[0];
        int nw = blockDim.x >> 5;
        for (int w = 1; w < nw; w++) r = ismax ? fmaxf(r, red[w]) : (r + red[w]);
        red[8] = r;
    }
    __syncthreads();
    float r = red[8];
    __syncthreads();
    return r;
}

__device__ __forceinline__ int token_type(int j) {
    return j < 512 ? 0 : (j < 1024 ? 1 : 2);
}

// Concat: fp32 tokens + fp16 copy
__global__ void concat_kernel(const float4* __restrict__ m0,
                              const float4* __restrict__ m1,
                              const float4* __restrict__ fus,
                              float4* __restrict__ tokens,
                              uint2* __restrict__ tok16) {
    int idx = blockIdx.x * blockDim.x + threadIdx.x;
    const int D4 = D_ / 4;
    int total = B_ * NTOK * D4;
    if (idx >= total) return;
    int d = idx % D4;
    int t = (idx / D4) % NTOK;
    int b = idx / (D4 * NTOK);
    float4 v;
    if (t < 512)       v = m0[((long)b * 512 + t) * D4 + d];
    else if (t < 1024) v = m1[((long)b * 512 + (t - 512)) * D4 + d];
    else               v = fus[(long)(t - 1024) * D4 + d];
    tokens[idx] = v;
    __half2 h0 = __floats2half2_rn(v.x, v.y);
    __half2 h1 = __floats2half2_rn(v.z, v.w);
    tok16[idx] = make_uint2(*(uint32_t*)&h0, *(uint32_t*)&h1);
}

// LayerNorm from fp16 residual copy (two-pass), writes gamma-scaled fp16 out
__global__ void ln16_kernel(const __half* __restrict__ x,
                            const float* __restrict__ gamma,
                            __half* __restrict__ out) {
    long row = blockIdx.x;
    const __half2* xr = (const __half2*)(x + row * D_);
    float2 a = __half22float2(xr[2 * threadIdx.x]);
    float2 b = __half22float2(xr[2 * threadIdx.x + 1]);
    float s = a.x + a.y + b.x + b.y;
    float mean = blk_reduce(s, false) * (1.0f / D_);
    float dx = a.x - mean, dy = a.y - mean, dz = b.x - mean, dw = b.y - mean;
    float s2 = dx * dx + dy * dy + dz * dz + dw * dw;
    float var = blk_reduce(s2, false) * (1.0f / D_);
    float inv = rsqrtf(var + 1e-5f);
    float4 g = ((const float4*)gamma)[threadIdx.x];
    __half2* o = (__half2*)(out + row * D_);
    o[2 * threadIdx.x]     = __floats2half2_rn(dx * inv * g.x, dy * inv * g.y);
    o[2 * threadIdx.x + 1] = __floats2half2_rn(dz * inv * g.z, dw * inv * g.w);
}

// ---------------------------------------------------------------------------
// Fused pool attention: sim + masked softmax + PV in one kernel.
// grid = B*H blocks, 256 threads. poolq fp32 [4][1024], kv fp16 [B*NTOK][2048],
// poolao fp32 [B*4][1024].
// ---------------------------------------------------------------------------
__global__ void __launch_bounds__(256)
pool_attn_kernel(const float* __restrict__ poolq,
                 const __half* __restrict__ kv,
                 float* __restrict__ poolao) {
    __shared__ float qs[4][64];
    __shared__ float sim[4][NTOK];

    const int bh = blockIdx.x;
    const int b = bh >> 4, h = bh & 15;
    const int tid = threadIdx.x;

    {
        int r = tid >> 6, d = tid & 63;
        qs[r][d] = poolq[r * D_ + h * 64 + d];
    }
    __syncthreads();

    const __half* kb = kv + (long)b * NTOK * 2048 + h * 64;
    const __half* vb = kb + 1024;

    // scores
    for (int j = tid; j < NTOK; j += 256) {
        const __half2* kj = (const __half2*)(kb + (long)j * 2048);
        float acc0 = 0.f, acc1 = 0.f, acc2 = 0.f, acc3 = 0.f;
        #pragma unroll
        for (int d2 = 0; d2 < 32; d2++) {
            float2 kv2 = __half22float2(kj[d2]);
            acc0 += qs[0][2 * d2] * kv2.x + qs[0][2 * d2 + 1] * kv2.y;
            acc1 += qs[1][2 * d2] * kv2.x + qs[1][2 * d2 + 1] * kv2.y;
            acc2 += qs[2][2 * d2] * kv2.x + qs[2][2 * d2 + 1] * kv2.y;
            acc3 += qs[3][2 * d2] * kv2.x + qs[3][2 * d2 + 1] * kv2.y;
        }
        int tt = token_type(j);
        sim[0][j] = (tt == 0) ? acc0 : -1e30f;
        sim[1][j] = (tt == 1) ? acc1 : -1e30f;
        sim[2][j] = (tt == 2) ? acc2 : -1e30f;
        sim[3][j] = acc3;                       // GLOBAL attends all
    }
    __syncthreads();

    // softmax per row
    #pragma unroll
    for (int r = 0; r < 4; r++) {
        float mx = -1e30f;
        for (int j = tid; j < NTOK; j += 256) mx = fmaxf(mx, sim[r][j]);
        mx = blk_reduce(mx, true);
        float s = 0.f;
        for (int j = tid; j < NTOK; j += 256) {
            float e = __expf(sim[r][j] - mx);
            sim[r][j] = e;
            s += e;
        }
        s = blk_reduce(s, false);
        float inv = 1.0f / s;
        for (int j = tid; j < NTOK; j += 256) sim[r][j] *= inv;
    }
    __syncthreads();

    // PV: one output element per thread
    {
        int r = tid >> 6, d = tid & 63;
        float acc = 0.f;
        const __half* vcol = vb + d;
        #pragma unroll 4
        for (int j = 0; j < NTOK; j++)
            acc += sim[r][j] * __half2float(vcol[(long)j * 2048]);
        poolao[((long)b * 4 + r) * D_ + h * 64 + d] = acc;
    }
}

// ---------------------------------------------------------------------------
// Host side
// ---------------------------------------------------------------------------
static constexpr int SM_H128  = 3 * (128 * 40 + 128 * 40) * 2;   // 61440
static constexpr int SM_FLASH = (64 * 72 + 4 * 128 * 72) * 2;    // 82944

extern "C" void kernel_launch(void* const* d_in, const int* in_sizes, int n_in,
                              void* d_out, int out_size) {
    const float* m0        = (const float*)d_in[0];
    const float* m1        = (const float*)d_in[1];
    const float* fusion    = (const float*)d_in[2];
    const float* ret_tok   = (const float*)d_in[3];
    const float* ln_gamma  = (const float*)d_in[4];
    const float* wq        = (const float*)d_in[5];
    const float* wkv       = (const float*)d_in[6];
    const float* wo        = (const float*)d_in[7];
    const float* ff_w1     = (const float*)d_in[8];
    const float* ff_w2     = (const float*)d_in[9];
    const float* pool_wq   = (const float*)d_in[10];
    const float* pool_wkv  = (const float*)d_in[11];
    const float* pool_wo   = (const float*)d_in[12];
    const float* final_g   = (const float*)d_in[13];
    float* out = (float*)d_out;

    cudaFuncSetAttribute(hgemm<true, false, false>,
                         cudaFuncAttributeMaxDynamicSharedMemorySize, SM_H128);
    cudaFuncSetAttribute(hgemm<false, false, true>,
                         cudaFuncAttributeMaxDynamicSharedMemorySize, SM_H128);
    cudaFuncSetAttribute(hgemm<true, true, false>,
                         cudaFuncAttributeMaxDynamicSharedMemorySize, SM_H128);
    cudaFuncSetAttribute(flash_kernel,
                         cudaFuncAttributeMaxDynamicSharedMemorySize, SM_FLASH);

    float *tokens, *poolq, *poolao;
    __half *tok16, *hbuf, *qkvbuf, *kvbuf, *aobuf, *actbuf;
    __half *wqkvT, *woT, *ff1T, *ff2T, *pkvT;
    cudaGetSymbolAddress((void**)&tokens, g_tokens);
    cudaGetSymbolAddress((void**)&poolq,  g_poolq);
    cudaGetSymbolAddress((void**)&poolao, g_poolao);
    cudaGetSymbolAddress((void**)&tok16,  h_tok);
    cudaGetSymbolAddress((void**)&hbuf,   h_h);
    cudaGetSymbolAddress((void**)&qkvbuf, h_qkv);
    cudaGetSymbolAddress((void**)&kvbuf,  h_kv);
    cudaGetSymbolAddress((void**)&aobuf,  h_ao);
    cudaGetSymbolAddress((void**)&actbuf, h_act);
    cudaGetSymbolAddress((void**)&wqkvT,  h_wqkvT);
    cudaGetSymbolAddress((void**)&woT,    h_woT);
    cudaGetSymbolAddress((void**)&ff1T,   h_ff1T);
    cudaGetSymbolAddress((void**)&ff2T,   h_ff2T);
    cudaGetSymbolAddress((void**)&pkvT,   h_pkvT);

    const float scale = 0.125f;

    // --- weight pre-transposes (fp32 -> fp16; q-scale folded into wq) ---
    {
        dim3 thr(32, 8);
        const long zq = (long)3 * D_ * D_;
        transpose_kernel<<<dim3(32, 16, 4),  thr>>>(wq,  wqkvT, 1024, 1024, 1024,
                                                    (long)D_ * D_, zq, scale);
        transpose_kernel<<<dim3(64, 16, 4),  thr>>>(wkv, wqkvT + (long)D_ * D_,
                                                    1024, 2048, 1024,
                                                    (long)2 * D_ * D_, zq, 1.0f);
        transpose_kernel<<<dim3(32, 16, 4),  thr>>>(wo, woT, 1024, 1024, 1024,
                                                    (long)D_ * D_, (long)D_ * D_, 1.0f);
        transpose_kernel<<<dim3(171, 16, 4), thr>>>(ff_w1, ff1T, 1024, 5460, 1024,
                                                    (long)D_ * FF2_, (long)FF2_ * D_, 1.0f);
        transpose_kernel<<<dim3(32, 43, 4),  thr>>>(ff_w2, ff2T, 2730, 1024, ACTLD,
                                                    (long)FF_ * D_, (long)D_ * ACTLD, 1.0f);
        transpose_kernel<<<dim3(64, 16, 1),  thr>>>(pool_wkv, pkvT, 1024, 2048, 1024,
                                                    0, 0, 1.0f);
    }

    {
        int total = B_ * NTOK * (D_ / 4);
        concat_kernel<<<(total + 255) / 256, 256>>>(
            (const float4*)m0, (const float4*)m1, (const float4*)fusion,
            (float4*)tokens, (uint2*)tok16);
    }

    for (int l = 0; l < L_; l++) {
        const __half* wqkvT_l = wqkvT + (long)l * 3 * D_ * D_;
        const __half* woT_l   = woT   + (long)l * D_ * D_;
        const __half* w1T_l   = ff1T  + (long)l * FF2_ * D_;
        const __half* w2T_l   = ff2T  + (long)l * D_ * ACTLD;
        const float*  g_l     = ln_gamma + (long)l * D_;

        // attention block
        ln16_kernel<<<ROWS, 256>>>(tok16, g_l, hbuf);
        hgemm<true, false, false><<<dim3(24, 33, 1), 128, SM_H128>>>(
            hbuf, wqkvT_l, qkvbuf, nullptr, nullptr,
            ROWS, 3 * D_, D_, D_, D_, 3 * D_, 1.0f, 0, 0);
        flash_kernel<<<dim3(17, 1, B_ * H_), 128, SM_FLASH>>>(qkvbuf, aobuf);
        hgemm<false, false, true><<<dim3(8, 33, 1), 128, SM_H128>>>(
            aobuf, woT_l, tokens, tokens, tok16,
            ROWS, D_, D_, D_, D_, D_, 1.0f, 0, D_);

        // feed-forward block: FF1 + GEGLU fused, then FF2 (+res, +fp16 copy)
        ln16_kernel<<<ROWS, 256>>>(tok16, g_l, hbuf);
        hgemm<true, true, false><<<dim3(2 * ACTLD / 128, 33, 1), 128, SM_H128>>>(
            hbuf, w1T_l, actbuf, nullptr, nullptr,
            ROWS, 2 * ACTLD, D_, D_, D_, ACTLD, 1.0f, 0, 0);
        hgemm<false, false, true><<<dim3(8, 33, 1), 128, SM_H128>>>(
            actbuf, w2T_l, tokens, tokens, tok16,
            ROWS, D_, FF_, ACTLD, ACTLD, D_, 1.0f, 0, D_);
    }

    // --- final LN + attention pooling ---
    ln16_kernel<<<ROWS, 256>>>(tok16, final_g, hbuf);

    gemm_small_kernel<64, 64, 16, 4, 4><<<dim3(16, 1, 1), 256>>>(
        ret_tok, pool_wq, poolq, nullptr, 4, D_, D_, D_, D_, D_, scale, 0, 0);

    hgemm<true, false, false><<<dim3(16, 33, 1), 128, SM_H128>>>(
        hbuf, pkvT, kvbuf, nullptr, nullptr,
        ROWS, 2 * D_, D_, D_, D_, 2 * D_, 1.0f, 0, 0);

    pool_attn_kernel<<<B_ * H_, 256>>>(poolq, kvbuf, poolao);

    gemm_small_kernel<64, 64, 16, 4, 4><<<dim3(16, 1, 1), 256>>>(
        poolao, pool_wo, out, ret_tok, B_ * 4, D_, D_, D_, D_, D_, 1.0f,
        /*resRowMod=*/4, /*ldres=*/D_);
}

// round 13
// speedup vs baseline: 1.1397x; 1.0540x over previous
#include <cuda_runtime.h>
#include <cuda_fp16.h>
#include <math.h>
#include <stdint.h>

// ---------------------------------------------------------------------------
// Problem constants
// ---------------------------------------------------------------------------
static constexpr int B_    = 4;
static constexpr int NTOK  = 1040;   // 512 + 512 + 16
static constexpr int D_    = 1024;
static constexpr int H_    = 16;
static constexpr int DH_   = 64;
static constexpr int L_    = 4;
static constexpr int FF_   = 2730;
static constexpr int FF2_  = 5460;
static constexpr int ROWS  = B_ * NTOK;   // 4160
static constexpr int ACTLD = 2752;        // act cols (43 blocks x 64), padded

// ---------------------------------------------------------------------------
// Device scratch
// ---------------------------------------------------------------------------
__device__ float  g_tokens[B_ * NTOK * D_];
__device__ float  g_sim   [B_ * H_ * 4 * NTOK];   // pool sim only
__device__ float  g_poolq [4 * D_];
__device__ float  g_poolao[B_ * 4 * D_];
__device__ __half h_h     [ROWS * D_];
__device__ __half h_qkv   [ROWS * 3 * D_];
__device__ __half h_kv    [ROWS * 2 * D_];        // pool kv
__device__ __half h_ao    [ROWS * D_];
__device__ __half h_act   [(long long)ROWS * ACTLD];
// transposed fp16 weights
__device__ __half h_wqkvT[(long long)L_ * 3 * D_ * D_];
__device__ __half h_woT  [L_ * D_ * D_];
__device__ __half h_ff1T [(long long)L_ * FF2_ * D_];
__device__ __half h_ff2T [(long long)L_ * D_ * ACTLD];   // pad rows stay zero
__device__ __half h_pkvT [2 * D_ * D_];

// ---------------------------------------------------------------------------
// Helpers
// ---------------------------------------------------------------------------
__device__ __forceinline__ uint32_t smem_u32(const void* p) {
    uint32_t a;
    asm("{ .reg .u64 t; cvta.to.shared.u64 t, %1; cvt.u32.u64 %0, t; }"
        : "=r"(a) : "l"(p));
    return a;
}

__device__ __forceinline__ void mma_f16(float* c, const uint32_t* a, const uint32_t* b) {
    asm volatile(
        "mma.sync.aligned.m16n8k16.row.col.f32.f16.f16.f32 "
        "{%0,%1,%2,%3}, {%4,%5,%6,%7}, {%8,%9}, {%0,%1,%2,%3};"
        : "+f"(c[0]), "+f"(c[1]), "+f"(c[2]), "+f"(c[3])
        : "r"(a[0]), "r"(a[1]), "r"(a[2]), "r"(a[3]), "r"(b[0]), "r"(b[1]));
}

#define LDSM4(d, addr)                                                         \
    asm volatile("ldmatrix.sync.aligned.m8n8.x4.shared.b16 {%0,%1,%2,%3}, [%4];" \
        : "=r"((d)[0]), "=r"((d)[1]), "=r"((d)[2]), "=r"((d)[3]) : "r"(addr))
#define LDSM4T(d, addr)                                                        \
    asm volatile("ldmatrix.sync.aligned.m8n8.x4.trans.shared.b16 {%0,%1,%2,%3}, [%4];" \
        : "=r"((d)[0]), "=r"((d)[1]), "=r"((d)[2]), "=r"((d)[3]) : "r"(addr))

__device__ __forceinline__ void cp16h(uint32_t dst, const __half* src, int bytes) {
    asm volatile("cp.async.cg.shared.global [%0], [%1], 16, %2;"
                 :: "r"(dst), "l"(src), "r"(bytes));
}
#define CP_COMMIT() asm volatile("cp.async.commit_group;" ::: "memory")
#define CP_WAIT1()  asm volatile("cp.async.wait_group 1;" ::: "memory")
#define CP_WAIT0()  asm volatile("cp.async.wait_group 0;" ::: "memory")

__device__ __forceinline__ uint32_t packh2(float x, float y) {
    __half2 h = __floats2half2_rn(x, y);
    return *(uint32_t*)&h;
}
__device__ __forceinline__ float gelu_exact(float g) {
    return 0.5f * g * (1.0f + erff(g * 0.70710678118654752f));
}

// ---------------------------------------------------------------------------
// Flash attention (block-masked).  qkv: [B*NTOK][3072] fp16 (q pre-scaled),
// ao: [B*NTOK][1024] fp16.  grid (17, 1, B*H), 128 threads.  (R9 exact)
// ---------------------------------------------------------------------------
__global__ void __launch_bounds__(128, 2)
flash_kernel(const __half* __restrict__ qkv, __half* __restrict__ ao) {
    constexpr int LDS_ = 72;
    constexpr int QOFF = 0;
    constexpr int KOFF = 64 * LDS_;
    constexpr int VOFF = KOFF + 2 * 128 * LDS_;
    extern __shared__ __half sm[];
    const uint32_t sb = smem_u32(sm);

    const int tid = threadIdx.x;
    const int w = tid >> 5, lane = tid & 31;
    const int g = lane >> 2, t4 = lane & 3;
    const int q8 = lane >> 3, r8 = lane & 7;

    const int bh = blockIdx.z;
    const int b = bh >> 4, h = bh & 15;
    const int qb = blockIdx.x;
    int q0, c0, clen, qrows;
    if (qb < 16) { q0 = qb * 64; c0 = (qb < 8) ? 0 : 512; clen = 512; qrows = 64; }
    else         { q0 = 1024;  c0 = 0;  clen = NTOK;  qrows = 16; }

    const __half* qb_g = qkv + ((long)b * NTOK) * 3072 + h * 64;
    const __half* kb_g = qkv + ((long)b * NTOK) * 3072 + 1024 + h * 64;
    const __half* vb_g = qkv + ((long)b * NTOK) * 3072 + 2048 + h * 64;

    {
        int row = tid >> 1;
        int gr = q0 + row;
        int bytes = (row < qrows) ? 16 : 0;
        const __half* src = qb_g + (long)(bytes ? gr : 0) * 3072 + (tid & 1) * 32;
        uint32_t dst = sb + (QOFF + row * LDS_ + (tid & 1) * 32) * 2;
        #pragma unroll
        for (int e = 0; e < 4; e++)
            cp16h(dst + e * 16, src + e * 8, bytes);
    }

    const int T = (clen + 127) >> 7;
    int issued = 0;
    auto issueKV = [&](int t) {
        int buf = t & 1;
        int j = c0 + t * 128 + tid;
        int bytes = (j < c0 + clen) ? 16 : 0;
        const __half* ks = kb_g + (long)(bytes ? j : 0) * 3072;
        const __half* vs = vb_g + (long)(bytes ? j : 0) * 3072;
        uint32_t kd = sb + (KOFF + buf * 128 * LDS_ + tid * LDS_) * 2;
        uint32_t vd = sb + (VOFF + buf * 128 * LDS_ + tid * LDS_) * 2;
        #pragma unroll
        for (int ch = 0; ch < 8; ch++) cp16h(kd + ch * 16, ks + ch * 8, bytes);
        #pragma unroll
        for (int ch = 0; ch < 8; ch++) cp16h(vd + ch * 16, vs + ch * 8, bytes);
        CP_COMMIT();
        issued++;
    };
    issueKV(0);
    if (T > 1) issueKV(1);

    float m0 = -1e30f, m1 = -1e30f, l0 = 0.f, l1 = 0.f;
    float o[8][4];
    #pragma unroll
    for (int i = 0; i < 8; i++)
        #pragma unroll
        for (int q = 0; q < 4; q++) o[i][q] = 0.f;

    const int aIdx = (w * 16 + (q8 & 1) * 8 + r8) * LDS_ + (q8 >> 1) * 8;
    const int kIdx = ((q8 >> 1) * 8 + r8) * LDS_ + (q8 & 1) * 8;
    const int vIdx = ((q8 & 1) * 8 + r8) * LDS_ + (q8 >> 1) * 8;

    for (int t = 0; t < T; t++) {
        if (issued - (t + 1) >= 1) { CP_WAIT1(); } else { CP_WAIT0(); }
        __syncthreads();

        const uint32_t kb_s = sb + (KOFF + (t & 1) * 128 * LDS_) * 2;
        const uint32_t vb_s = sb + (VOFF + (t & 1) * 128 * LDS_) * 2;
        const uint32_t qs = sb + QOFF * 2;

        float s[16][4];
        #pragma unroll
        for (int i = 0; i < 16; i++)
            #pragma unroll
            for (int q = 0; q < 4; q++) s[i][q] = 0.f;

        #pragma unroll
        for (int ks = 0; ks < 4; ks++) {
            uint32_t af[4];
            LDSM4(af, qs + (aIdx + ks * 16) * 2);
            #pragma unroll
            for (int p = 0; p < 8; p++) {
                uint32_t d[4];
                LDSM4(d, kb_s + (kIdx + p * 16 * LDS_ + ks * 16) * 2);
                mma_f16(s[2 * p], af, d);
                mma_f16(s[2 * p + 1], af, d + 2);
            }
        }

        int lim = clen - t * 128;
        if (lim < 128) {
            #pragma unroll
            for (int nt = 0; nt < 16; nt++) {
                int cc = nt * 8 + 2 * t4;
                if (cc >= lim)     { s[nt][0] = -1e30f; s[nt][2] = -1e30f; }
                if (cc + 1 >= lim) { s[nt][1] = -1e30f; s[nt][3] = -1e30f; }
            }
        }

        float tm0 = -1e30f, tm1 = -1e30f;
        #pragma unroll
        for (int nt = 0; nt < 16; nt++) {
            tm0 = fmaxf(tm0, fmaxf(s[nt][0], s[nt][1]));
            tm1 = fmaxf(tm1, fmaxf(s[nt][2], s[nt][3]));
        }
        tm0 = fmaxf(tm0, __shfl_xor_sync(0xffffffffu, tm0, 1));
        tm0 = fmaxf(tm0, __shfl_xor_sync(0xffffffffu, tm0, 2));
        tm1 = fmaxf(tm1, __shfl_xor_sync(0xffffffffu, tm1, 1));
        tm1 = fmaxf(tm1, __shfl_xor_sync(0xffffffffu, tm1, 2));

        float nm0 = fmaxf(m0, tm0), nm1 = fmaxf(m1, tm1);
        float sc0 = __expf(m0 - nm0), sc1 = __expf(m1 - nm1);
        m0 = nm0; m1 = nm1;
        l0 *= sc0; l1 *= sc1;
        #pragma unroll
        for (int nt = 0; nt < 8; nt++) {
            o[nt][0] *= sc0; o[nt][1] *= sc0;
            o[nt][2] *= sc1; o[nt][3] *= sc1;
        }

        uint32_t pf[16][2];
        #pragma unroll
        for (int nt = 0; nt < 16; nt++) {
            float p0 = __expf(s[nt][0] - m0);
            float p1 = __expf(s[nt][1] - m0);
            float p2 = __expf(s[nt][2] - m1);
            float p3 = __expf(s[nt][3] - m1);
            l0 += p0 + p1; l1 += p2 + p3;
            pf[nt][0] = packh2(p0, p1);
            pf[nt][1] = packh2(p2, p3);
        }

        #pragma unroll
        for (int kv = 0; kv < 8; kv++) {
            uint32_t a[4] = { pf[2 * kv][0], pf[2 * kv][1],
                              pf[2 * kv + 1][0], pf[2 * kv + 1][1] };
            #pragma unroll
            for (int p = 0; p < 4; p++) {
                uint32_t d[4];
                LDSM4T(d, vb_s + (vIdx + kv * 16 * LDS_ + p * 16) * 2);
                mma_f16(o[2 * p], a, d);
                mma_f16(o[2 * p + 1], a, d + 2);
            }
        }

        __syncthreads();
        if (t + 2 < T) issueKV(t + 2);
    }

    l0 += __shfl_xor_sync(0xffffffffu, l0, 1);
    l0 += __shfl_xor_sync(0xffffffffu, l0, 2);
    l1 += __shfl_xor_sync(0xffffffffu, l1, 1);
    l1 += __shfl_xor_sync(0xffffffffu, l1, 2);
    float inv0 = 1.0f / l0, inv1 = 1.0f / l1;

    int lr0 = w * 16 + g, lr1 = lr0 + 8;
    __half* aob = ao + ((long)b * NTOK) * 1024 + h * 64;
    if (lr0 < qrows) {
        __half* rp = aob + (long)(q0 + lr0) * 1024 + 2 * t4;
        #pragma unroll
        for (int nt = 0; nt < 8; nt++)
            *(__half2*)(rp + nt * 8) = __floats2half2_rn(o[nt][0] * inv0, o[nt][1] * inv0);
    }
    if (lr1 < qrows) {
        __half* rp = aob + (long)(q0 + lr1) * 1024 + 2 * t4;
        #pragma unroll
        for (int nt = 0; nt < 8; nt++)
            *(__half2*)(rp + nt * 8) = __floats2half2_rn(o[nt][2] * inv1, o[nt][3] * inv1);
    }
}

// ---------------------------------------------------------------------------
// fp16 mma.sync GEMM (R9 exact): BM=128, BN=128, BK=32, warp tile 64x64,
// 128 threads (4 warps), 2 CTAs/SM, 3-stage cp.async + ldmatrix.
// ---------------------------------------------------------------------------
template<bool OUTH, bool GEGLU>
__global__ void __launch_bounds__(128, 2)
hgemm(const __half* __restrict__ A, const __half* __restrict__ Bm,
      void* __restrict__ Cv, const float* __restrict__ Res,
      int M, int N, int K, int lda, int ldb, int ldc,
      float alpha, int resRowMod, int ldres) {
    constexpr int MT = 4;
    constexpr int NT = 8;
    constexpr int A_ST_H = 128 * 40;
    constexpr int B_ST_H = 128 * 40;
    constexpr int ST_H   = A_ST_H + B_ST_H;

    extern __shared__ __align__(16) __half smem[];
    const uint32_t sb = smem_u32(smem);

    const int tid = threadIdx.x;
    const int wid = tid >> 5, lane = tid & 31;
    const int g = lane >> 2, t4 = lane & 3;
    const int wm = wid >> 1, wn = wid & 1;
    const int q8 = lane >> 3, r8 = lane & 7;

    const int rowBase = blockIdx.y * 128;
    const int colBase = blockIdx.x * 128;
    const int KC = (K + 31) >> 5;

    const int chA = tid & 3;
    const __half* aSrc[4];
    uint32_t aOff[4];
    bool aOk[4];
    #pragma unroll
    for (int e = 0; e < 4; e++) {
        int m = (tid >> 2) + 32 * e;
        int gr = rowBase + m;
        aOk[e] = gr < M;
        aSrc[e] = A + (long)(aOk[e] ? gr : 0) * lda + chA * 8;
        aOff[e] = (uint32_t)((m * 40 + chA * 8) * 2);
    }
    const __half* bSrc[4];
    uint32_t bOff[4];
    int bOkA[4];
    #pragma unroll
    for (int e = 0; e < 4; e++) {
        int n = (tid >> 2) + 32 * e;
        int gn = colBase + n;
        int srcRow;
        if (GEGLU) {
            int j = gn >> 4, ww = gn & 15;
            int f8 = j * 8 + (ww & 7);
            bOkA[e] = (f8 < FF_) ? 1 : 0;
            srcRow = (ww < 8) ? f8 : (FF_ + f8);
        } else {
            bOkA[e] = (gn < N) ? 1 : 0;
            srcRow = gn;
        }
        bSrc[e] = Bm + (long)(bOkA[e] ? srcRow : 0) * ldb + chA * 8;
        bOff[e] = (uint32_t)((n * 40 + chA * 8) * 2);
    }

    auto issue = [&](int c, int st) {
        const uint32_t stb = sb + (uint32_t)(st * ST_H * 2);
        int krem = K - (c << 5);
        int kb = (krem - chA * 8) * 2;
        kb = kb < 0 ? 0 : (kb > 16 ? 16 : kb);
        #pragma unroll
        for (int e = 0; e < 4; e++) {
            int bytes = aOk[e] ? kb : 0;
            cp16h(stb + aOff[e], bytes ? aSrc[e] : A, bytes);
            aSrc[e] += 32;
        }
        const uint32_t bstb = stb + (uint32_t)(A_ST_H * 2);
        #pragma unroll
        for (int e = 0; e < 4; e++) {
            int bytes = bOkA[e] ? kb : 0;
            cp16h(bstb + bOff[e], bytes ? bSrc[e] : Bm, bytes);
            bSrc[e] += 32;
        }
        CP_COMMIT();
    };

    float acc[MT][NT][4];
    #pragma unroll
    for (int i = 0; i < MT; i++)
        #pragma unroll
        for (int j = 0; j < NT; j++)
            #pragma unroll
            for (int q = 0; q < 4; q++) acc[i][j][q] = 0.0f;

    const int aIdx0 = (wm * 64 + (q8 & 1) * 8 + r8) * 40 + (q8 >> 1) * 8;
    const int bIdx0 = (wn * 64 + (q8 >> 1) * 8 + r8) * 40 + (q8 & 1) * 8;

    issue(0, 0);
    issue(1, 1);

    int st = 0;
    for (int c = 0; c < KC; c++) {
        CP_WAIT1();
        __syncthreads();
        if (c + 2 < KC) issue(c + 2, (st + 2) % 3);
        else CP_COMMIT();

        const uint32_t aStB = sb + (uint32_t)(st * ST_H * 2);
        const uint32_t bStB = aStB + (uint32_t)(A_ST_H * 2);

        #pragma unroll
        for (int ks = 0; ks < 2; ks++) {
            uint32_t af[MT][4], bf[NT][2];
            #pragma unroll
            for (int mt = 0; mt < MT; mt++)
                LDSM4(af[mt], aStB + (uint32_t)((aIdx0 + mt * 16 * 40 + ks * 16) * 2));
            #pragma unroll
            for (int p = 0; p < NT / 2; p++) {
                uint32_t d[4];
                LDSM4(d, bStB + (uint32_t)((bIdx0 + p * 16 * 40 + ks * 16) * 2));
                bf[2 * p][0] = d[0]; bf[2 * p][1] = d[1];
                bf[2 * p + 1][0] = d[2]; bf[2 * p + 1][1] = d[3];
            }
            #pragma unroll
            for (int mt = 0; mt < MT; mt++)
                #pragma unroll
                for (int nt = 0; nt < NT; nt++)
                    mma_f16(acc[mt][nt], af[mt], bf[nt]);
        }
        st++; if (st == 3) st = 0;
    }

    if (GEGLU) {
        __half* act = (__half*)Cv;
        const int actBase = (colBase >> 1) + wn * 32;
        #pragma unroll
        for (int mt = 0; mt < MT; mt++) {
            int r0 = rowBase + wm * 64 + mt * 16 + g;
            #pragma unroll
            for (int p = 0; p < NT / 2; p++) {
                int col = actBase + p * 8 + t4 * 2;
                #pragma unroll
                for (int hh = 0; hh < 2; hh++) {
                    int rr = r0 + hh * 8;
                    if (rr >= M) continue;
                    float v0 = acc[mt][2 * p][hh * 2];
                    float v1 = acc[mt][2 * p][hh * 2 + 1];
                    float g0 = acc[mt][2 * p + 1][hh * 2];
                    float g1 = acc[mt][2 * p + 1][hh * 2 + 1];
                    *(__half2*)(act + (long)rr * ldc + col) =
                        __floats2half2_rn(gelu_exact(g0) * v0, gelu_exact(g1) * v1);
                }
            }
        }
        return;
    }

    #pragma unroll
    for (int mt = 0; mt < MT; mt++) {
        int r0 = rowBase + wm * 64 + mt * 16 + g;
        #pragma unroll
        for (int nt = 0; nt < NT; nt++) {
            int col = colBase + wn * 64 + nt * 8 + t4 * 2;
            if (col >= N) continue;
            #pragma unroll
            for (int hh = 0; hh < 2; hh++) {
                int rr = r0 + hh * 8;
                if (rr >= M) continue;
                float vx = alpha * acc[mt][nt][hh * 2];
                float vy = alpha * acc[mt][nt][hh * 2 + 1];
                if (Res) {
                    int rx = resRowMod ? (rr % resRowMod) : rr;
                    float2 rv = *(const float2*)(Res + (long)rx * ldres + col);
                    vx += rv.x; vy += rv.y;
                }
                if (OUTH) {
                    *(__half2*)((__half*)Cv + (long)rr * ldc + col) = __floats2half2_rn(vx, vy);
                } else {
                    float2 v; v.x = vx; v.y = vy;
                    *(float2*)((float*)Cv + (long)rr * ldc + col) = v;
                }
            }
        }
    }
}

// ---------------------------------------------------------------------------
// Weight transpose (vectorized): dst[z][n][k] = (half)(scale * src[z][k][n])
// Tile 32k x 128n, 256 threads (32x8). float4 reads, half2 writes, MLP 8.
// All N divisible by 4; all K even.
// ---------------------------------------------------------------------------
__global__ void __launch_bounds__(256)
transpose_kernel(const float* __restrict__ src,
                 __half* __restrict__ dst,
                 int K, int N, int ldd,
                 long srcZ, long dstZ, float scale) {
    __shared__ float tile[32][129];
    const int k0 = blockIdx.y * 32, n0 = blockIdx.x * 128;
    const long zS = (long)blockIdx.z * srcZ;
    const long zD = (long)blockIdx.z * dstZ;
    const int tx = threadIdx.x, ty = threadIdx.y;   // 32 x 8
    const int tid = ty * 32 + tx;

    #pragma unroll
    for (int it = 0; it < 4; it++) {
        int k = k0 + ty + it * 8;
        int n = n0 + tx * 4;
        if (k < K && n + 3 < N) {
            float4 v = *(const float4*)(src + zS + (long)k * N + n);
            tile[ty + it * 8][tx * 4 + 0] = v.x;
            tile[ty + it * 8][tx * 4 + 1] = v.y;
            tile[ty + it * 8][tx * 4 + 2] = v.z;
            tile[ty + it * 8][tx * 4 + 3] = v.w;
        }
    }
    __syncthreads();

    const int kk = tid & 15;            // k-pair 0..15 -> k = k0 + 2*kk
    const int nr = tid >> 4;            // 0..15
    const int k = k0 + 2 * kk;
    if (k < K) {                        // K even => k+1 < K too
        #pragma unroll
        for (int it = 0; it < 8; it++) {
            int n = n0 + nr + it * 16;
            if (n < N)
                *(__half2*)(dst + zD + (long)n * ldd + k) =
                    __floats2half2_rn(scale * tile[2 * kk][nr + it * 16],
                                      scale * tile[2 * kk + 1][nr + it * 16]);
        }
    }
}

// ---------------------------------------------------------------------------
// Small SIMT GEMM (pool)   (R9 exact)
// ---------------------------------------------------------------------------
template<typename T>
__device__ __forceinline__ float ldf(const T* p) { return (float)*p; }
template<>
__device__ __forceinline__ float ldf<__half>(const __half* p) { return __half2float(*p); }

template<int BM, int BN, int BK, int TM, int TN, bool TB, typename TAT, typename TBT>
__global__ void __launch_bounds__((BM / TM) * (BN / TN))
gemm_kernel(const TAT* __restrict__ A, const TBT* __restrict__ Bm,
            float* __restrict__ C, const float* __restrict__ Res,
            int M, int Nn, int K,
            int lda, int ldb, int ldc,
            long sAb, long sAh, long sBb, long sBh, long sCb, long sCh, int Hdiv,
            float alpha, int resRowMod, int ldres) {
    constexpr int THREADS = (BM / TM) * (BN / TN);
    constexpr int AELEM = BM * BK / THREADS;
    constexpr int BELEM = BK * BN / THREADS;

    int z = blockIdx.z;
    int zb = z / Hdiv, zh = z - zb * Hdiv;
    A  += (long)zb * sAb + (long)zh * sAh;
    Bm += (long)zb * sBb + (long)zh * sBh;
    C  += (long)zb * sCb + (long)zh * sCh;

    __shared__ __align__(16) float As[BK][BM + 4];
    __shared__ __align__(16) float Bs[BK][BN + 4];

    int tid = threadIdx.x;
    int tcol = tid % (BN / TN);
    int trow = tid / (BN / TN);
    int rowBase = blockIdx.y * BM;
    int colBase = blockIdx.x * BN;

    float acc[TM][TN] = {};

    for (int k0 = 0; k0 < K; k0 += BK) {
        #pragma unroll
        for (int e = 0; e < AELEM; e++) {
            int idx = tid + e * THREADS;
            int m = idx / BK, kk = idx % BK;
            int gr = rowBase + m, gc = k0 + kk;
            As[kk][m] = (gr < M && gc < K) ? ldf(A + (long)gr * lda + gc) : 0.0f;
        }
        #pragma unroll
        for (int e = 0; e < BELEM; e++) {
            int idx = tid + e * THREADS;
            int kk, n;
            if (!TB) { kk = idx / BN; n = idx % BN; }
            else     { n = idx / BK;  kk = idx % BK; }
            int gc = colBase + n, gk = k0 + kk;
            float v = 0.0f;
            if (gc < Nn && gk < K)
                v = TB ? ldf(Bm + (long)gc * ldb + gk) : ldf(Bm + (long)gk * ldb + gc);
            Bs[kk][n] = v;
        }
        __syncthreads();

        #pragma unroll
        for (int kk = 0; kk < BK; kk++) {
            float a[TM], bb[TN];
            #pragma unroll
            for (int i = 0; i < TM; i++) a[i] = As[kk][trow * TM + i];
            #pragma unroll
            for (int j = 0; j < TN; j++) bb[j] = Bs[kk][tcol * TN + j];
            #pragma unroll
            for (int i = 0; i < TM; i++)
                #pragma unroll
                for (int j = 0; j < TN; j++)
                    acc[i][j] += a[i] * bb[j];
        }
        __syncthreads();
    }

    #pragma unroll
    for (int i = 0; i < TM; i++) {
        int r = rowBase + trow * TM + i;
        if (r >= M) continue;
        #pragma unroll
        for (int j = 0; j < TN; j++) {
            int c = colBase + tcol * TN + j;
            if (c >= Nn) continue;
            float v = alpha * acc[i][j];
            if (Res) {
                int rr = resRowMod ? (r % resRowMod) : r;
                v += Res[(long)rr * ldres + c];
            }
            C[(long)r * ldc + c] = v;
        }
    }
}

// ---------------------------------------------------------------------------
// Elementwise / reduction kernels (R9 exact)
// ---------------------------------------------------------------------------
__device__ __forceinline__ float blk_reduce(float v, bool ismax) {
    __shared__ float red[9];
    #pragma unroll
    for (int o = 16; o; o >>= 1) {
        float u = __shfl_xor_sync(0xffffffffu, v, o);
        v = ismax ? fmaxf(v, u) : (v + u);
    }
    if ((threadIdx.x & 31) == 0) red[threadIdx.x >> 5] = v;
    __syncthreads();
    if (threadIdx.x == 0) {
        float r = red[0];
        int nw = blockDim.x >> 5;
        for (int w = 1; w < nw; w++) r = ismax ? fmaxf(r, red[w]) : (r + red[w]);
        red[8] = r;
    }
    __syncthreads();
    float r = red[8];
    __syncthreads();
    return r;
}

__device__ __forceinline__ int token_type(int j) {
    return j < 512 ? 0 : (j < 1024 ? 1 : 2);
}

__global__ void concat_kernel(const float4* __restrict__ m0,
                              const float4* __restrict__ m1,
                              const float4* __restrict__ fus,
                              float4* __restrict__ tokens) {
    int idx = blockIdx.x * blockDim.x + threadIdx.x;
    const int D4 = D_ / 4;
    int total = B_ * NTOK * D4;
    if (idx >= total) return;
    int d = idx % D4;
    int t = (idx / D4) % NTOK;
    int b = idx / (D4 * NTOK);
    float4 v;
    if (t < 512)       v = m0[((long)b * 512 + t) * D4 + d];
    else if (t < 1024) v = m1[((long)b * 512 + (t - 512)) * D4 + d];
    else               v = fus[(long)(t - 1024) * D4 + d];
    tokens[idx] = v;
}

__global__ void ln_kernel(const float* __restrict__ x,
                          const float* __restrict__ gamma,
                          __half* __restrict__ out) {
    long row = blockIdx.x;
    const float4* xr = (const float4*)(x + row * D_);
    float4 v = xr[threadIdx.x];
    float s = v.x + v.y + v.z + v.w;
    float mean = blk_reduce(s, false) * (1.0f / D_);
    float dx = v.x - mean, dy = v.y - mean, dz = v.z - mean, dw = v.w - mean;
    float s2 = dx * dx + dy * dy + dz * dz + dw * dw;
    float var = blk_reduce(s2, false) * (1.0f / D_);
    float inv = rsqrtf(var + 1e-5f);
    float4 g = ((const float4*)gamma)[threadIdx.x];
    __half2* o = (__half2*)(out + row * D_);
    o[2 * threadIdx.x]     = __floats2half2_rn(dx * inv * g.x, dy * inv * g.y);
    o[2 * threadIdx.x + 1] = __floats2half2_rn(dz * inv * g.z, dw * inv * g.w);
}

__global__ void softmax_pool_kernel(float* __restrict__ sim) {
    long row = blockIdx.x;
    float* p = sim + row * NTOK;
    int r = (int)(row % 4);
    int tid = threadIdx.x;

    float vals[5];
    float mx = -3.4e38f;
    #pragma unroll
    for (int it = 0; it < 5; it++) {
        int j = tid + it * 256;
        float v = -3.4e38f;
        if (j < NTOK) {
            bool ok = (r == 3) || (token_type(j) == r);
            v = ok ? p[j] : -3.4e38f;
        }
        vals[it] = v;
        mx = fmaxf(mx, v);
    }
    mx = blk_reduce(mx, true);

    float e[5];
    float s = 0.0f;
    #pragma unroll
    for (int it = 0; it < 5; it++) {
        float ex = __expf(vals[it] - mx);
        e[it] = ex;
        s += ex;
    }
    s = blk_reduce(s, false);
    float inv = 1.0f / s;
    #pragma unroll
    for (int it = 0; it < 5; it++) {
        int j = tid + it * 256;
        if (j < NTOK) p[j] = e[it] * inv;
    }
}

// ---------------------------------------------------------------------------
// Host side
// ---------------------------------------------------------------------------
static constexpr int SM_H128  = 3 * (128 * 40 + 128 * 40) * 2;   // 61440
static constexpr int SM_FLASH = (64 * 72 + 4 * 128 * 72) * 2;    // 82944

static inline void hg(const __half* A, const __half* Bt, void* C, const float* Res,
                      int M, int Nn, int K, int lda, int ldbT, int ldc, float alpha,
                      bool outh, int resRowMod = 0, int ldres = 0) {
    dim3 grid((Nn + 127) / 128, (M + 127) / 128, 1);
    if (outh)
        hgemm<true, false><<<grid, 128, SM_H128>>>(
            A, Bt, C, Res, M, Nn, K, lda, ldbT, ldc, alpha, resRowMod, ldres);
    else
        hgemm<false, false><<<grid, 128, SM_H128>>>(
            A, Bt, C, Res, M, Nn, K, lda, ldbT, ldc, alpha, resRowMod, ldres);
}

extern "C" void kernel_launch(void* const* d_in, const int* in_sizes, int n_in,
                              void* d_out, int out_size) {
    const float* m0        = (const float*)d_in[0];
    const float* m1        = (const float*)d_in[1];
    const float* fusion    = (const float*)d_in[2];
    const float* ret_tok   = (const float*)d_in[3];
    const float* ln_gamma  = (const float*)d_in[4];
    const float* wq        = (const float*)d_in[5];
    const float* wkv       = (const float*)d_in[6];
    const float* wo        = (const float*)d_in[7];
    const float* ff_w1     = (const float*)d_in[8];
    const float* ff_w2     = (const float*)d_in[9];
    const float* pool_wq   = (const float*)d_in[10];
    const float* pool_wkv  = (const float*)d_in[11];
    const float* pool_wo   = (const float*)d_in[12];
    const float* final_g   = (const float*)d_in[13];
    float* out = (float*)d_out;

    cudaFuncSetAttribute(hgemm<true, false>,
                         cudaFuncAttributeMaxDynamicSharedMemorySize, SM_H128);
    cudaFuncSetAttribute(hgemm<false, false>,
                         cudaFuncAttributeMaxDynamicSharedMemorySize, SM_H128);
    cudaFuncSetAttribute(hgemm<true, true>,
                         cudaFuncAttributeMaxDynamicSharedMemorySize, SM_H128);
    cudaFuncSetAttribute(flash_kernel,
                         cudaFuncAttributeMaxDynamicSharedMemorySize, SM_FLASH);

    float *tokens, *simbuf, *poolq, *poolao;
    __half *hbuf, *qkvbuf, *kvbuf, *aobuf, *actbuf;
    __half *wqkvT, *woT, *ff1T, *ff2T, *pkvT;
    cudaGetSymbolAddress((void**)&tokens, g_tokens);
    cudaGetSymbolAddress((void**)&simbuf, g_sim);
    cudaGetSymbolAddress((void**)&poolq,  g_poolq);
    cudaGetSymbolAddress((void**)&poolao, g_poolao);
    cudaGetSymbolAddress((void**)&hbuf,   h_h);
    cudaGetSymbolAddress((void**)&qkvbuf, h_qkv);
    cudaGetSymbolAddress((void**)&kvbuf,  h_kv);
    cudaGetSymbolAddress((void**)&aobuf,  h_ao);
    cudaGetSymbolAddress((void**)&actbuf, h_act);
    cudaGetSymbolAddress((void**)&wqkvT,  h_wqkvT);
    cudaGetSymbolAddress((void**)&woT,    h_woT);
    cudaGetSymbolAddress((void**)&ff1T,   h_ff1T);
    cudaGetSymbolAddress((void**)&ff2T,   h_ff2T);
    cudaGetSymbolAddress((void**)&pkvT,   h_pkvT);

    const float scale = 0.125f;

    // --- weight pre-transposes (fp32 -> fp16; q-scale folded into wq) ---
    {
        dim3 thr(32, 8);
        const long zq = (long)3 * D_ * D_;
        transpose_kernel<<<dim3(8, 32, 4),   thr>>>(wq,  wqkvT, 1024, 1024, 1024,
                                                    (long)D_ * D_, zq, scale);
        transpose_kernel<<<dim3(16, 32, 4),  thr>>>(wkv, wqkvT + (long)D_ * D_,
                                                    1024, 2048, 1024,
                                                    (long)2 * D_ * D_, zq, 1.0f);
        transpose_kernel<<<dim3(8, 32, 4),   thr>>>(wo, woT, 1024, 1024, 1024,
                                                    (long)D_ * D_, (long)D_ * D_, 1.0f);
        transpose_kernel<<<dim3(43, 32, 4),  thr>>>(ff_w1, ff1T, 1024, 5460, 1024,
                                                    (long)D_ * FF2_, (long)FF2_ * D_, 1.0f);
        transpose_kernel<<<dim3(8, 86, 4),   thr>>>(ff_w2, ff2T, 2730, 1024, ACTLD,
                                                    (long)FF_ * D_, (long)D_ * ACTLD, 1.0f);
        transpose_kernel<<<dim3(16, 32, 1),  thr>>>(pool_wkv, pkvT, 1024, 2048, 1024,
                                                    0, 0, 1.0f);
    }

    {
        int total = B_ * NTOK * (D_ / 4);
        concat_kernel<<<(total + 255) / 256, 256>>>(
            (const float4*)m0, (const float4*)m1, (const float4*)fusion,
            (float4*)tokens);
    }

    const long sKVB = (long)NTOK * 2 * D_;

    for (int l = 0; l < L_; l++) {
        const __half* wqkvT_l = wqkvT + (long)l * 3 * D_ * D_;
        const __half* woT_l   = woT   + (long)l * D_ * D_;
        const __half* w1T_l   = ff1T  + (long)l * FF2_ * D_;
        const __half* w2T_l   = ff2T  + (long)l * D_ * ACTLD;
        const float*  g_l     = ln_gamma + (long)l * D_;

        // attention block
        ln_kernel<<<ROWS, 256>>>(tokens, g_l, hbuf);
        hg(hbuf, wqkvT_l, qkvbuf, nullptr, ROWS, 3 * D_, D_, D_, D_, 3 * D_, 1.0f, true);
        flash_kernel<<<dim3(17, 1, B_ * H_), 128, SM_FLASH>>>(qkvbuf, aobuf);
        hg(aobuf, woT_l, tokens, tokens, ROWS, D_, D_, D_, D_, D_, 1.0f, false, 0, D_);

        // feed-forward block: FF1 + GEGLU fused
        ln_kernel<<<ROWS, 256>>>(tokens, g_l, hbuf);
        hgemm<true, true><<<dim3(2 * ACTLD / 128, (ROWS + 127) / 128, 1),
                            128, SM_H128>>>(
            hbuf, w1T_l, actbuf, nullptr,
            ROWS, 2 * ACTLD, D_, D_, D_, ACTLD, 1.0f, 0, 0);
        hg(actbuf, w2T_l, tokens, tokens, ROWS, D_, FF_, ACTLD, ACTLD, D_, 1.0f, false, 0, D_);
    }

    // --- final LN + attention pooling ---
    ln_kernel<<<ROWS, 256>>>(tokens, final_g, hbuf);

    gemm_kernel<64, 64, 16, 4, 4, false, float, float>
        <<<dim3(16, 1, 1), 256>>>(
        ret_tok, pool_wq, poolq, nullptr, 4, D_, D_, D_, D_, D_,
        0, 0, 0, 0, 0, 0, 1, scale, 0, 0);

    hg(hbuf, pkvT, kvbuf, nullptr, ROWS, 2 * D_, D_, D_, D_, 2 * D_, 1.0f, true);

    gemm_kernel<64, 64, 16, 4, 4, true, float, __half>
        <<<dim3((NTOK + 63) / 64, 1, B_ * H_), 256>>>(
        poolq, kvbuf, simbuf, nullptr,
        4, NTOK, DH_, D_, 2 * D_, NTOK,
        0L, DH_, sKVB, DH_,
        (long)H_ * 4 * NTOK, (long)4 * NTOK, H_,
        1.0f, 0, 0);

    softmax_pool_kernel<<<B_ * H_ * 4, 256>>>(simbuf);

    gemm_kernel<64, 64, 16, 4, 4, false, float, __half>
        <<<dim3(1, 1, B_ * H_), 256>>>(
        simbuf, kvbuf + D_, poolao, nullptr,
        4, DH_, NTOK, NTOK, 2 * D_, D_,
        (long)H_ * 4 * NTOK, (long)4 * NTOK,
        sKVB, DH_,
        (long)4 * D_, DH_, H_,
        1.0f, 0, 0);

    gemm_kernel<64, 64, 16, 4, 4, false, float, float>
        <<<dim3(16, 1, 1), 256>>>(
        poolao, pool_wo, out, ret_tok, B_ * 4, D_, D_, D_, D_, D_,
        0, 0, 0, 0, 0, 0, 1, 1.0f, /*resRowMod=*/4, /*ldres=*/D_);
}

// round 14
// speedup vs baseline: 1.1498x; 1.0089x over previous
#include <cuda_runtime.h>
#include <cuda_fp16.h>
#include <math.h>
#include <stdint.h>

// ---------------------------------------------------------------------------
// Problem constants
// ---------------------------------------------------------------------------
static constexpr int B_    = 4;
static constexpr int NTOK  = 1040;   // 512 + 512 + 16
static constexpr int D_    = 1024;
static constexpr int H_    = 16;
static constexpr int DH_   = 64;
static constexpr int L_    = 4;
static constexpr int FF_   = 2730;
static constexpr int FF2_  = 5460;
static constexpr int ROWS  = B_ * NTOK;   // 4160
static constexpr int ACTLD = 2752;        // act cols (43 blocks x 64), padded

// ---------------------------------------------------------------------------
// Device scratch
// ---------------------------------------------------------------------------
__device__ float  g_tokens[B_ * NTOK * D_];
__device__ float  g_sim   [B_ * H_ * 4 * NTOK];   // pool sim only
__device__ float  g_poolq [4 * D_];
__device__ float  g_poolao[B_ * 4 * D_];
__device__ __half h_h     [ROWS * D_];
__device__ __half h_qkv   [ROWS * 3 * D_];
__device__ __half h_kv    [ROWS * 2 * D_];        // pool kv
__device__ __half h_ao    [ROWS * D_];
__device__ __half h_act   [(long long)ROWS * ACTLD];
// transposed fp16 weights
__device__ __half h_wqkvT[(long long)L_ * 3 * D_ * D_];
__device__ __half h_woT  [L_ * D_ * D_];
__device__ __half h_ff1T [(long long)L_ * FF2_ * D_];
__device__ __half h_ff2T [(long long)L_ * D_ * ACTLD];   // pad rows stay zero
__device__ __half h_pkvT [2 * D_ * D_];

// ---------------------------------------------------------------------------
// Helpers
// ---------------------------------------------------------------------------
__device__ __forceinline__ uint32_t smem_u32(const void* p) {
    uint32_t a;
    asm("{ .reg .u64 t; cvta.to.shared.u64 t, %1; cvt.u32.u64 %0, t; }"
        : "=r"(a) : "l"(p));
    return a;
}

__device__ __forceinline__ void mma_f16(float* c, const uint32_t* a, const uint32_t* b) {
    asm volatile(
        "mma.sync.aligned.m16n8k16.row.col.f32.f16.f16.f32 "
        "{%0,%1,%2,%3}, {%4,%5,%6,%7}, {%8,%9}, {%0,%1,%2,%3};"
        : "+f"(c[0]), "+f"(c[1]), "+f"(c[2]), "+f"(c[3])
        : "r"(a[0]), "r"(a[1]), "r"(a[2]), "r"(a[3]), "r"(b[0]), "r"(b[1]));
}

#define LDSM4(d, addr)                                                         \
    asm volatile("ldmatrix.sync.aligned.m8n8.x4.shared.b16 {%0,%1,%2,%3}, [%4];" \
        : "=r"((d)[0]), "=r"((d)[1]), "=r"((d)[2]), "=r"((d)[3]) : "r"(addr))
#define LDSM4T(d, addr)                                                        \
    asm volatile("ldmatrix.sync.aligned.m8n8.x4.trans.shared.b16 {%0,%1,%2,%3}, [%4];" \
        : "=r"((d)[0]), "=r"((d)[1]), "=r"((d)[2]), "=r"((d)[3]) : "r"(addr))

__device__ __forceinline__ void cp16h(uint32_t dst, const __half* src, int bytes) {
    asm volatile("cp.async.cg.shared.global [%0], [%1], 16, %2;"
                 :: "r"(dst), "l"(src), "r"(bytes));
}
#define CP_COMMIT() asm volatile("cp.async.commit_group;" ::: "memory")
#define CP_WAIT1()  asm volatile("cp.async.wait_group 1;" ::: "memory")
#define CP_WAIT0()  asm volatile("cp.async.wait_group 0;" ::: "memory")

__device__ __forceinline__ uint32_t packh2(float x, float y) {
    __half2 h = __floats2half2_rn(x, y);
    return *(uint32_t*)&h;
}
__device__ __forceinline__ float gelu_exact(float g) {
    return 0.5f * g * (1.0f + erff(g * 0.70710678118654752f));
}

// ---------------------------------------------------------------------------
// Flash attention (block-masked).  qkv: [B*NTOK][3072] fp16 (q pre-scaled),
// ao: [B*NTOK][1024] fp16.  grid (17, 1, B*H), 128 threads.  (R9 exact)
// ---------------------------------------------------------------------------
__global__ void __launch_bounds__(128, 2)
flash_kernel(const __half* __restrict__ qkv, __half* __restrict__ ao) {
    constexpr int LDS_ = 72;
    constexpr int QOFF = 0;
    constexpr int KOFF = 64 * LDS_;
    constexpr int VOFF = KOFF + 2 * 128 * LDS_;
    extern __shared__ __half sm[];
    const uint32_t sb = smem_u32(sm);

    const int tid = threadIdx.x;
    const int w = tid >> 5, lane = tid & 31;
    const int g = lane >> 2, t4 = lane & 3;
    const int q8 = lane >> 3, r8 = lane & 7;

    const int bh = blockIdx.z;
    const int b = bh >> 4, h = bh & 15;
    const int qb = blockIdx.x;
    int q0, c0, clen, qrows;
    if (qb < 16) { q0 = qb * 64; c0 = (qb < 8) ? 0 : 512; clen = 512; qrows = 64; }
    else         { q0 = 1024;  c0 = 0;  clen = NTOK;  qrows = 16; }

    const __half* qb_g = qkv + ((long)b * NTOK) * 3072 + h * 64;
    const __half* kb_g = qkv + ((long)b * NTOK) * 3072 + 1024 + h * 64;
    const __half* vb_g = qkv + ((long)b * NTOK) * 3072 + 2048 + h * 64;

    {
        int row = tid >> 1;
        int gr = q0 + row;
        int bytes = (row < qrows) ? 16 : 0;
        const __half* src = qb_g + (long)(bytes ? gr : 0) * 3072 + (tid & 1) * 32;
        uint32_t dst = sb + (QOFF + row * LDS_ + (tid & 1) * 32) * 2;
        #pragma unroll
        for (int e = 0; e < 4; e++)
            cp16h(dst + e * 16, src + e * 8, bytes);
    }

    const int T = (clen + 127) >> 7;
    int issued = 0;
    auto issueKV = [&](int t) {
        int buf = t & 1;
        int j = c0 + t * 128 + tid;
        int bytes = (j < c0 + clen) ? 16 : 0;
        const __half* ks = kb_g + (long)(bytes ? j : 0) * 3072;
        const __half* vs = vb_g + (long)(bytes ? j : 0) * 3072;
        uint32_t kd = sb + (KOFF + buf * 128 * LDS_ + tid * LDS_) * 2;
        uint32_t vd = sb + (VOFF + buf * 128 * LDS_ + tid * LDS_) * 2;
        #pragma unroll
        for (int ch = 0; ch < 8; ch++) cp16h(kd + ch * 16, ks + ch * 8, bytes);
        #pragma unroll
        for (int ch = 0; ch < 8; ch++) cp16h(vd + ch * 16, vs + ch * 8, bytes);
        CP_COMMIT();
        issued++;
    };
    issueKV(0);
    if (T > 1) issueKV(1);

    float m0 = -1e30f, m1 = -1e30f, l0 = 0.f, l1 = 0.f;
    float o[8][4];
    #pragma unroll
    for (int i = 0; i < 8; i++)
        #pragma unroll
        for (int q = 0; q < 4; q++) o[i][q] = 0.f;

    const int aIdx = (w * 16 + (q8 & 1) * 8 + r8) * LDS_ + (q8 >> 1) * 8;
    const int kIdx = ((q8 >> 1) * 8 + r8) * LDS_ + (q8 & 1) * 8;
    const int vIdx = ((q8 & 1) * 8 + r8) * LDS_ + (q8 >> 1) * 8;

    for (int t = 0; t < T; t++) {
        if (issued - (t + 1) >= 1) { CP_WAIT1(); } else { CP_WAIT0(); }
        __syncthreads();

        const uint32_t kb_s = sb + (KOFF + (t & 1) * 128 * LDS_) * 2;
        const uint32_t vb_s = sb + (VOFF + (t & 1) * 128 * LDS_) * 2;
        const uint32_t qs = sb + QOFF * 2;

        float s[16][4];
        #pragma unroll
        for (int i = 0; i < 16; i++)
            #pragma unroll
            for (int q = 0; q < 4; q++) s[i][q] = 0.f;

        #pragma unroll
        for (int ks = 0; ks < 4; ks++) {
            uint32_t af[4];
            LDSM4(af, qs + (aIdx + ks * 16) * 2);
            #pragma unroll
            for (int p = 0; p < 8; p++) {
                uint32_t d[4];
                LDSM4(d, kb_s + (kIdx + p * 16 * LDS_ + ks * 16) * 2);
                mma_f16(s[2 * p], af, d);
                mma_f16(s[2 * p + 1], af, d + 2);
            }
        }

        int lim = clen - t * 128;
        if (lim < 128) {
            #pragma unroll
            for (int nt = 0; nt < 16; nt++) {
                int cc = nt * 8 + 2 * t4;
                if (cc >= lim)     { s[nt][0] = -1e30f; s[nt][2] = -1e30f; }
                if (cc + 1 >= lim) { s[nt][1] = -1e30f; s[nt][3] = -1e30f; }
            }
        }

        float tm0 = -1e30f, tm1 = -1e30f;
        #pragma unroll
        for (int nt = 0; nt < 16; nt++) {
            tm0 = fmaxf(tm0, fmaxf(s[nt][0], s[nt][1]));
            tm1 = fmaxf(tm1, fmaxf(s[nt][2], s[nt][3]));
        }
        tm0 = fmaxf(tm0, __shfl_xor_sync(0xffffffffu, tm0, 1));
        tm0 = fmaxf(tm0, __shfl_xor_sync(0xffffffffu, tm0, 2));
        tm1 = fmaxf(tm1, __shfl_xor_sync(0xffffffffu, tm1, 1));
        tm1 = fmaxf(tm1, __shfl_xor_sync(0xffffffffu, tm1, 2));

        float nm0 = fmaxf(m0, tm0), nm1 = fmaxf(m1, tm1);
        float sc0 = __expf(m0 - nm0), sc1 = __expf(m1 - nm1);
        m0 = nm0; m1 = nm1;
        l0 *= sc0; l1 *= sc1;
        #pragma unroll
        for (int nt = 0; nt < 8; nt++) {
            o[nt][0] *= sc0; o[nt][1] *= sc0;
            o[nt][2] *= sc1; o[nt][3] *= sc1;
        }

        uint32_t pf[16][2];
        #pragma unroll
        for (int nt = 0; nt < 16; nt++) {
            float p0 = __expf(s[nt][0] - m0);
            float p1 = __expf(s[nt][1] - m0);
            float p2 = __expf(s[nt][2] - m1);
            float p3 = __expf(s[nt][3] - m1);
            l0 += p0 + p1; l1 += p2 + p3;
            pf[nt][0] = packh2(p0, p1);
            pf[nt][1] = packh2(p2, p3);
        }

        #pragma unroll
        for (int kv = 0; kv < 8; kv++) {
            uint32_t a[4] = { pf[2 * kv][0], pf[2 * kv][1],
                              pf[2 * kv + 1][0], pf[2 * kv + 1][1] };
            #pragma unroll
            for (int p = 0; p < 4; p++) {
                uint32_t d[4];
                LDSM4T(d, vb_s + (vIdx + kv * 16 * LDS_ + p * 16) * 2);
                mma_f16(o[2 * p], a, d);
                mma_f16(o[2 * p + 1], a, d + 2);
            }
        }

        __syncthreads();
        if (t + 2 < T) issueKV(t + 2);
    }

    l0 += __shfl_xor_sync(0xffffffffu, l0, 1);
    l0 += __shfl_xor_sync(0xffffffffu, l0, 2);
    l1 += __shfl_xor_sync(0xffffffffu, l1, 1);
    l1 += __shfl_xor_sync(0xffffffffu, l1, 2);
    float inv0 = 1.0f / l0, inv1 = 1.0f / l1;

    int lr0 = w * 16 + g, lr1 = lr0 + 8;
    __half* aob = ao + ((long)b * NTOK) * 1024 + h * 64;
    if (lr0 < qrows) {
        __half* rp = aob + (long)(q0 + lr0) * 1024 + 2 * t4;
        #pragma unroll
        for (int nt = 0; nt < 8; nt++)
            *(__half2*)(rp + nt * 8) = __floats2half2_rn(o[nt][0] * inv0, o[nt][1] * inv0);
    }
    if (lr1 < qrows) {
        __half* rp = aob + (long)(q0 + lr1) * 1024 + 2 * t4;
        #pragma unroll
        for (int nt = 0; nt < 8; nt++)
            *(__half2*)(rp + nt * 8) = __floats2half2_rn(o[nt][2] * inv1, o[nt][3] * inv1);
    }
}

// ---------------------------------------------------------------------------
// fp16 mma.sync GEMM (R9 exact): BM=128, BN=128, BK=32, warp tile 64x64,
// 128 threads (4 warps), 2 CTAs/SM, 3-stage cp.async + ldmatrix.
// ---------------------------------------------------------------------------
template<bool OUTH, bool GEGLU>
__global__ void __launch_bounds__(128, 2)
hgemm(const __half* __restrict__ A, const __half* __restrict__ Bm,
      void* __restrict__ Cv, const float* __restrict__ Res,
      int M, int N, int K, int lda, int ldb, int ldc,
      float alpha, int resRowMod, int ldres) {
    constexpr int MT = 4;
    constexpr int NT = 8;
    constexpr int A_ST_H = 128 * 40;
    constexpr int B_ST_H = 128 * 40;
    constexpr int ST_H   = A_ST_H + B_ST_H;

    extern __shared__ __align__(16) __half smem[];
    const uint32_t sb = smem_u32(smem);

    const int tid = threadIdx.x;
    const int wid = tid >> 5, lane = tid & 31;
    const int g = lane >> 2, t4 = lane & 3;
    const int wm = wid >> 1, wn = wid & 1;
    const int q8 = lane >> 3, r8 = lane & 7;

    const int rowBase = blockIdx.y * 128;
    const int colBase = blockIdx.x * 128;
    const int KC = (K + 31) >> 5;

    const int chA = tid & 3;
    const __half* aSrc[4];
    uint32_t aOff[4];
    bool aOk[4];
    #pragma unroll
    for (int e = 0; e < 4; e++) {
        int m = (tid >> 2) + 32 * e;
        int gr = rowBase + m;
        aOk[e] = gr < M;
        aSrc[e] = A + (long)(aOk[e] ? gr : 0) * lda + chA * 8;
        aOff[e] = (uint32_t)((m * 40 + chA * 8) * 2);
    }
    const __half* bSrc[4];
    uint32_t bOff[4];
    int bOkA[4];
    #pragma unroll
    for (int e = 0; e < 4; e++) {
        int n = (tid >> 2) + 32 * e;
        int gn = colBase + n;
        int srcRow;
        if (GEGLU) {
            int j = gn >> 4, ww = gn & 15;
            int f8 = j * 8 + (ww & 7);
            bOkA[e] = (f8 < FF_) ? 1 : 0;
            srcRow = (ww < 8) ? f8 : (FF_ + f8);
        } else {
            bOkA[e] = (gn < N) ? 1 : 0;
            srcRow = gn;
        }
        bSrc[e] = Bm + (long)(bOkA[e] ? srcRow : 0) * ldb + chA * 8;
        bOff[e] = (uint32_t)((n * 40 + chA * 8) * 2);
    }

    auto issue = [&](int c, int st) {
        const uint32_t stb = sb + (uint32_t)(st * ST_H * 2);
        int krem = K - (c << 5);
        int kb = (krem - chA * 8) * 2;
        kb = kb < 0 ? 0 : (kb > 16 ? 16 : kb);
        #pragma unroll
        for (int e = 0; e < 4; e++) {
            int bytes = aOk[e] ? kb : 0;
            cp16h(stb + aOff[e], bytes ? aSrc[e] : A, bytes);
            aSrc[e] += 32;
        }
        const uint32_t bstb = stb + (uint32_t)(A_ST_H * 2);
        #pragma unroll
        for (int e = 0; e < 4; e++) {
            int bytes = bOkA[e] ? kb : 0;
            cp16h(bstb + bOff[e], bytes ? bSrc[e] : Bm, bytes);
            bSrc[e] += 32;
        }
        CP_COMMIT();
    };

    float acc[MT][NT][4];
    #pragma unroll
    for (int i = 0; i < MT; i++)
        #pragma unroll
        for (int j = 0; j < NT; j++)
            #pragma unroll
            for (int q = 0; q < 4; q++) acc[i][j][q] = 0.0f;

    const int aIdx0 = (wm * 64 + (q8 & 1) * 8 + r8) * 40 + (q8 >> 1) * 8;
    const int bIdx0 = (wn * 64 + (q8 >> 1) * 8 + r8) * 40 + (q8 & 1) * 8;

    issue(0, 0);
    issue(1, 1);

    int st = 0;
    for (int c = 0; c < KC; c++) {
        CP_WAIT1();
        __syncthreads();
        if (c + 2 < KC) issue(c + 2, (st + 2) % 3);
        else CP_COMMIT();

        const uint32_t aStB = sb + (uint32_t)(st * ST_H * 2);
        const uint32_t bStB = aStB + (uint32_t)(A_ST_H * 2);

        #pragma unroll
        for (int ks = 0; ks < 2; ks++) {
            uint32_t af[MT][4], bf[NT][2];
            #pragma unroll
            for (int mt = 0; mt < MT; mt++)
                LDSM4(af[mt], aStB + (uint32_t)((aIdx0 + mt * 16 * 40 + ks * 16) * 2));
            #pragma unroll
            for (int p = 0; p < NT / 2; p++) {
                uint32_t d[4];
                LDSM4(d, bStB + (uint32_t)((bIdx0 + p * 16 * 40 + ks * 16) * 2));
                bf[2 * p][0] = d[0]; bf[2 * p][1] = d[1];
                bf[2 * p + 1][0] = d[2]; bf[2 * p + 1][1] = d[3];
            }
            #pragma unroll
            for (int mt = 0; mt < MT; mt++)
                #pragma unroll
                for (int nt = 0; nt < NT; nt++)
                    mma_f16(acc[mt][nt], af[mt], bf[nt]);
        }
        st++; if (st == 3) st = 0;
    }

    if (GEGLU) {
        __half* act = (__half*)Cv;
        const int actBase = (colBase >> 1) + wn * 32;
        #pragma unroll
        for (int mt = 0; mt < MT; mt++) {
            int r0 = rowBase + wm * 64 + mt * 16 + g;
            #pragma unroll
            for (int p = 0; p < NT / 2; p++) {
                int col = actBase + p * 8 + t4 * 2;
                #pragma unroll
                for (int hh = 0; hh < 2; hh++) {
                    int rr = r0 + hh * 8;
                    if (rr >= M) continue;
                    float v0 = acc[mt][2 * p][hh * 2];
                    float v1 = acc[mt][2 * p][hh * 2 + 1];
                    float g0 = acc[mt][2 * p + 1][hh * 2];
                    float g1 = acc[mt][2 * p + 1][hh * 2 + 1];
                    *(__half2*)(act + (long)rr * ldc + col) =
                        __floats2half2_rn(gelu_exact(g0) * v0, gelu_exact(g1) * v1);
                }
            }
        }
        return;
    }

    #pragma unroll
    for (int mt = 0; mt < MT; mt++) {
        int r0 = rowBase + wm * 64 + mt * 16 + g;
        #pragma unroll
        for (int nt = 0; nt < NT; nt++) {
            int col = colBase + wn * 64 + nt * 8 + t4 * 2;
            if (col >= N) continue;
            #pragma unroll
            for (int hh = 0; hh < 2; hh++) {
                int rr = r0 + hh * 8;
                if (rr >= M) continue;
                float vx = alpha * acc[mt][nt][hh * 2];
                float vy = alpha * acc[mt][nt][hh * 2 + 1];
                if (Res) {
                    int rx = resRowMod ? (rr % resRowMod) : rr;
                    float2 rv = *(const float2*)(Res + (long)rx * ldres + col);
                    vx += rv.x; vy += rv.y;
                }
                if (OUTH) {
                    *(__half2*)((__half*)Cv + (long)rr * ldc + col) = __floats2half2_rn(vx, vy);
                } else {
                    float2 v; v.x = vx; v.y = vy;
                    *(float2*)((float*)Cv + (long)rr * ldc + col) = v;
                }
            }
        }
    }
}

// ---------------------------------------------------------------------------
// Weight transpose (vectorized, R13 exact)
// ---------------------------------------------------------------------------
__global__ void __launch_bounds__(256)
transpose_kernel(const float* __restrict__ src,
                 __half* __restrict__ dst,
                 int K, int N, int ldd,
                 long srcZ, long dstZ, float scale) {
    __shared__ float tile[32][129];
    const int k0 = blockIdx.y * 32, n0 = blockIdx.x * 128;
    const long zS = (long)blockIdx.z * srcZ;
    const long zD = (long)blockIdx.z * dstZ;
    const int tx = threadIdx.x, ty = threadIdx.y;   // 32 x 8
    const int tid = ty * 32 + tx;

    #pragma unroll
    for (int it = 0; it < 4; it++) {
        int k = k0 + ty + it * 8;
        int n = n0 + tx * 4;
        if (k < K && n + 3 < N) {
            float4 v = *(const float4*)(src + zS + (long)k * N + n);
            tile[ty + it * 8][tx * 4 + 0] = v.x;
            tile[ty + it * 8][tx * 4 + 1] = v.y;
            tile[ty + it * 8][tx * 4 + 2] = v.z;
            tile[ty + it * 8][tx * 4 + 3] = v.w;
        }
    }
    __syncthreads();

    const int kk = tid & 15;
    const int nr = tid >> 4;
    const int k = k0 + 2 * kk;
    if (k < K) {
        #pragma unroll
        for (int it = 0; it < 8; it++) {
            int n = n0 + nr + it * 16;
            if (n < N)
                *(__half2*)(dst + zD + (long)n * ldd + k) =
                    __floats2half2_rn(scale * tile[2 * kk][nr + it * 16],
                                      scale * tile[2 * kk + 1][nr + it * 16]);
        }
    }
}

// ---------------------------------------------------------------------------
// Small SIMT GEMM (pool)   (R9 exact)
// ---------------------------------------------------------------------------
template<typename T>
__device__ __forceinline__ float ldf(const T* p) { return (float)*p; }
template<>
__device__ __forceinline__ float ldf<__half>(const __half* p) { return __half2float(*p); }

template<int BM, int BN, int BK, int TM, int TN, bool TB, typename TAT, typename TBT>
__global__ void __launch_bounds__((BM / TM) * (BN / TN))
gemm_kernel(const TAT* __restrict__ A, const TBT* __restrict__ Bm,
            float* __restrict__ C, const float* __restrict__ Res,
            int M, int Nn, int K,
            int lda, int ldb, int ldc,
            long sAb, long sAh, long sBb, long sBh, long sCb, long sCh, int Hdiv,
            float alpha, int resRowMod, int ldres) {
    constexpr int THREADS = (BM / TM) * (BN / TN);
    constexpr int AELEM = BM * BK / THREADS;
    constexpr int BELEM = BK * BN / THREADS;

    int z = blockIdx.z;
    int zb = z / Hdiv, zh = z - zb * Hdiv;
    A  += (long)zb * sAb + (long)zh * sAh;
    Bm += (long)zb * sBb + (long)zh * sBh;
    C  += (long)zb * sCb + (long)zh * sCh;

    __shared__ __align__(16) float As[BK][BM + 4];
    __shared__ __align__(16) float Bs[BK][BN + 4];

    int tid = threadIdx.x;
    int tcol = tid % (BN / TN);
    int trow = tid / (BN / TN);
    int rowBase = blockIdx.y * BM;
    int colBase = blockIdx.x * BN;

    float acc[TM][TN] = {};

    for (int k0 = 0; k0 < K; k0 += BK) {
        #pragma unroll
        for (int e = 0; e < AELEM; e++) {
            int idx = tid + e * THREADS;
            int m = idx / BK, kk = idx % BK;
            int gr = rowBase + m, gc = k0 + kk;
            As[kk][m] = (gr < M && gc < K) ? ldf(A + (long)gr * lda + gc) : 0.0f;
        }
        #pragma unroll
        for (int e = 0; e < BELEM; e++) {
            int idx = tid + e * THREADS;
            int kk, n;
            if (!TB) { kk = idx / BN; n = idx % BN; }
            else     { n = idx / BK;  kk = idx % BK; }
            int gc = colBase + n, gk = k0 + kk;
            float v = 0.0f;
            if (gc < Nn && gk < K)
                v = TB ? ldf(Bm + (long)gc * ldb + gk) : ldf(Bm + (long)gk * ldb + gc);
            Bs[kk][n] = v;
        }
        __syncthreads();

        #pragma unroll
        for (int kk = 0; kk < BK; kk++) {
            float a[TM], bb[TN];
            #pragma unroll
            for (int i = 0; i < TM; i++) a[i] = As[kk][trow * TM + i];
            #pragma unroll
            for (int j = 0; j < TN; j++) bb[j] = Bs[kk][tcol * TN + j];
            #pragma unroll
            for (int i = 0; i < TM; i++)
                #pragma unroll
                for (int j = 0; j < TN; j++)
                    acc[i][j] += a[i] * bb[j];
        }
        __syncthreads();
    }

    #pragma unroll
    for (int i = 0; i < TM; i++) {
        int r = rowBase + trow * TM + i;
        if (r >= M) continue;
        #pragma unroll
        for (int j = 0; j < TN; j++) {
            int c = colBase + tcol * TN + j;
            if (c >= Nn) continue;
            float v = alpha * acc[i][j];
            if (Res) {
                int rr = resRowMod ? (r % resRowMod) : r;
                v += Res[(long)rr * ldres + c];
            }
            C[(long)r * ldc + c] = v;
        }
    }
}

// ---------------------------------------------------------------------------
// Elementwise / reduction kernels
// ---------------------------------------------------------------------------
__device__ __forceinline__ float blk_reduce(float v, bool ismax) {
    __shared__ float red[9];
    #pragma unroll
    for (int o = 16; o; o >>= 1) {
        float u = __shfl_xor_sync(0xffffffffu, v, o);
        v = ismax ? fmaxf(v, u) : (v + u);
    }
    if ((threadIdx.x & 31) == 0) red[threadIdx.x >> 5] = v;
    __syncthreads();
    if (threadIdx.x == 0) {
        float r = red[0];
        int nw = blockDim.x >> 5;
        for (int w = 1; w < nw; w++) r = ismax ? fmaxf(r, red[w]) : (r + red[w]);
        red[8] = r;
    }
    __syncthreads();
    float r = red[8];
    __syncthreads();
    return r;
}

__device__ __forceinline__ int token_type(int j) {
    return j < 512 ? 0 : (j < 1024 ? 1 : 2);
}

__global__ void concat_kernel(const float4* __restrict__ m0,
                              const float4* __restrict__ m1,
                              const float4* __restrict__ fus,
                              float4* __restrict__ tokens) {
    int idx = blockIdx.x * blockDim.x + threadIdx.x;
    const int D4 = D_ / 4;
    int total = B_ * NTOK * D4;
    if (idx >= total) return;
    int d = idx % D4;
    int t = (idx / D4) % NTOK;
    int b = idx / (D4 * NTOK);
    float4 v;
    if (t < 512)       v = m0[((long)b * 512 + t) * D4 + d];
    else if (t < 1024) v = m1[((long)b * 512 + (t - 512)) * D4 + d];
    else               v = fus[(long)(t - 1024) * D4 + d];
    tokens[idx] = v;
}

// Warp-per-row LayerNorm: 8 rows/block, no barriers, single-pass stats.
__global__ void __launch_bounds__(256)
ln_kernel(const float* __restrict__ x,
          const float* __restrict__ gamma,
          __half* __restrict__ out) {
    const int lane = threadIdx.x & 31;
    const long row = (long)blockIdx.x * 8 + (threadIdx.x >> 5);
    const float4* xr = (const float4*)(x + row * D_);

    float4 v[8];
    float s = 0.f, s2 = 0.f;
    #pragma unroll
    for (int e = 0; e < 8; e++) {
        v[e] = xr[lane + e * 32];
        s  += v[e].x + v[e].y + v[e].z + v[e].w;
        s2 += v[e].x * v[e].x + v[e].y * v[e].y
            + v[e].z * v[e].z + v[e].w * v[e].w;
    }
    #pragma unroll
    for (int o = 16; o; o >>= 1) {
        s  += __shfl_xor_sync(0xffffffffu, s,  o);
        s2 += __shfl_xor_sync(0xffffffffu, s2, o);
    }
    float mu  = s * (1.0f / D_);
    float var = s2 * (1.0f / D_) - mu * mu;
    float inv = rsqrtf(var + 1e-5f);

    uint2* o2 = (uint2*)(out + row * D_);
    const float4* gm = (const float4*)gamma;
    #pragma unroll
    for (int e = 0; e < 8; e++) {
        float4 g = gm[lane + e * 32];
        uint2 pk;
        pk.x = packh2((v[e].x - mu) * inv * g.x, (v[e].y - mu) * inv * g.y);
        pk.y = packh2((v[e].z - mu) * inv * g.z, (v[e].w - mu) * inv * g.w);
        o2[lane + e * 32] = pk;
    }
}

__global__ void softmax_pool_kernel(float* __restrict__ sim) {
    long row = blockIdx.x;
    float* p = sim + row * NTOK;
    int r = (int)(row % 4);
    int tid = threadIdx.x;

    float vals[5];
    float mx = -3.4e38f;
    #pragma unroll
    for (int it = 0; it < 5; it++) {
        int j = tid + it * 256;
        float v = -3.4e38f;
        if (j < NTOK) {
            bool ok = (r == 3) || (token_type(j) == r);
            v = ok ? p[j] : -3.4e38f;
        }
        vals[it] = v;
        mx = fmaxf(mx, v);
    }
    mx = blk_reduce(mx, true);

    float e[5];
    float s = 0.0f;
    #pragma unroll
    for (int it = 0; it < 5; it++) {
        float ex = __expf(vals[it] - mx);
        e[it] = ex;
        s += ex;
    }
    s = blk_reduce(s, false);
    float inv = 1.0f / s;
    #pragma unroll
    for (int it = 0; it < 5; it++) {
        int j = tid + it * 256;
        if (j < NTOK) p[j] = e[it] * inv;
    }
}

// ---------------------------------------------------------------------------
// Host side
// ---------------------------------------------------------------------------
static constexpr int SM_H128  = 3 * (128 * 40 + 128 * 40) * 2;   // 61440
static constexpr int SM_FLASH = (64 * 72 + 4 * 128 * 72) * 2;    // 82944

static inline void hg(const __half* A, const __half* Bt, void* C, const float* Res,
                      int M, int Nn, int K, int lda, int ldbT, int ldc, float alpha,
                      bool outh, int resRowMod = 0, int ldres = 0) {
    dim3 grid((Nn + 127) / 128, (M + 127) / 128, 1);
    if (outh)
        hgemm<true, false><<<grid, 128, SM_H128>>>(
            A, Bt, C, Res, M, Nn, K, lda, ldbT, ldc, alpha, resRowMod, ldres);
    else
        hgemm<false, false><<<grid, 128, SM_H128>>>(
            A, Bt, C, Res, M, Nn, K, lda, ldbT, ldc, alpha, resRowMod, ldres);
}

extern "C" void kernel_launch(void* const* d_in, const int* in_sizes, int n_in,
                              void* d_out, int out_size) {
    const float* m0        = (const float*)d_in[0];
    const float* m1        = (const float*)d_in[1];
    const float* fusion    = (const float*)d_in[2];
    const float* ret_tok   = (const float*)d_in[3];
    const float* ln_gamma  = (const float*)d_in[4];
    const float* wq        = (const float*)d_in[5];
    const float* wkv       = (const float*)d_in[6];
    const float* wo        = (const float*)d_in[7];
    const float* ff_w1     = (const float*)d_in[8];
    const float* ff_w2     = (const float*)d_in[9];
    const float* pool_wq   = (const float*)d_in[10];
    const float* pool_wkv  = (const float*)d_in[11];
    const float* pool_wo   = (const float*)d_in[12];
    const float* final_g   = (const float*)d_in[13];
    float* out = (float*)d_out;

    cudaFuncSetAttribute(hgemm<true, false>,
                         cudaFuncAttributeMaxDynamicSharedMemorySize, SM_H128);
    cudaFuncSetAttribute(hgemm<false, false>,
                         cudaFuncAttributeMaxDynamicSharedMemorySize, SM_H128);
    cudaFuncSetAttribute(hgemm<true, true>,
                         cudaFuncAttributeMaxDynamicSharedMemorySize, SM_H128);
    cudaFuncSetAttribute(flash_kernel,
                         cudaFuncAttributeMaxDynamicSharedMemorySize, SM_FLASH);

    float *tokens, *simbuf, *poolq, *poolao;
    __half *hbuf, *qkvbuf, *kvbuf, *aobuf, *actbuf;
    __half *wqkvT, *woT, *ff1T, *ff2T, *pkvT;
    cudaGetSymbolAddress((void**)&tokens, g_tokens);
    cudaGetSymbolAddress((void**)&simbuf, g_sim);
    cudaGetSymbolAddress((void**)&poolq,  g_poolq);
    cudaGetSymbolAddress((void**)&poolao, g_poolao);
    cudaGetSymbolAddress((void**)&hbuf,   h_h);
    cudaGetSymbolAddress((void**)&qkvbuf, h_qkv);
    cudaGetSymbolAddress((void**)&kvbuf,  h_kv);
    cudaGetSymbolAddress((void**)&aobuf,  h_ao);
    cudaGetSymbolAddress((void**)&actbuf, h_act);
    cudaGetSymbolAddress((void**)&wqkvT,  h_wqkvT);
    cudaGetSymbolAddress((void**)&woT,    h_woT);
    cudaGetSymbolAddress((void**)&ff1T,   h_ff1T);
    cudaGetSymbolAddress((void**)&ff2T,   h_ff2T);
    cudaGetSymbolAddress((void**)&pkvT,   h_pkvT);

    const float scale = 0.125f;

    // --- weight pre-transposes (fp32 -> fp16; q-scale folded into wq) ---
    {
        dim3 thr(32, 8);
        const long zq = (long)3 * D_ * D_;
        transpose_kernel<<<dim3(8, 32, 4),   thr>>>(wq,  wqkvT, 1024, 1024, 1024,
                                                    (long)D_ * D_, zq, scale);
        transpose_kernel<<<dim3(16, 32, 4),  thr>>>(wkv, wqkvT + (long)D_ * D_,
                                                    1024, 2048, 1024,
                                                    (long)2 * D_ * D_, zq, 1.0f);
        transpose_kernel<<<dim3(8, 32, 4),   thr>>>(wo, woT, 1024, 1024, 1024,
                                                    (long)D_ * D_, (long)D_ * D_, 1.0f);
        transpose_kernel<<<dim3(43, 32, 4),  thr>>>(ff_w1, ff1T, 1024, 5460, 1024,
                                                    (long)D_ * FF2_, (long)FF2_ * D_, 1.0f);
        transpose_kernel<<<dim3(8, 86, 4),   thr>>>(ff_w2, ff2T, 2730, 1024, ACTLD,
                                                    (long)FF_ * D_, (long)D_ * ACTLD, 1.0f);
        transpose_kernel<<<dim3(16, 32, 1),  thr>>>(pool_wkv, pkvT, 1024, 2048, 1024,
                                                    0, 0, 1.0f);
    }

    {
        int total = B_ * NTOK * (D_ / 4);
        concat_kernel<<<(total + 255) / 256, 256>>>(
            (const float4*)m0, (const float4*)m1, (const float4*)fusion,
            (float4*)tokens);
    }

    const long sKVB = (long)NTOK * 2 * D_;

    for (int l = 0; l < L_; l++) {
        const __half* wqkvT_l = wqkvT + (long)l * 3 * D_ * D_;
        const __half* woT_l   = woT   + (long)l * D_ * D_;
        const __half* w1T_l   = ff1T  + (long)l * FF2_ * D_;
        const __half* w2T_l   = ff2T  + (long)l * D_ * ACTLD;
        const float*  g_l     = ln_gamma + (long)l * D_;

        // attention block
        ln_kernel<<<ROWS / 8, 256>>>(tokens, g_l, hbuf);
        hg(hbuf, wqkvT_l, qkvbuf, nullptr, ROWS, 3 * D_, D_, D_, D_, 3 * D_, 1.0f, true);
        flash_kernel<<<dim3(17, 1, B_ * H_), 128, SM_FLASH>>>(qkvbuf, aobuf);
        hg(aobuf, woT_l, tokens, tokens, ROWS, D_, D_, D_, D_, D_, 1.0f, false, 0, D_);

        // feed-forward block: FF1 + GEGLU fused
        ln_kernel<<<ROWS / 8, 256>>>(tokens, g_l, hbuf);
        hgemm<true, true><<<dim3(2 * ACTLD / 128, (ROWS + 127) / 128, 1),
                            128, SM_H128>>>(
            hbuf, w1T_l, actbuf, nullptr,
            ROWS, 2 * ACTLD, D_, D_, D_, ACTLD, 1.0f, 0, 0);
        hg(actbuf, w2T_l, tokens, tokens, ROWS, D_, FF_, ACTLD, ACTLD, D_, 1.0f, false, 0, D_);
    }

    // --- final LN + attention pooling ---
    ln_kernel<<<ROWS / 8, 256>>>(tokens, final_g, hbuf);

    gemm_kernel<64, 64, 16, 4, 4, false, float, float>
        <<<dim3(16, 1, 1), 256>>>(
        ret_tok, pool_wq, poolq, nullptr, 4, D_, D_, D_, D_, D_,
        0, 0, 0, 0, 0, 0, 1, scale, 0, 0);

    hg(hbuf, pkvT, kvbuf, nullptr, ROWS, 2 * D_, D_, D_, D_, 2 * D_, 1.0f, true);

    gemm_kernel<64, 64, 16, 4, 4, true, float, __half>
        <<<dim3((NTOK + 63) / 64, 1, B_ * H_), 256>>>(
        poolq, kvbuf, simbuf, nullptr,
        4, NTOK, DH_, D_, 2 * D_, NTOK,
        0L, DH_, sKVB, DH_,
        (long)H_ * 4 * NTOK, (long)4 * NTOK, H_,
        1.0f, 0, 0);

    softmax_pool_kernel<<<B_ * H_ * 4, 256>>>(simbuf);

    gemm_kernel<64, 64, 16, 4, 4, false, float, __half>
        <<<dim3(1, 1, B_ * H_), 256>>>(
        simbuf, kvbuf + D_, poolao, nullptr,
        4, DH_, NTOK, NTOK, 2 * D_, D_,
        (long)H_ * 4 * NTOK, (long)4 * NTOK,
        sKVB, DH_,
        (long)4 * D_, DH_, H_,
        1.0f, 0, 0);

    gemm_kernel<64, 64, 16, 4, 4, false, float, float>
        <<<dim3(16, 1, 1), 256>>>(
        poolao, pool_wo, out, ret_tok, B_ * 4, D_, D_, D_, D_, D_,
        0, 0, 0, 0, 0, 0, 1, 1.0f, /*resRowMod=*/4, /*ldres=*/D_);
}

// round 15
// speedup vs baseline: 1.1611x; 1.0098x over previous
#include <cuda_runtime.h>
#include <cuda_fp16.h>
#include <math.h>
#include <stdint.h>

// ---------------------------------------------------------------------------
// Problem constants
// ---------------------------------------------------------------------------
static constexpr int B_    = 4;
static constexpr int NTOK  = 1040;   // 512 + 512 + 16
static constexpr int D_    = 1024;
static constexpr int H_    = 16;
static constexpr int DH_   = 64;
static constexpr int L_    = 4;
static constexpr int FF_   = 2730;
static constexpr int FF2_  = 5460;
static constexpr int ROWS  = B_ * NTOK;   // 4160
static constexpr int ACTLD = 2752;        // act cols (43 blocks x 64), padded

// ---------------------------------------------------------------------------
// Device scratch
// ---------------------------------------------------------------------------
__device__ float  g_tokens[B_ * NTOK * D_];
__device__ float  g_sim   [B_ * H_ * 4 * NTOK];   // pool sim only
__device__ float  g_poolq [4 * D_];
__device__ float  g_poolao[B_ * 4 * D_];
__device__ __half h_h     [ROWS * D_];
__device__ __half h_qkv   [ROWS * 3 * D_];
__device__ __half h_kv    [ROWS * 2 * D_];        // pool kv
__device__ __half h_ao    [ROWS * D_];
__device__ __half h_act   [(long long)ROWS * ACTLD];
// transposed fp16 weights
__device__ __half h_wqkvT[(long long)L_ * 3 * D_ * D_];
__device__ __half h_woT  [L_ * D_ * D_];
__device__ __half h_ff1T [(long long)L_ * FF2_ * D_];
__device__ __half h_ff2T [(long long)L_ * D_ * ACTLD];   // pad rows stay zero
__device__ __half h_pkvT [2 * D_ * D_];

// ---------------------------------------------------------------------------
// Helpers
// ---------------------------------------------------------------------------
__device__ __forceinline__ uint32_t smem_u32(const void* p) {
    uint32_t a;
    asm("{ .reg .u64 t; cvta.to.shared.u64 t, %1; cvt.u32.u64 %0, t; }"
        : "=r"(a) : "l"(p));
    return a;
}

__device__ __forceinline__ void mma_f16(float* c, const uint32_t* a, const uint32_t* b) {
    asm volatile(
        "mma.sync.aligned.m16n8k16.row.col.f32.f16.f16.f32 "
        "{%0,%1,%2,%3}, {%4,%5,%6,%7}, {%8,%9}, {%0,%1,%2,%3};"
        : "+f"(c[0]), "+f"(c[1]), "+f"(c[2]), "+f"(c[3])
        : "r"(a[0]), "r"(a[1]), "r"(a[2]), "r"(a[3]), "r"(b[0]), "r"(b[1]));
}

#define LDSM4(d, addr)                                                         \
    asm volatile("ldmatrix.sync.aligned.m8n8.x4.shared.b16 {%0,%1,%2,%3}, [%4];" \
        : "=r"((d)[0]), "=r"((d)[1]), "=r"((d)[2]), "=r"((d)[3]) : "r"(addr))
#define LDSM4T(d, addr)                                                        \
    asm volatile("ldmatrix.sync.aligned.m8n8.x4.trans.shared.b16 {%0,%1,%2,%3}, [%4];" \
        : "=r"((d)[0]), "=r"((d)[1]), "=r"((d)[2]), "=r"((d)[3]) : "r"(addr))

__device__ __forceinline__ void cp16h(uint32_t dst, const __half* src, int bytes) {
    asm volatile("cp.async.cg.shared.global [%0], [%1], 16, %2;"
                 :: "r"(dst), "l"(src), "r"(bytes));
}
#define CP_COMMIT() asm volatile("cp.async.commit_group;" ::: "memory")
#define CP_WAIT1()  asm volatile("cp.async.wait_group 1;" ::: "memory")
#define CP_WAIT0()  asm volatile("cp.async.wait_group 0;" ::: "memory")

__device__ __forceinline__ uint32_t packh2(float x, float y) {
    __half2 h = __floats2half2_rn(x, y);
    return *(uint32_t*)&h;
}
__device__ __forceinline__ float gelu_exact(float g) {
    return 0.5f * g * (1.0f + erff(g * 0.70710678118654752f));
}

// ---------------------------------------------------------------------------
// Flash attention (block-masked), plain-sum softmax (scores bounded << 88).
// qkv: [B*NTOK][3072] fp16 (q pre-scaled), ao: [B*NTOK][1024] fp16.
// grid (17, 1, B*H), 128 threads.
// ---------------------------------------------------------------------------
__global__ void __launch_bounds__(128, 2)
flash_kernel(const __half* __restrict__ qkv, __half* __restrict__ ao) {
    constexpr int LDS_ = 72;
    constexpr int QOFF = 0;
    constexpr int KOFF = 64 * LDS_;
    constexpr int VOFF = KOFF + 2 * 128 * LDS_;
    extern __shared__ __half sm[];
    const uint32_t sb = smem_u32(sm);

    const int tid = threadIdx.x;
    const int w = tid >> 5, lane = tid & 31;
    const int g = lane >> 2, t4 = lane & 3;
    const int q8 = lane >> 3, r8 = lane & 7;

    const int bh = blockIdx.z;
    const int b = bh >> 4, h = bh & 15;
    const int qb = blockIdx.x;
    int q0, c0, clen, qrows;
    if (qb < 16) { q0 = qb * 64; c0 = (qb < 8) ? 0 : 512; clen = 512; qrows = 64; }
    else         { q0 = 1024;  c0 = 0;  clen = NTOK;  qrows = 16; }

    const __half* qb_g = qkv + ((long)b * NTOK) * 3072 + h * 64;
    const __half* kb_g = qkv + ((long)b * NTOK) * 3072 + 1024 + h * 64;
    const __half* vb_g = qkv + ((long)b * NTOK) * 3072 + 2048 + h * 64;

    {
        int row = tid >> 1;
        int gr = q0 + row;
        int bytes = (row < qrows) ? 16 : 0;
        const __half* src = qb_g + (long)(bytes ? gr : 0) * 3072 + (tid & 1) * 32;
        uint32_t dst = sb + (QOFF + row * LDS_ + (tid & 1) * 32) * 2;
        #pragma unroll
        for (int e = 0; e < 4; e++)
            cp16h(dst + e * 16, src + e * 8, bytes);
    }

    const int T = (clen + 127) >> 7;
    int issued = 0;
    auto issueKV = [&](int t) {
        int buf = t & 1;
        int j = c0 + t * 128 + tid;
        int bytes = (j < c0 + clen) ? 16 : 0;
        const __half* ks = kb_g + (long)(bytes ? j : 0) * 3072;
        const __half* vs = vb_g + (long)(bytes ? j : 0) * 3072;
        uint32_t kd = sb + (KOFF + buf * 128 * LDS_ + tid * LDS_) * 2;
        uint32_t vd = sb + (VOFF + buf * 128 * LDS_ + tid * LDS_) * 2;
        #pragma unroll
        for (int ch = 0; ch < 8; ch++) cp16h(kd + ch * 16, ks + ch * 8, bytes);
        #pragma unroll
        for (int ch = 0; ch < 8; ch++) cp16h(vd + ch * 16, vs + ch * 8, bytes);
        CP_COMMIT();
        issued++;
    };
    issueKV(0);
    if (T > 1) issueKV(1);

    float l0 = 0.f, l1 = 0.f;
    float o[8][4];
    #pragma unroll
    for (int i = 0; i < 8; i++)
        #pragma unroll
        for (int q = 0; q < 4; q++) o[i][q] = 0.f;

    const int aIdx = (w * 16 + (q8 & 1) * 8 + r8) * LDS_ + (q8 >> 1) * 8;
    const int kIdx = ((q8 >> 1) * 8 + r8) * LDS_ + (q8 & 1) * 8;
    const int vIdx = ((q8 & 1) * 8 + r8) * LDS_ + (q8 >> 1) * 8;

    for (int t = 0; t < T; t++) {
        if (issued - (t + 1) >= 1) { CP_WAIT1(); } else { CP_WAIT0(); }
        __syncthreads();

        const uint32_t kb_s = sb + (KOFF + (t & 1) * 128 * LDS_) * 2;
        const uint32_t vb_s = sb + (VOFF + (t & 1) * 128 * LDS_) * 2;
        const uint32_t qs = sb + QOFF * 2;

        float s[16][4];
        #pragma unroll
        for (int i = 0; i < 16; i++)
            #pragma unroll
            for (int q = 0; q < 4; q++) s[i][q] = 0.f;

        #pragma unroll
        for (int ks = 0; ks < 4; ks++) {
            uint32_t af[4];
            LDSM4(af, qs + (aIdx + ks * 16) * 2);
            #pragma unroll
            for (int p = 0; p < 8; p++) {
                uint32_t d[4];
                LDSM4(d, kb_s + (kIdx + p * 16 * LDS_ + ks * 16) * 2);
                mma_f16(s[2 * p], af, d);
                mma_f16(s[2 * p + 1], af, d + 2);
            }
        }

        int lim = clen - t * 128;
        if (lim < 128) {
            #pragma unroll
            for (int nt = 0; nt < 16; nt++) {
                int cc = nt * 8 + 2 * t4;
                if (cc >= lim)     { s[nt][0] = -1e30f; s[nt][2] = -1e30f; }
                if (cc + 1 >= lim) { s[nt][1] = -1e30f; s[nt][3] = -1e30f; }
            }
        }

        // plain-sum softmax accumulation (scores bounded, no overflow risk)
        uint32_t pf[16][2];
        #pragma unroll
        for (int nt = 0; nt < 16; nt++) {
            float p0 = __expf(s[nt][0]);
            float p1 = __expf(s[nt][1]);
            float p2 = __expf(s[nt][2]);
            float p3 = __expf(s[nt][3]);
            l0 += p0 + p1; l1 += p2 + p3;
            pf[nt][0] = packh2(p0, p1);
            pf[nt][1] = packh2(p2, p3);
        }

        #pragma unroll
        for (int kv = 0; kv < 8; kv++) {
            uint32_t a[4] = { pf[2 * kv][0], pf[2 * kv][1],
                              pf[2 * kv + 1][0], pf[2 * kv + 1][1] };
            #pragma unroll
            for (int p = 0; p < 4; p++) {
                uint32_t d[4];
                LDSM4T(d, vb_s + (vIdx + kv * 16 * LDS_ + p * 16) * 2);
                mma_f16(o[2 * p], a, d);
                mma_f16(o[2 * p + 1], a, d + 2);
            }
        }

        __syncthreads();
        if (t + 2 < T) issueKV(t + 2);
    }

    l0 += __shfl_xor_sync(0xffffffffu, l0, 1);
    l0 += __shfl_xor_sync(0xffffffffu, l0, 2);
    l1 += __shfl_xor_sync(0xffffffffu, l1, 1);
    l1 += __shfl_xor_sync(0xffffffffu, l1, 2);
    float inv0 = 1.0f / l0, inv1 = 1.0f / l1;

    int lr0 = w * 16 + g, lr1 = lr0 + 8;
    __half* aob = ao + ((long)b * NTOK) * 1024 + h * 64;
    if (lr0 < qrows) {
        __half* rp = aob + (long)(q0 + lr0) * 1024 + 2 * t4;
        #pragma unroll
        for (int nt = 0; nt < 8; nt++)
            *(__half2*)(rp + nt * 8) = __floats2half2_rn(o[nt][0] * inv0, o[nt][1] * inv0);
    }
    if (lr1 < qrows) {
        __half* rp = aob + (long)(q0 + lr1) * 1024 + 2 * t4;
        #pragma unroll
        for (int nt = 0; nt < 8; nt++)
            *(__half2*)(rp + nt * 8) = __floats2half2_rn(o[nt][2] * inv1, o[nt][3] * inv1);
    }
}

// ---------------------------------------------------------------------------
// fp16 mma.sync GEMM (R9 exact): BM=128, BN=128, BK=32, warp tile 64x64,
// 128 threads (4 warps), 2 CTAs/SM, 3-stage cp.async + ldmatrix.
// ---------------------------------------------------------------------------
template<bool OUTH, bool GEGLU>
__global__ void __launch_bounds__(128, 2)
hgemm(const __half* __restrict__ A, const __half* __restrict__ Bm,
      void* __restrict__ Cv, const float* __restrict__ Res,
      int M, int N, int K, int lda, int ldb, int ldc,
      float alpha, int resRowMod, int ldres) {
    constexpr int MT = 4;
    constexpr int NT = 8;
    constexpr int A_ST_H = 128 * 40;
    constexpr int B_ST_H = 128 * 40;
    constexpr int ST_H   = A_ST_H + B_ST_H;

    extern __shared__ __align__(16) __half smem[];
    const uint32_t sb = smem_u32(smem);

    const int tid = threadIdx.x;
    const int wid = tid >> 5, lane = tid & 31;
    const int g = lane >> 2, t4 = lane & 3;
    const int wm = wid >> 1, wn = wid & 1;
    const int q8 = lane >> 3, r8 = lane & 7;

    const int rowBase = blockIdx.y * 128;
    const int colBase = blockIdx.x * 128;
    const int KC = (K + 31) >> 5;

    const int chA = tid & 3;
    const __half* aSrc[4];
    uint32_t aOff[4];
    bool aOk[4];
    #pragma unroll
    for (int e = 0; e < 4; e++) {
        int m = (tid >> 2) + 32 * e;
        int gr = rowBase + m;
        aOk[e] = gr < M;
        aSrc[e] = A + (long)(aOk[e] ? gr : 0) * lda + chA * 8;
        aOff[e] = (uint32_t)((m * 40 + chA * 8) * 2);
    }
    const __half* bSrc[4];
    uint32_t bOff[4];
    int bOkA[4];
    #pragma unroll
    for (int e = 0; e < 4; e++) {
        int n = (tid >> 2) + 32 * e;
        int gn = colBase + n;
        int srcRow;
        if (GEGLU) {
            int j = gn >> 4, ww = gn & 15;
            int f8 = j * 8 + (ww & 7);
            bOkA[e] = (f8 < FF_) ? 1 : 0;
            srcRow = (ww < 8) ? f8 : (FF_ + f8);
        } else {
            bOkA[e] = (gn < N) ? 1 : 0;
            srcRow = gn;
        }
        bSrc[e] = Bm + (long)(bOkA[e] ? srcRow : 0) * ldb + chA * 8;
        bOff[e] = (uint32_t)((n * 40 + chA * 8) * 2);
    }

    auto issue = [&](int c, int st) {
        const uint32_t stb = sb + (uint32_t)(st * ST_H * 2);
        int krem = K - (c << 5);
        int kb = (krem - chA * 8) * 2;
        kb = kb < 0 ? 0 : (kb > 16 ? 16 : kb);
        #pragma unroll
        for (int e = 0; e < 4; e++) {
            int bytes = aOk[e] ? kb : 0;
            cp16h(stb + aOff[e], bytes ? aSrc[e] : A, bytes);
            aSrc[e] += 32;
        }
        const uint32_t bstb = stb + (uint32_t)(A_ST_H * 2);
        #pragma unroll
        for (int e = 0; e < 4; e++) {
            int bytes = bOkA[e] ? kb : 0;
            cp16h(bstb + bOff[e], bytes ? bSrc[e] : Bm, bytes);
            bSrc[e] += 32;
        }
        CP_COMMIT();
    };

    float acc[MT][NT][4];
    #pragma unroll
    for (int i = 0; i < MT; i++)
        #pragma unroll
        for (int j = 0; j < NT; j++)
            #pragma unroll
            for (int q = 0; q < 4; q++) acc[i][j][q] = 0.0f;

    const int aIdx0 = (wm * 64 + (q8 & 1) * 8 + r8) * 40 + (q8 >> 1) * 8;
    const int bIdx0 = (wn * 64 + (q8 >> 1) * 8 + r8) * 40 + (q8 & 1) * 8;

    issue(0, 0);
    issue(1, 1);

    int st = 0;
    for (int c = 0; c < KC; c++) {
        CP_WAIT1();
        __syncthreads();
        if (c + 2 < KC) issue(c + 2, (st + 2) % 3);
        else CP_COMMIT();

        const uint32_t aStB = sb + (uint32_t)(st * ST_H * 2);
        const uint32_t bStB = aStB + (uint32_t)(A_ST_H * 2);

        #pragma unroll
        for (int ks = 0; ks < 2; ks++) {
            uint32_t af[MT][4], bf[NT][2];
            #pragma unroll
            for (int mt = 0; mt < MT; mt++)
                LDSM4(af[mt], aStB + (uint32_t)((aIdx0 + mt * 16 * 40 + ks * 16) * 2));
            #pragma unroll
            for (int p = 0; p < NT / 2; p++) {
                uint32_t d[4];
                LDSM4(d, bStB + (uint32_t)((bIdx0 + p * 16 * 40 + ks * 16) * 2));
                bf[2 * p][0] = d[0]; bf[2 * p][1] = d[1];
                bf[2 * p + 1][0] = d[2]; bf[2 * p + 1][1] = d[3];
            }
            #pragma unroll
            for (int mt = 0; mt < MT; mt++)
                #pragma unroll
                for (int nt = 0; nt < NT; nt++)
                    mma_f16(acc[mt][nt], af[mt], bf[nt]);
        }
        st++; if (st == 3) st = 0;
    }

    if (GEGLU) {
        __half* act = (__half*)Cv;
        const int actBase = (colBase >> 1) + wn * 32;
        #pragma unroll
        for (int mt = 0; mt < MT; mt++) {
            int r0 = rowBase + wm * 64 + mt * 16 + g;
            #pragma unroll
            for (int p = 0; p < NT / 2; p++) {
                int col = actBase + p * 8 + t4 * 2;
                #pragma unroll
                for (int hh = 0; hh < 2; hh++) {
                    int rr = r0 + hh * 8;
                    if (rr >= M) continue;
                    float v0 = acc[mt][2 * p][hh * 2];
                    float v1 = acc[mt][2 * p][hh * 2 + 1];
                    float g0 = acc[mt][2 * p + 1][hh * 2];
                    float g1 = acc[mt][2 * p + 1][hh * 2 + 1];
                    *(__half2*)(act + (long)rr * ldc + col) =
                        __floats2half2_rn(gelu_exact(g0) * v0, gelu_exact(g1) * v1);
                }
            }
        }
        return;
    }

    #pragma unroll
    for (int mt = 0; mt < MT; mt++) {
        int r0 = rowBase + wm * 64 + mt * 16 + g;
        #pragma unroll
        for (int nt = 0; nt < NT; nt++) {
            int col = colBase + wn * 64 + nt * 8 + t4 * 2;
            if (col >= N) continue;
            #pragma unroll
            for (int hh = 0; hh < 2; hh++) {
                int rr = r0 + hh * 8;
                if (rr >= M) continue;
                float vx = alpha * acc[mt][nt][hh * 2];
                float vy = alpha * acc[mt][nt][hh * 2 + 1];
                if (Res) {
                    int rx = resRowMod ? (rr % resRowMod) : rr;
                    float2 rv = *(const float2*)(Res + (long)rx * ldres + col);
                    vx += rv.x; vy += rv.y;
                }
                if (OUTH) {
                    *(__half2*)((__half*)Cv + (long)rr * ldc + col) = __floats2half2_rn(vx, vy);
                } else {
                    float2 v; v.x = vx; v.y = vy;
                    *(float2*)((float*)Cv + (long)rr * ldc + col) = v;
                }
            }
        }
    }
}

// ---------------------------------------------------------------------------
// Weight transpose (vectorized, R13 exact)
// ---------------------------------------------------------------------------
__global__ void __launch_bounds__(256)
transpose_kernel(const float* __restrict__ src,
                 __half* __restrict__ dst,
                 int K, int N, int ldd,
                 long srcZ, long dstZ, float scale) {
    __shared__ float tile[32][129];
    const int k0 = blockIdx.y * 32, n0 = blockIdx.x * 128;
    const long zS = (long)blockIdx.z * srcZ;
    const long zD = (long)blockIdx.z * dstZ;
    const int tx = threadIdx.x, ty = threadIdx.y;   // 32 x 8
    const int tid = ty * 32 + tx;

    #pragma unroll
    for (int it = 0; it < 4; it++) {
        int k = k0 + ty + it * 8;
        int n = n0 + tx * 4;
        if (k < K && n + 3 < N) {
            float4 v = *(const float4*)(src + zS + (long)k * N + n);
            tile[ty + it * 8][tx * 4 + 0] = v.x;
            tile[ty + it * 8][tx * 4 + 1] = v.y;
            tile[ty + it * 8][tx * 4 + 2] = v.z;
            tile[ty + it * 8][tx * 4 + 3] = v.w;
        }
    }
    __syncthreads();

    const int kk = tid & 15;
    const int nr = tid >> 4;
    const int k = k0 + 2 * kk;
    if (k < K) {
        #pragma unroll
        for (int it = 0; it < 8; it++) {
            int n = n0 + nr + it * 16;
            if (n < N)
                *(__half2*)(dst + zD + (long)n * ldd + k) =
                    __floats2half2_rn(scale * tile[2 * kk][nr + it * 16],
                                      scale * tile[2 * kk + 1][nr + it * 16]);
        }
    }
}

// ---------------------------------------------------------------------------
// Small SIMT GEMM (pool)   (R9 exact)
// ---------------------------------------------------------------------------
template<typename T>
__device__ __forceinline__ float ldf(const T* p) { return (float)*p; }
template<>
__device__ __forceinline__ float ldf<__half>(const __half* p) { return __half2float(*p); }

template<int BM, int BN, int BK, int TM, int TN, bool TB, typename TAT, typename TBT>
__global__ void __launch_bounds__((BM / TM) * (BN / TN))
gemm_kernel(const TAT* __restrict__ A, const TBT* __restrict__ Bm,
            float* __restrict__ C, const float* __restrict__ Res,
            int M, int Nn, int K,
            int lda, int ldb, int ldc,
            long sAb, long sAh, long sBb, long sBh, long sCb, long sCh, int Hdiv,
            float alpha, int resRowMod, int ldres) {
    constexpr int THREADS = (BM / TM) * (BN / TN);
    constexpr int AELEM = BM * BK / THREADS;
    constexpr int BELEM = BK * BN / THREADS;

    int z = blockIdx.z;
    int zb = z / Hdiv, zh = z - zb * Hdiv;
    A  += (long)zb * sAb + (long)zh * sAh;
    Bm += (long)zb * sBb + (long)zh * sBh;
    C  += (long)zb * sCb + (long)zh * sCh;

    __shared__ __align__(16) float As[BK][BM + 4];
    __shared__ __align__(16) float Bs[BK][BN + 4];

    int tid = threadIdx.x;
    int tcol = tid % (BN / TN);
    int trow = tid / (BN / TN);
    int rowBase = blockIdx.y * BM;
    int colBase = blockIdx.x * BN;

    float acc[TM][TN] = {};

    for (int k0 = 0; k0 < K; k0 += BK) {
        #pragma unroll
        for (int e = 0; e < AELEM; e++) {
            int idx = tid + e * THREADS;
            int m = idx / BK, kk = idx % BK;
            int gr = rowBase + m, gc = k0 + kk;
            As[kk][m] = (gr < M && gc < K) ? ldf(A + (long)gr * lda + gc) : 0.0f;
        }
        #pragma unroll
        for (int e = 0; e < BELEM; e++) {
            int idx = tid + e * THREADS;
            int kk, n;
            if (!TB) { kk = idx / BN; n = idx % BN; }
            else     { n = idx / BK;  kk = idx % BK; }
            int gc = colBase + n, gk = k0 + kk;
            float v = 0.0f;
            if (gc < Nn && gk < K)
                v = TB ? ldf(Bm + (long)gc * ldb + gk) : ldf(Bm + (long)gk * ldb + gc);
            Bs[kk][n] = v;
        }
        __syncthreads();

        #pragma unroll
        for (int kk = 0; kk < BK; kk++) {
            float a[TM], bb[TN];
            #pragma unroll
            for (int i = 0; i < TM; i++) a[i] = As[kk][trow * TM + i];
            #pragma unroll
            for (int j = 0; j < TN; j++) bb[j] = Bs[kk][tcol * TN + j];
            #pragma unroll
            for (int i = 0; i < TM; i++)
                #pragma unroll
                for (int j = 0; j < TN; j++)
                    acc[i][j] += a[i] * bb[j];
        }
        __syncthreads();
    }

    #pragma unroll
    for (int i = 0; i < TM; i++) {
        int r = rowBase + trow * TM + i;
        if (r >= M) continue;
        #pragma unroll
        for (int j = 0; j < TN; j++) {
            int c = colBase + tcol * TN + j;
            if (c >= Nn) continue;
            float v = alpha * acc[i][j];
            if (Res) {
                int rr = resRowMod ? (r % resRowMod) : r;
                v += Res[(long)rr * ldres + c];
            }
            C[(long)r * ldc + c] = v;
        }
    }
}

// ---------------------------------------------------------------------------
// Elementwise / reduction kernels
// ---------------------------------------------------------------------------
__device__ __forceinline__ float blk_reduce(float v, bool ismax) {
    __shared__ float red[9];
    #pragma unroll
    for (int o = 16; o; o >>= 1) {
        float u = __shfl_xor_sync(0xffffffffu, v, o);
        v = ismax ? fmaxf(v, u) : (v + u);
    }
    if ((threadIdx.x & 31) == 0) red[threadIdx.x >> 5] = v;
    __syncthreads();
    if (threadIdx.x == 0) {
        float r = red[0];
        int nw = blockDim.x >> 5;
        for (int w = 1; w < nw; w++) r = ismax ? fmaxf(r, red[w]) : (r + red[w]);
        red[8] = r;
    }
    __syncthreads();
    float r = red[8];
    __syncthreads();
    return r;
}

__device__ __forceinline__ int token_type(int j) {
    return j < 512 ? 0 : (j < 1024 ? 1 : 2);
}

// Fused concat + layer-0 LayerNorm: warp per row; writes fp32 tokens and
// gamma-scaled fp16 LN output. grid = ROWS/8, 256 threads.
__global__ void __launch_bounds__(256)
concat_ln_kernel(const float4* __restrict__ m0,
                 const float4* __restrict__ m1,
                 const float4* __restrict__ fus,
                 const float* __restrict__ gamma,
                 float4* __restrict__ tokens,
                 __half* __restrict__ out) {
    const int lane = threadIdx.x & 31;
    const long row = (long)blockIdx.x * 8 + (threadIdx.x >> 5);
    const int t = (int)(row % NTOK);
    const int b = (int)(row / NTOK);

    const float4* src;
    if (t < 512)       src = m0 + ((long)b * 512 + t) * (D_ / 4);
    else if (t < 1024) src = m1 + ((long)b * 512 + (t - 512)) * (D_ / 4);
    else               src = fus + (long)(t - 1024) * (D_ / 4);

    float4 v[8];
    float s = 0.f, s2 = 0.f;
    #pragma unroll
    for (int e = 0; e < 8; e++) {
        v[e] = src[lane + e * 32];
        s  += v[e].x + v[e].y + v[e].z + v[e].w;
        s2 += v[e].x * v[e].x + v[e].y * v[e].y
            + v[e].z * v[e].z + v[e].w * v[e].w;
    }
    float4* tr = tokens + row * (D_ / 4);
    #pragma unroll
    for (int e = 0; e < 8; e++) tr[lane + e * 32] = v[e];

    #pragma unroll
    for (int o = 16; o; o >>= 1) {
        s  += __shfl_xor_sync(0xffffffffu, s,  o);
        s2 += __shfl_xor_sync(0xffffffffu, s2, o);
    }
    float mu  = s * (1.0f / D_);
    float var = s2 * (1.0f / D_) - mu * mu;
    float inv = rsqrtf(var + 1e-5f);

    uint2* o2 = (uint2*)(out + row * D_);
    const float4* gm = (const float4*)gamma;
    #pragma unroll
    for (int e = 0; e < 8; e++) {
        float4 g = gm[lane + e * 32];
        uint2 pk;
        pk.x = packh2((v[e].x - mu) * inv * g.x, (v[e].y - mu) * inv * g.y);
        pk.y = packh2((v[e].z - mu) * inv * g.z, (v[e].w - mu) * inv * g.w);
        o2[lane + e * 32] = pk;
    }
}

// Warp-per-row LayerNorm (R14 exact)
__global__ void __launch_bounds__(256)
ln_kernel(const float* __restrict__ x,
          const float* __restrict__ gamma,
          __half* __restrict__ out) {
    const int lane = threadIdx.x & 31;
    const long row = (long)blockIdx.x * 8 + (threadIdx.x >> 5);
    const float4* xr = (const float4*)(x + row * D_);

    float4 v[8];
    float s = 0.f, s2 = 0.f;
    #pragma unroll
    for (int e = 0; e < 8; e++) {
        v[e] = xr[lane + e * 32];
        s  += v[e].x + v[e].y + v[e].z + v[e].w;
        s2 += v[e].x * v[e].x + v[e].y * v[e].y
            + v[e].z * v[e].z + v[e].w * v[e].w;
    }
    #pragma unroll
    for (int o = 16; o; o >>= 1) {
        s  += __shfl_xor_sync(0xffffffffu, s,  o);
        s2 += __shfl_xor_sync(0xffffffffu, s2, o);
    }
    float mu  = s * (1.0f / D_);
    float var = s2 * (1.0f / D_) - mu * mu;
    float inv = rsqrtf(var + 1e-5f);

    uint2* o2 = (uint2*)(out + row * D_);
    const float4* gm = (const float4*)gamma;
    #pragma unroll
    for (int e = 0; e < 8; e++) {
        float4 g = gm[lane + e * 32];
        uint2 pk;
        pk.x = packh2((v[e].x - mu) * inv * g.x, (v[e].y - mu) * inv * g.y);
        pk.y = packh2((v[e].z - mu) * inv * g.z, (v[e].w - mu) * inv * g.w);
        o2[lane + e * 32] = pk;
    }
}

__global__ void softmax_pool_kernel(float* __restrict__ sim) {
    long row = blockIdx.x;
    float* p = sim + row * NTOK;
    int r = (int)(row % 4);
    int tid = threadIdx.x;

    float vals[5];
    float mx = -3.4e38f;
    #pragma unroll
    for (int it = 0; it < 5; it++) {
        int j = tid + it * 256;
        float v = -3.4e38f;
        if (j < NTOK) {
            bool ok = (r == 3) || (token_type(j) == r);
            v = ok ? p[j] : -3.4e38f;
        }
        vals[it] = v;
        mx = fmaxf(mx, v);
    }
    mx = blk_reduce(mx, true);

    float e[5];
    float s = 0.0f;
    #pragma unroll
    for (int it = 0; it < 5; it++) {
        float ex = __expf(vals[it] - mx);
        e[it] = ex;
        s += ex;
    }
    s = blk_reduce(s, false);
    float inv = 1.0f / s;
    #pragma unroll
    for (int it = 0; it < 5; it++) {
        int j = tid + it * 256;
        if (j < NTOK) p[j] = e[it] * inv;
    }
}

// ---------------------------------------------------------------------------
// Host side
// ---------------------------------------------------------------------------
static constexpr int SM_H128  = 3 * (128 * 40 + 128 * 40) * 2;   // 61440
static constexpr int SM_FLASH = (64 * 72 + 4 * 128 * 72) * 2;    // 82944

static inline void hg(const __half* A, const __half* Bt, void* C, const float* Res,
                      int M, int Nn, int K, int lda, int ldbT, int ldc, float alpha,
                      bool outh, int resRowMod = 0, int ldres = 0) {
    dim3 grid((Nn + 127) / 128, (M + 127) / 128, 1);
    if (outh)
        hgemm<true, false><<<grid, 128, SM_H128>>>(
            A, Bt, C, Res, M, Nn, K, lda, ldbT, ldc, alpha, resRowMod, ldres);
    else
        hgemm<false, false><<<grid, 128, SM_H128>>>(
            A, Bt, C, Res, M, Nn, K, lda, ldbT, ldc, alpha, resRowMod, ldres);
}

extern "C" void kernel_launch(void* const* d_in, const int* in_sizes, int n_in,
                              void* d_out, int out_size) {
    const float* m0        = (const float*)d_in[0];
    const float* m1        = (const float*)d_in[1];
    const float* fusion    = (const float*)d_in[2];
    const float* ret_tok   = (const float*)d_in[3];
    const float* ln_gamma  = (const float*)d_in[4];
    const float* wq        = (const float*)d_in[5];
    const float* wkv       = (const float*)d_in[6];
    const float* wo        = (const float*)d_in[7];
    const float* ff_w1     = (const float*)d_in[8];
    const float* ff_w2     = (const float*)d_in[9];
    const float* pool_wq   = (const float*)d_in[10];
    const float* pool_wkv  = (const float*)d_in[11];
    const float* pool_wo   = (const float*)d_in[12];
    const float* final_g   = (const float*)d_in[13];
    float* out = (float*)d_out;

    cudaFuncSetAttribute(hgemm<true, false>,
                         cudaFuncAttributeMaxDynamicSharedMemorySize, SM_H128);
    cudaFuncSetAttribute(hgemm<false, false>,
                         cudaFuncAttributeMaxDynamicSharedMemorySize, SM_H128);
    cudaFuncSetAttribute(hgemm<true, true>,
                         cudaFuncAttributeMaxDynamicSharedMemorySize, SM_H128);
    cudaFuncSetAttribute(flash_kernel,
                         cudaFuncAttributeMaxDynamicSharedMemorySize, SM_FLASH);

    float *tokens, *simbuf, *poolq, *poolao;
    __half *hbuf, *qkvbuf, *kvbuf, *aobuf, *actbuf;
    __half *wqkvT, *woT, *ff1T, *ff2T, *pkvT;
    cudaGetSymbolAddress((void**)&tokens, g_tokens);
    cudaGetSymbolAddress((void**)&simbuf, g_sim);
    cudaGetSymbolAddress((void**)&poolq,  g_poolq);
    cudaGetSymbolAddress((void**)&poolao, g_poolao);
    cudaGetSymbolAddress((void**)&hbuf,   h_h);
    cudaGetSymbolAddress((void**)&qkvbuf, h_qkv);
    cudaGetSymbolAddress((void**)&kvbuf,  h_kv);
    cudaGetSymbolAddress((void**)&aobuf,  h_ao);
    cudaGetSymbolAddress((void**)&actbuf, h_act);
    cudaGetSymbolAddress((void**)&wqkvT,  h_wqkvT);
    cudaGetSymbolAddress((void**)&woT,    h_woT);
    cudaGetSymbolAddress((void**)&ff1T,   h_ff1T);
    cudaGetSymbolAddress((void**)&ff2T,   h_ff2T);
    cudaGetSymbolAddress((void**)&pkvT,   h_pkvT);

    const float scale = 0.125f;

    // --- weight pre-transposes (fp32 -> fp16; q-scale folded into wq) ---
    {
        dim3 thr(32, 8);
        const long zq = (long)3 * D_ * D_;
        transpose_kernel<<<dim3(8, 32, 4),   thr>>>(wq,  wqkvT, 1024, 1024, 1024,
                                                    (long)D_ * D_, zq, scale);
        transpose_kernel<<<dim3(16, 32, 4),  thr>>>(wkv, wqkvT + (long)D_ * D_,
                                                    1024, 2048, 1024,
                                                    (long)2 * D_ * D_, zq, 1.0f);
        transpose_kernel<<<dim3(8, 32, 4),   thr>>>(wo, woT, 1024, 1024, 1024,
                                                    (long)D_ * D_, (long)D_ * D_, 1.0f);
        transpose_kernel<<<dim3(43, 32, 4),  thr>>>(ff_w1, ff1T, 1024, 5460, 1024,
                                                    (long)D_ * FF2_, (long)FF2_ * D_, 1.0f);
        transpose_kernel<<<dim3(8, 86, 4),   thr>>>(ff_w2, ff2T, 2730, 1024, ACTLD,
                                                    (long)FF_ * D_, (long)D_ * ACTLD, 1.0f);
        transpose_kernel<<<dim3(16, 32, 1),  thr>>>(pool_wkv, pkvT, 1024, 2048, 1024,
                                                    0, 0, 1.0f);
    }

    // concat fused with layer-0 attention LN
    concat_ln_kernel<<<ROWS / 8, 256>>>(
        (const float4*)m0, (const float4*)m1, (const float4*)fusion,
        ln_gamma, (float4*)tokens, hbuf);

    const long sKVB = (long)NTOK * 2 * D_;

    for (int l = 0; l < L_; l++) {
        const __half* wqkvT_l = wqkvT + (long)l * 3 * D_ * D_;
        const __half* woT_l   = woT   + (long)l * D_ * D_;
        const __half* w1T_l   = ff1T  + (long)l * FF2_ * D_;
        const __half* w2T_l   = ff2T  + (long)l * D_ * ACTLD;
        const float*  g_l     = ln_gamma + (long)l * D_;

        // attention block (layer 0's LN already produced by concat_ln)
        if (l > 0) ln_kernel<<<ROWS / 8, 256>>>(tokens, g_l, hbuf);
        hg(hbuf, wqkvT_l, qkvbuf, nullptr, ROWS, 3 * D_, D_, D_, D_, 3 * D_, 1.0f, true);
        flash_kernel<<<dim3(17, 1, B_ * H_), 128, SM_FLASH>>>(qkvbuf, aobuf);
        hg(aobuf, woT_l, tokens, tokens, ROWS, D_, D_, D_, D_, D_, 1.0f, false, 0, D_);

        // feed-forward block: FF1 + GEGLU fused
        ln_kernel<<<ROWS / 8, 256>>>(tokens, g_l, hbuf);
        hgemm<true, true><<<dim3(2 * ACTLD / 128, (ROWS + 127) / 128, 1),
                            128, SM_H128>>>(
            hbuf, w1T_l, actbuf, nullptr,
            ROWS, 2 * ACTLD, D_, D_, D_, ACTLD, 1.0f, 0, 0);
        hg(actbuf, w2T_l, tokens, tokens, ROWS, D_, FF_, ACTLD, ACTLD, D_, 1.0f, false, 0, D_);
    }

    // --- final LN + attention pooling ---
    ln_kernel<<<ROWS / 8, 256>>>(tokens, final_g, hbuf);

    gemm_kernel<64, 64, 16, 4, 4, false, float, float>
        <<<dim3(16, 1, 1), 256>>>(
        ret_tok, pool_wq, poolq, nullptr, 4, D_, D_, D_, D_, D_,
        0, 0, 0, 0, 0, 0, 1, scale, 0, 0);

    hg(hbuf, pkvT, kvbuf, nullptr, ROWS, 2 * D_, D_, D_, D_, 2 * D_, 1.0f, true);

    gemm_kernel<64, 64, 16, 4, 4, true, float, __half>
        <<<dim3((NTOK + 63) / 64, 1, B_ * H_), 256>>>(
        poolq, kvbuf, simbuf, nullptr,
        4, NTOK, DH_, D_, 2 * D_, NTOK,
        0L, DH_, sKVB, DH_,
        (long)H_ * 4 * NTOK, (long)4 * NTOK, H_,
        1.0f, 0, 0);

    softmax_pool_kernel<<<B_ * H_ * 4, 256>>>(simbuf);

    gemm_kernel<64, 64, 16, 4, 4, false, float, __half>
        <<<dim3(1, 1, B_ * H_), 256>>>(
        simbuf, kvbuf + D_, poolao, nullptr,
        4, DH_, NTOK, NTOK, 2 * D_, D_,
        (long)H_ * 4 * NTOK, (long)4 * NTOK,
        sKVB, DH_,
        (long)4 * D_, DH_, H_,
        1.0f, 0, 0);

    gemm_kernel<64, 64, 16, 4, 4, false, float, float>
        <<<dim3(16, 1, 1), 256>>>(
        poolao, pool_wo, out, ret_tok, B_ * 4, D_, D_, D_, D_, D_,
        0, 0, 0, 0, 0, 0, 1, 1.0f, /*resRowMod=*/4, /*ldres=*/D_);
}

// round 16
// speedup vs baseline: 1.2037x; 1.0367x over previous
#include <cuda_runtime.h>
#include <cuda_fp16.h>
#include <math.h>
#include <stdint.h>

// ---------------------------------------------------------------------------
// Problem constants
// ---------------------------------------------------------------------------
static constexpr int B_    = 4;
static constexpr int NTOK  = 1040;   // 512 + 512 + 16
static constexpr int D_    = 1024;
static constexpr int H_    = 16;
static constexpr int DH_   = 64;
static constexpr int L_    = 4;
static constexpr int FF_   = 2730;
static constexpr int FF2_  = 5460;
static constexpr int ROWS  = B_ * NTOK;   // 4160
static constexpr int ACTLD = 2752;        // act cols (43 blocks x 64), padded

// ---------------------------------------------------------------------------
// Device scratch
// ---------------------------------------------------------------------------
__device__ float  g_sim   [B_ * H_ * 4 * NTOK];   // pool sim only
__device__ float  g_poolq [4 * D_];
__device__ float  g_poolao[B_ * 4 * D_];
__device__ __half h_tok   [ROWS * D_];            // fp16 residual stream
__device__ __half h_h     [ROWS * D_];
__device__ __half h_qkv   [ROWS * 3 * D_];
__device__ __half h_kv    [ROWS * 2 * D_];        // pool kv
__device__ __half h_ao    [ROWS * D_];
__device__ __half h_act   [(long long)ROWS * ACTLD];
// transposed fp16 weights
__device__ __half h_wqkvT[(long long)L_ * 3 * D_ * D_];
__device__ __half h_woT  [L_ * D_ * D_];
__device__ __half h_ff1T [(long long)L_ * FF2_ * D_];
__device__ __half h_ff2T [(long long)L_ * D_ * ACTLD];   // pad rows stay zero
__device__ __half h_pkvT [2 * D_ * D_];

// ---------------------------------------------------------------------------
// Helpers
// ---------------------------------------------------------------------------
__device__ __forceinline__ uint32_t smem_u32(const void* p) {
    uint32_t a;
    asm("{ .reg .u64 t; cvta.to.shared.u64 t, %1; cvt.u32.u64 %0, t; }"
        : "=r"(a) : "l"(p));
    return a;
}

__device__ __forceinline__ void mma_f16(float* c, const uint32_t* a, const uint32_t* b) {
    asm volatile(
        "mma.sync.aligned.m16n8k16.row.col.f32.f16.f16.f32 "
        "{%0,%1,%2,%3}, {%4,%5,%6,%7}, {%8,%9}, {%0,%1,%2,%3};"
        : "+f"(c[0]), "+f"(c[1]), "+f"(c[2]), "+f"(c[3])
        : "r"(a[0]), "r"(a[1]), "r"(a[2]), "r"(a[3]), "r"(b[0]), "r"(b[1]));
}

#define LDSM4(d, addr)                                                         \
    asm volatile("ldmatrix.sync.aligned.m8n8.x4.shared.b16 {%0,%1,%2,%3}, [%4];" \
        : "=r"((d)[0]), "=r"((d)[1]), "=r"((d)[2]), "=r"((d)[3]) : "r"(addr))
#define LDSM4T(d, addr)                                                        \
    asm volatile("ldmatrix.sync.aligned.m8n8.x4.trans.shared.b16 {%0,%1,%2,%3}, [%4];" \
        : "=r"((d)[0]), "=r"((d)[1]), "=r"((d)[2]), "=r"((d)[3]) : "r"(addr))

__device__ __forceinline__ void cp16h(uint32_t dst, const __half* src, int bytes) {
    asm volatile("cp.async.cg.shared.global [%0], [%1], 16, %2;"
                 :: "r"(dst), "l"(src), "r"(bytes));
}
#define CP_COMMIT() asm volatile("cp.async.commit_group;" ::: "memory")
#define CP_WAIT1()  asm volatile("cp.async.wait_group 1;" ::: "memory")
#define CP_WAIT0()  asm volatile("cp.async.wait_group 0;" ::: "memory")

__device__ __forceinline__ uint32_t packh2(float x, float y) {
    __half2 h = __floats2half2_rn(x, y);
    return *(uint32_t*)&h;
}
__device__ __forceinline__ float gelu_exact(float g) {
    return 0.5f * g * (1.0f + erff(g * 0.70710678118654752f));
}

// ---------------------------------------------------------------------------
// Flash attention (block-masked), plain-sum softmax (scores bounded << 88).
// qkv: [B*NTOK][3072] fp16 (q pre-scaled), ao: [B*NTOK][1024] fp16.
// grid (17, 1, B*H), 128 threads.  (R15 exact)
// ---------------------------------------------------------------------------
__global__ void __launch_bounds__(128, 2)
flash_kernel(const __half* __restrict__ qkv, __half* __restrict__ ao) {
    constexpr int LDS_ = 72;
    constexpr int QOFF = 0;
    constexpr int KOFF = 64 * LDS_;
    constexpr int VOFF = KOFF + 2 * 128 * LDS_;
    extern __shared__ __half sm[];
    const uint32_t sb = smem_u32(sm);

    const int tid = threadIdx.x;
    const int w = tid >> 5, lane = tid & 31;
    const int g = lane >> 2, t4 = lane & 3;
    const int q8 = lane >> 3, r8 = lane & 7;

    const int bh = blockIdx.z;
    const int b = bh >> 4, h = bh & 15;
    const int qb = blockIdx.x;
    int q0, c0, clen, qrows;
    if (qb < 16) { q0 = qb * 64; c0 = (qb < 8) ? 0 : 512; clen = 512; qrows = 64; }
    else         { q0 = 1024;  c0 = 0;  clen = NTOK;  qrows = 16; }

    const __half* qb_g = qkv + ((long)b * NTOK) * 3072 + h * 64;
    const __half* kb_g = qkv + ((long)b * NTOK) * 3072 + 1024 + h * 64;
    const __half* vb_g = qkv + ((long)b * NTOK) * 3072 + 2048 + h * 64;

    {
        int row = tid >> 1;
        int gr = q0 + row;
        int bytes = (row < qrows) ? 16 : 0;
        const __half* src = qb_g + (long)(bytes ? gr : 0) * 3072 + (tid & 1) * 32;
        uint32_t dst = sb + (QOFF + row * LDS_ + (tid & 1) * 32) * 2;
        #pragma unroll
        for (int e = 0; e < 4; e++)
            cp16h(dst + e * 16, src + e * 8, bytes);
    }

    const int T = (clen + 127) >> 7;
    int issued = 0;
    auto issueKV = [&](int t) {
        int buf = t & 1;
        int j = c0 + t * 128 + tid;
        int bytes = (j < c0 + clen) ? 16 : 0;
        const __half* ks = kb_g + (long)(bytes ? j : 0) * 3072;
        const __half* vs = vb_g + (long)(bytes ? j : 0) * 3072;
        uint32_t kd = sb + (KOFF + buf * 128 * LDS_ + tid * LDS_) * 2;
        uint32_t vd = sb + (VOFF + buf * 128 * LDS_ + tid * LDS_) * 2;
        #pragma unroll
        for (int ch = 0; ch < 8; ch++) cp16h(kd + ch * 16, ks + ch * 8, bytes);
        #pragma unroll
        for (int ch = 0; ch < 8; ch++) cp16h(vd + ch * 16, vs + ch * 8, bytes);
        CP_COMMIT();
        issued++;
    };
    issueKV(0);
    if (T > 1) issueKV(1);

    float l0 = 0.f, l1 = 0.f;
    float o[8][4];
    #pragma unroll
    for (int i = 0; i < 8; i++)
        #pragma unroll
        for (int q = 0; q < 4; q++) o[i][q] = 0.f;

    const int aIdx = (w * 16 + (q8 & 1) * 8 + r8) * LDS_ + (q8 >> 1) * 8;
    const int kIdx = ((q8 >> 1) * 8 + r8) * LDS_ + (q8 & 1) * 8;
    const int vIdx = ((q8 & 1) * 8 + r8) * LDS_ + (q8 >> 1) * 8;

    for (int t = 0; t < T; t++) {
        if (issued - (t + 1) >= 1) { CP_WAIT1(); } else { CP_WAIT0(); }
        __syncthreads();

        const uint32_t kb_s = sb + (KOFF + (t & 1) * 128 * LDS_) * 2;
        const uint32_t vb_s = sb + (VOFF + (t & 1) * 128 * LDS_) * 2;
        const uint32_t qs = sb + QOFF * 2;

        float s[16][4];
        #pragma unroll
        for (int i = 0; i < 16; i++)
            #pragma unroll
            for (int q = 0; q < 4; q++) s[i][q] = 0.f;

        #pragma unroll
        for (int ks = 0; ks < 4; ks++) {
            uint32_t af[4];
            LDSM4(af, qs + (aIdx + ks * 16) * 2);
            #pragma unroll
            for (int p = 0; p < 8; p++) {
                uint32_t d[4];
                LDSM4(d, kb_s + (kIdx + p * 16 * LDS_ + ks * 16) * 2);
                mma_f16(s[2 * p], af, d);
                mma_f16(s[2 * p + 1], af, d + 2);
            }
        }

        int lim = clen - t * 128;
        if (lim < 128) {
            #pragma unroll
            for (int nt = 0; nt < 16; nt++) {
                int cc = nt * 8 + 2 * t4;
                if (cc >= lim)     { s[nt][0] = -1e30f; s[nt][2] = -1e30f; }
                if (cc + 1 >= lim) { s[nt][1] = -1e30f; s[nt][3] = -1e30f; }
            }
        }

        uint32_t pf[16][2];
        #pragma unroll
        for (int nt = 0; nt < 16; nt++) {
            float p0 = __expf(s[nt][0]);
            float p1 = __expf(s[nt][1]);
            float p2 = __expf(s[nt][2]);
            float p3 = __expf(s[nt][3]);
            l0 += p0 + p1; l1 += p2 + p3;
            pf[nt][0] = packh2(p0, p1);
            pf[nt][1] = packh2(p2, p3);
        }

        #pragma unroll
        for (int kv = 0; kv < 8; kv++) {
            uint32_t a[4] = { pf[2 * kv][0], pf[2 * kv][1],
                              pf[2 * kv + 1][0], pf[2 * kv + 1][1] };
            #pragma unroll
            for (int p = 0; p < 4; p++) {
                uint32_t d[4];
                LDSM4T(d, vb_s + (vIdx + kv * 16 * LDS_ + p * 16) * 2);
                mma_f16(o[2 * p], a, d);
                mma_f16(o[2 * p + 1], a, d + 2);
            }
        }

        __syncthreads();
        if (t + 2 < T) issueKV(t + 2);
    }

    l0 += __shfl_xor_sync(0xffffffffu, l0, 1);
    l0 += __shfl_xor_sync(0xffffffffu, l0, 2);
    l1 += __shfl_xor_sync(0xffffffffu, l1, 1);
    l1 += __shfl_xor_sync(0xffffffffu, l1, 2);
    float inv0 = 1.0f / l0, inv1 = 1.0f / l1;

    int lr0 = w * 16 + g, lr1 = lr0 + 8;
    __half* aob = ao + ((long)b * NTOK) * 1024 + h * 64;
    if (lr0 < qrows) {
        __half* rp = aob + (long)(q0 + lr0) * 1024 + 2 * t4;
        #pragma unroll
        for (int nt = 0; nt < 8; nt++)
            *(__half2*)(rp + nt * 8) = __floats2half2_rn(o[nt][0] * inv0, o[nt][1] * inv0);
    }
    if (lr1 < qrows) {
        __half* rp = aob + (long)(q0 + lr1) * 1024 + 2 * t4;
        #pragma unroll
        for (int nt = 0; nt < 8; nt++)
            *(__half2*)(rp + nt * 8) = __floats2half2_rn(o[nt][2] * inv1, o[nt][3] * inv1);
    }
}

// ---------------------------------------------------------------------------
// fp16 mma.sync GEMM (R9 mainloop): BM=128, BN=128, BK=32, warp tile 64x64,
// 128 threads (4 warps), 2 CTAs/SM, 3-stage cp.async + ldmatrix.
//   Residual (Res) is fp16; add in fp32 regs, store fp16.
// ---------------------------------------------------------------------------
template<bool OUTH, bool GEGLU>
__global__ void __launch_bounds__(128, 2)
hgemm(const __half* __restrict__ A, const __half* __restrict__ Bm,
      __half* __restrict__ Cv, const __half* __restrict__ Res,
      int M, int N, int K, int lda, int ldb, int ldc,
      float alpha, int ldres) {
    constexpr int MT = 4;
    constexpr int NT = 8;
    constexpr int A_ST_H = 128 * 40;
    constexpr int B_ST_H = 128 * 40;
    constexpr int ST_H   = A_ST_H + B_ST_H;

    extern __shared__ __align__(16) __half smem[];
    const uint32_t sb = smem_u32(smem);

    const int tid = threadIdx.x;
    const int wid = tid >> 5, lane = tid & 31;
    const int g = lane >> 2, t4 = lane & 3;
    const int wm = wid >> 1, wn = wid & 1;
    const int q8 = lane >> 3, r8 = lane & 7;

    const int rowBase = blockIdx.y * 128;
    const int colBase = blockIdx.x * 128;
    const int KC = (K + 31) >> 5;

    const int chA = tid & 3;
    const __half* aSrc[4];
    uint32_t aOff[4];
    bool aOk[4];
    #pragma unroll
    for (int e = 0; e < 4; e++) {
        int m = (tid >> 2) + 32 * e;
        int gr = rowBase + m;
        aOk[e] = gr < M;
        aSrc[e] = A + (long)(aOk[e] ? gr : 0) * lda + chA * 8;
        aOff[e] = (uint32_t)((m * 40 + chA * 8) * 2);
    }
    const __half* bSrc[4];
    uint32_t bOff[4];
    int bOkA[4];
    #pragma unroll
    for (int e = 0; e < 4; e++) {
        int n = (tid >> 2) + 32 * e;
        int gn = colBase + n;
        int srcRow;
        if (GEGLU) {
            int j = gn >> 4, ww = gn & 15;
            int f8 = j * 8 + (ww & 7);
            bOkA[e] = (f8 < FF_) ? 1 : 0;
            srcRow = (ww < 8) ? f8 : (FF_ + f8);
        } else {
            bOkA[e] = (gn < N) ? 1 : 0;
            srcRow = gn;
        }
        bSrc[e] = Bm + (long)(bOkA[e] ? srcRow : 0) * ldb + chA * 8;
        bOff[e] = (uint32_t)((n * 40 + chA * 8) * 2);
    }

    auto issue = [&](int c, int st) {
        const uint32_t stb = sb + (uint32_t)(st * ST_H * 2);
        int krem = K - (c << 5);
        int kb = (krem - chA * 8) * 2;
        kb = kb < 0 ? 0 : (kb > 16 ? 16 : kb);
        #pragma unroll
        for (int e = 0; e < 4; e++) {
            int bytes = aOk[e] ? kb : 0;
            cp16h(stb + aOff[e], bytes ? aSrc[e] : A, bytes);
            aSrc[e] += 32;
        }
        const uint32_t bstb = stb + (uint32_t)(A_ST_H * 2);
        #pragma unroll
        for (int e = 0; e < 4; e++) {
            int bytes = bOkA[e] ? kb : 0;
            cp16h(bstb + bOff[e], bytes ? bSrc[e] : Bm, bytes);
            bSrc[e] += 32;
        }
        CP_COMMIT();
    };

    float acc[MT][NT][4];
    #pragma unroll
    for (int i = 0; i < MT; i++)
        #pragma unroll
        for (int j = 0; j < NT; j++)
            #pragma unroll
            for (int q = 0; q < 4; q++) acc[i][j][q] = 0.0f;

    const int aIdx0 = (wm * 64 + (q8 & 1) * 8 + r8) * 40 + (q8 >> 1) * 8;
    const int bIdx0 = (wn * 64 + (q8 >> 1) * 8 + r8) * 40 + (q8 & 1) * 8;

    issue(0, 0);
    issue(1, 1);

    int st = 0;
    for (int c = 0; c < KC; c++) {
        CP_WAIT1();
        __syncthreads();
        if (c + 2 < KC) issue(c + 2, (st + 2) % 3);
        else CP_COMMIT();

        const uint32_t aStB = sb + (uint32_t)(st * ST_H * 2);
        const uint32_t bStB = aStB + (uint32_t)(A_ST_H * 2);

        #pragma unroll
        for (int ks = 0; ks < 2; ks++) {
            uint32_t af[MT][4], bf[NT][2];
            #pragma unroll
            for (int mt = 0; mt < MT; mt++)
                LDSM4(af[mt], aStB + (uint32_t)((aIdx0 + mt * 16 * 40 + ks * 16) * 2));
            #pragma unroll
            for (int p = 0; p < NT / 2; p++) {
                uint32_t d[4];
                LDSM4(d, bStB + (uint32_t)((bIdx0 + p * 16 * 40 + ks * 16) * 2));
                bf[2 * p][0] = d[0]; bf[2 * p][1] = d[1];
                bf[2 * p + 1][0] = d[2]; bf[2 * p + 1][1] = d[3];
            }
            #pragma unroll
            for (int mt = 0; mt < MT; mt++)
                #pragma unroll
                for (int nt = 0; nt < NT; nt++)
                    mma_f16(acc[mt][nt], af[mt], bf[nt]);
        }
        st++; if (st == 3) st = 0;
    }

    if (GEGLU) {
        __half* act = Cv;
        const int actBase = (colBase >> 1) + wn * 32;
        #pragma unroll
        for (int mt = 0; mt < MT; mt++) {
            int r0 = rowBase + wm * 64 + mt * 16 + g;
            #pragma unroll
            for (int p = 0; p < NT / 2; p++) {
                int col = actBase + p * 8 + t4 * 2;
                #pragma unroll
                for (int hh = 0; hh < 2; hh++) {
                    int rr = r0 + hh * 8;
                    if (rr >= M) continue;
                    float v0 = acc[mt][2 * p][hh * 2];
                    float v1 = acc[mt][2 * p][hh * 2 + 1];
                    float g0 = acc[mt][2 * p + 1][hh * 2];
                    float g1 = acc[mt][2 * p + 1][hh * 2 + 1];
                    *(__half2*)(act + (long)rr * ldc + col) =
                        __floats2half2_rn(gelu_exact(g0) * v0, gelu_exact(g1) * v1);
                }
            }
        }
        return;
    }

    #pragma unroll
    for (int mt = 0; mt < MT; mt++) {
        int r0 = rowBase + wm * 64 + mt * 16 + g;
        #pragma unroll
        for (int nt = 0; nt < NT; nt++) {
            int col = colBase + wn * 64 + nt * 8 + t4 * 2;
            if (col >= N) continue;
            #pragma unroll
            for (int hh = 0; hh < 2; hh++) {
                int rr = r0 + hh * 8;
                if (rr >= M) continue;
                float vx = alpha * acc[mt][nt][hh * 2];
                float vy = alpha * acc[mt][nt][hh * 2 + 1];
                if (!OUTH) {   // residual path (fp16 residual)
                    __half2 rv = *(const __half2*)(Res + (long)rr * ldres + col);
                    float2 r = __half22float2(rv);
                    vx += r.x; vy += r.y;
                }
                *(__half2*)(Cv + (long)rr * ldc + col) = __floats2half2_rn(vx, vy);
            }
        }
    }
}

// ---------------------------------------------------------------------------
// Weight transpose (vectorized, R13 exact)
// ---------------------------------------------------------------------------
__global__ void __launch_bounds__(256)
transpose_kernel(const float* __restrict__ src,
                 __half* __restrict__ dst,
                 int K, int N, int ldd,
                 long srcZ, long dstZ, float scale) {
    __shared__ float tile[32][129];
    const int k0 = blockIdx.y * 32, n0 = blockIdx.x * 128;
    const long zS = (long)blockIdx.z * srcZ;
    const long zD = (long)blockIdx.z * dstZ;
    const int tx = threadIdx.x, ty = threadIdx.y;   // 32 x 8
    const int tid = ty * 32 + tx;

    #pragma unroll
    for (int it = 0; it < 4; it++) {
        int k = k0 + ty + it * 8;
        int n = n0 + tx * 4;
        if (k < K && n + 3 < N) {
            float4 v = *(const float4*)(src + zS + (long)k * N + n);
            tile[ty + it * 8][tx * 4 + 0] = v.x;
            tile[ty + it * 8][tx * 4 + 1] = v.y;
            tile[ty + it * 8][tx * 4 + 2] = v.z;
            tile[ty + it * 8][tx * 4 + 3] = v.w;
        }
    }
    __syncthreads();

    const int kk = tid & 15;
    const int nr = tid >> 4;
    const int k = k0 + 2 * kk;
    if (k < K) {
        #pragma unroll
        for (int it = 0; it < 8; it++) {
            int n = n0 + nr + it * 16;
            if (n < N)
                *(__half2*)(dst + zD + (long)n * ldd + k) =
                    __floats2half2_rn(scale * tile[2 * kk][nr + it * 16],
                                      scale * tile[2 * kk + 1][nr + it * 16]);
        }
    }
}

// ---------------------------------------------------------------------------
// Small SIMT GEMM (pool)   (R9 exact)
// ---------------------------------------------------------------------------
template<typename T>
__device__ __forceinline__ float ldf(const T* p) { return (float)*p; }
template<>
__device__ __forceinline__ float ldf<__half>(const __half* p) { return __half2float(*p); }

template<int BM, int BN, int BK, int TM, int TN, bool TB, typename TAT, typename TBT>
__global__ void __launch_bounds__((BM / TM) * (BN / TN))
gemm_kernel(const TAT* __restrict__ A, const TBT* __restrict__ Bm,
            float* __restrict__ C, const float* __restrict__ Res,
            int M, int Nn, int K,
            int lda, int ldb, int ldc,
            long sAb, long sAh, long sBb, long sBh, long sCb, long sCh, int Hdiv,
            float alpha, int resRowMod, int ldres) {
    constexpr int THREADS = (BM / TM) * (BN / TN);
    constexpr int AELEM = BM * BK / THREADS;
    constexpr int BELEM = BK * BN / THREADS;

    int z = blockIdx.z;
    int zb = z / Hdiv, zh = z - zb * Hdiv;
    A  += (long)zb * sAb + (long)zh * sAh;
    Bm += (long)zb * sBb + (long)zh * sBh;
    C  += (long)zb * sCb + (long)zh * sCh;

    __shared__ __align__(16) float As[BK][BM + 4];
    __shared__ __align__(16) float Bs[BK][BN + 4];

    int tid = threadIdx.x;
    int tcol = tid % (BN / TN);
    int trow = tid / (BN / TN);
    int rowBase = blockIdx.y * BM;
    int colBase = blockIdx.x * BN;

    float acc[TM][TN] = {};

    for (int k0 = 0; k0 < K; k0 += BK) {
        #pragma unroll
        for (int e = 0; e < AELEM; e++) {
            int idx = tid + e * THREADS;
            int m = idx / BK, kk = idx % BK;
            int gr = rowBase + m, gc = k0 + kk;
            As[kk][m] = (gr < M && gc < K) ? ldf(A + (long)gr * lda + gc) : 0.0f;
        }
        #pragma unroll
        for (int e = 0; e < BELEM; e++) {
            int idx = tid + e * THREADS;
            int kk, n;
            if (!TB) { kk = idx / BN; n = idx % BN; }
            else     { n = idx / BK;  kk = idx % BK; }
            int gc = colBase + n, gk = k0 + kk;
            float v = 0.0f;
            if (gc < Nn && gk < K)
                v = TB ? ldf(Bm + (long)gc * ldb + gk) : ldf(Bm + (long)gk * ldb + gc);
            Bs[kk][n] = v;
        }
        __syncthreads();

        #pragma unroll
        for (int kk = 0; kk < BK; kk++) {
            float a[TM], bb[TN];
            #pragma unroll
            for (int i = 0; i < TM; i++) a[i] = As[kk][trow * TM + i];
            #pragma unroll
            for (int j = 0; j < TN; j++) bb[j] = Bs[kk][tcol * TN + j];
            #pragma unroll
            for (int i = 0; i < TM; i++)
                #pragma unroll
                for (int j = 0; j < TN; j++)
                    acc[i][j] += a[i] * bb[j];
        }
        __syncthreads();
    }

    #pragma unroll
    for (int i = 0; i < TM; i++) {
        int r = rowBase + trow * TM + i;
        if (r >= M) continue;
        #pragma unroll
        for (int j = 0; j < TN; j++) {
            int c = colBase + tcol * TN + j;
            if (c >= Nn) continue;
            float v = alpha * acc[i][j];
            if (Res) {
                int rr = resRowMod ? (r % resRowMod) : r;
                v += Res[(long)rr * ldres + c];
            }
            C[(long)r * ldc + c] = v;
        }
    }
}

// ---------------------------------------------------------------------------
// Elementwise / reduction kernels
// ---------------------------------------------------------------------------
__device__ __forceinline__ float blk_reduce(float v, bool ismax) {
    __shared__ float red[9];
    #pragma unroll
    for (int o = 16; o; o >>= 1) {
        float u = __shfl_xor_sync(0xffffffffu, v, o);
        v = ismax ? fmaxf(v, u) : (v + u);
    }
    if ((threadIdx.x & 31) == 0) red[threadIdx.x >> 5] = v;
    __syncthreads();
    if (threadIdx.x == 0) {
        float r = red[0];
        int nw = blockDim.x >> 5;
        for (int w = 1; w < nw; w++) r = ismax ? fmaxf(r, red[w]) : (r + red[w]);
        red[8] = r;
    }
    __syncthreads();
    float r = red[8];
    __syncthreads();
    return r;
}

__device__ __forceinline__ int token_type(int j) {
    return j < 512 ? 0 : (j < 1024 ? 1 : 2);
}

// Fused concat + layer-0 LN: writes fp16 residual stream + gamma-scaled LN out.
__global__ void __launch_bounds__(256)
concat_ln_kernel(const float4* __restrict__ m0,
                 const float4* __restrict__ m1,
                 const float4* __restrict__ fus,
                 const float* __restrict__ gamma,
                 __half* __restrict__ tok,
                 __half* __restrict__ out) {
    const int lane = threadIdx.x & 31;
    const long row = (long)blockIdx.x * 8 + (threadIdx.x >> 5);
    const int t = (int)(row % NTOK);
    const int b = (int)(row / NTOK);

    const float4* src;
    if (t < 512)       src = m0 + ((long)b * 512 + t) * (D_ / 4);
    else if (t < 1024) src = m1 + ((long)b * 512 + (t - 512)) * (D_ / 4);
    else               src = fus + (long)(t - 1024) * (D_ / 4);

    float4 v[8];
    float s = 0.f, s2 = 0.f;
    #pragma unroll
    for (int e = 0; e < 8; e++) {
        v[e] = src[lane + e * 32];
        s  += v[e].x + v[e].y + v[e].z + v[e].w;
        s2 += v[e].x * v[e].x + v[e].y * v[e].y
            + v[e].z * v[e].z + v[e].w * v[e].w;
    }
    uint2* tr = (uint2*)(tok + row * D_);
    #pragma unroll
    for (int e = 0; e < 8; e++) {
        uint2 pk;
        pk.x = packh2(v[e].x, v[e].y);
        pk.y = packh2(v[e].z, v[e].w);
        tr[lane + e * 32] = pk;
    }

    #pragma unroll
    for (int o = 16; o; o >>= 1) {
        s  += __shfl_xor_sync(0xffffffffu, s,  o);
        s2 += __shfl_xor_sync(0xffffffffu, s2, o);
    }
    float mu  = s * (1.0f / D_);
    float var = s2 * (1.0f / D_) - mu * mu;
    float inv = rsqrtf(var + 1e-5f);

    uint2* o2 = (uint2*)(out + row * D_);
    const float4* gm = (const float4*)gamma;
    #pragma unroll
    for (int e = 0; e < 8; e++) {
        float4 g = gm[lane + e * 32];
        uint2 pk;
        pk.x = packh2((v[e].x - mu) * inv * g.x, (v[e].y - mu) * inv * g.y);
        pk.y = packh2((v[e].z - mu) * inv * g.z, (v[e].w - mu) * inv * g.w);
        o2[lane + e * 32] = pk;
    }
}

// Warp-per-row LayerNorm over fp16 residual stream.
__global__ void __launch_bounds__(256)
ln_kernel(const __half* __restrict__ x,
          const float* __restrict__ gamma,
          __half* __restrict__ out) {
    const int lane = threadIdx.x & 31;
    const long row = (long)blockIdx.x * 8 + (threadIdx.x >> 5);
    const uint4* xr = (const uint4*)(x + row * D_);   // 8 halves per uint4

    float f[32];
    float s = 0.f, s2 = 0.f;
    #pragma unroll
    for (int e = 0; e < 4; e++) {
        uint4 v = xr[lane + e * 32];
        const __half2* hp = (const __half2*)&v;
        #pragma unroll
        for (int q = 0; q < 4; q++) {
            float2 t = __half22float2(hp[q]);
            f[e * 8 + 2 * q]     = t.x;
            f[e * 8 + 2 * q + 1] = t.y;
            s  += t.x + t.y;
            s2 += t.x * t.x + t.y * t.y;
        }
    }
    #pragma unroll
    for (int o = 16; o; o >>= 1) {
        s  += __shfl_xor_sync(0xffffffffu, s,  o);
        s2 += __shfl_xor_sync(0xffffffffu, s2, o);
    }
    float mu  = s * (1.0f / D_);
    float var = s2 * (1.0f / D_) - mu * mu;
    float inv = rsqrtf(var + 1e-5f);

    uint4* o4 = (uint4*)(out + row * D_);
    const float4* gm = (const float4*)gamma;
    #pragma unroll
    for (int e = 0; e < 4; e++) {
        float4 g0 = gm[(lane + e * 32) * 2];
        float4 g1 = gm[(lane + e * 32) * 2 + 1];
        uint4 pk;
        pk.x = packh2((f[e*8+0] - mu) * inv * g0.x, (f[e*8+1] - mu) * inv * g0.y);
        pk.y = packh2((f[e*8+2] - mu) * inv * g0.z, (f[e*8+3] - mu) * inv * g0.w);
        pk.z = packh2((f[e*8+4] - mu) * inv * g1.x, (f[e*8+5] - mu) * inv * g1.y);
        pk.w = packh2((f[e*8+6] - mu) * inv * g1.z, (f[e*8+7] - mu) * inv * g1.w);
        o4[lane + e * 32] = pk;
    }
}

__global__ void softmax_pool_kernel(float* __restrict__ sim) {
    long row = blockIdx.x;
    float* p = sim + row * NTOK;
    int r = (int)(row % 4);
    int tid = threadIdx.x;

    float vals[5];
    float mx = -3.4e38f;
    #pragma unroll
    for (int it = 0; it < 5; it++) {
        int j = tid + it * 256;
        float v = -3.4e38f;
        if (j < NTOK) {
            bool ok = (r == 3) || (token_type(j) == r);
            v = ok ? p[j] : -3.4e38f;
        }
        vals[it] = v;
        mx = fmaxf(mx, v);
    }
    mx = blk_reduce(mx, true);

    float e[5];
    float s = 0.0f;
    #pragma unroll
    for (int it = 0; it < 5; it++) {
        float ex = __expf(vals[it] - mx);
        e[it] = ex;
        s += ex;
    }
    s = blk_reduce(s, false);
    float inv = 1.0f / s;
    #pragma unroll
    for (int it = 0; it < 5; it++) {
        int j = tid + it * 256;
        if (j < NTOK) p[j] = e[it] * inv;
    }
}

// ---------------------------------------------------------------------------
// Host side
// ---------------------------------------------------------------------------
static constexpr int SM_H128  = 3 * (128 * 40 + 128 * 40) * 2;   // 61440
static constexpr int SM_FLASH = (64 * 72 + 4 * 128 * 72) * 2;    // 82944

static inline void hg(const __half* A, const __half* Bt, __half* C, const __half* Res,
                      int M, int Nn, int K, int lda, int ldbT, int ldc, float alpha,
                      bool outh, int ldres = 0) {
    dim3 grid((Nn + 127) / 128, (M + 127) / 128, 1);
    if (outh)
        hgemm<true, false><<<grid, 128, SM_H128>>>(
            A, Bt, C, Res, M, Nn, K, lda, ldbT, ldc, alpha, ldres);
    else
        hgemm<false, false><<<grid, 128, SM_H128>>>(
            A, Bt, C, Res, M, Nn, K, lda, ldbT, ldc, alpha, ldres);
}

extern "C" void kernel_launch(void* const* d_in, const int* in_sizes, int n_in,
                              void* d_out, int out_size) {
    const float* m0        = (const float*)d_in[0];
    const float* m1        = (const float*)d_in[1];
    const float* fusion    = (const float*)d_in[2];
    const float* ret_tok   = (const float*)d_in[3];
    const float* ln_gamma  = (const float*)d_in[4];
    const float* wq        = (const float*)d_in[5];
    const float* wkv       = (const float*)d_in[6];
    const float* wo        = (const float*)d_in[7];
    const float* ff_w1     = (const float*)d_in[8];
    const float* ff_w2     = (const float*)d_in[9];
    const float* pool_wq   = (const float*)d_in[10];
    const float* pool_wkv  = (const float*)d_in[11];
    const float* pool_wo   = (const float*)d_in[12];
    const float* final_g   = (const float*)d_in[13];
    float* out = (float*)d_out;

    cudaFuncSetAttribute(hgemm<true, false>,
                         cudaFuncAttributeMaxDynamicSharedMemorySize, SM_H128);
    cudaFuncSetAttribute(hgemm<false, false>,
                         cudaFuncAttributeMaxDynamicSharedMemorySize, SM_H128);
    cudaFuncSetAttribute(hgemm<true, true>,
                         cudaFuncAttributeMaxDynamicSharedMemorySize, SM_H128);
    cudaFuncSetAttribute(flash_kernel,
                         cudaFuncAttributeMaxDynamicSharedMemorySize, SM_FLASH);

    float *simbuf, *poolq, *poolao;
    __half *tok, *hbuf, *qkvbuf, *kvbuf, *aobuf, *actbuf;
    __half *wqkvT, *woT, *ff1T, *ff2T, *pkvT;
    cudaGetSymbolAddress((void**)&simbuf, g_sim);
    cudaGetSymbolAddress((void**)&poolq,  g_poolq);
    cudaGetSymbolAddress((void**)&poolao, g_poolao);
    cudaGetSymbolAddress((void**)&tok,    h_tok);
    cudaGetSymbolAddress((void**)&hbuf,   h_h);
    cudaGetSymbolAddress((void**)&qkvbuf, h_qkv);
    cudaGetSymbolAddress((void**)&kvbuf,  h_kv);
    cudaGetSymbolAddress((void**)&aobuf,  h_ao);
    cudaGetSymbolAddress((void**)&actbuf, h_act);
    cudaGetSymbolAddress((void**)&wqkvT,  h_wqkvT);
    cudaGetSymbolAddress((void**)&woT,    h_woT);
    cudaGetSymbolAddress((void**)&ff1T,   h_ff1T);
    cudaGetSymbolAddress((void**)&ff2T,   h_ff2T);
    cudaGetSymbolAddress((void**)&pkvT,   h_pkvT);

    const float scale = 0.125f;

    // --- weight pre-transposes (fp32 -> fp16; q-scale folded into wq) ---
    {
        dim3 thr(32, 8);
        const long zq = (long)3 * D_ * D_;
        transpose_kernel<<<dim3(8, 32, 4),   thr>>>(wq,  wqkvT, 1024, 1024, 1024,
                                                    (long)D_ * D_, zq, scale);
        transpose_kernel<<<dim3(16, 32, 4),  thr>>>(wkv, wqkvT + (long)D_ * D_,
                                                    1024, 2048, 1024,
                                                    (long)2 * D_ * D_, zq, 1.0f);
        transpose_kernel<<<dim3(8, 32, 4),   thr>>>(wo, woT, 1024, 1024, 1024,
                                                    (long)D_ * D_, (long)D_ * D_, 1.0f);
        transpose_kernel<<<dim3(43, 32, 4),  thr>>>(ff_w1, ff1T, 1024, 5460, 1024,
                                                    (long)D_ * FF2_, (long)FF2_ * D_, 1.0f);
        transpose_kernel<<<dim3(8, 86, 4),   thr>>>(ff_w2, ff2T, 2730, 1024, ACTLD,
                                                    (long)FF_ * D_, (long)D_ * ACTLD, 1.0f);
        transpose_kernel<<<dim3(16, 32, 1),  thr>>>(pool_wkv, pkvT, 1024, 2048, 1024,
                                                    0, 0, 1.0f);
    }

    // concat fused with layer-0 attention LN (fp16 residual stream)
    concat_ln_kernel<<<ROWS / 8, 256>>>(
        (const float4*)m0, (const float4*)m1, (const float4*)fusion,
        ln_gamma, tok, hbuf);

    const long sKVB = (long)NTOK * 2 * D_;

    for (int l = 0; l < L_; l++) {
        const __half* wqkvT_l = wqkvT + (long)l * 3 * D_ * D_;
        const __half* woT_l   = woT   + (long)l * D_ * D_;
        const __half* w1T_l   = ff1T  + (long)l * FF2_ * D_;
        const __half* w2T_l   = ff2T  + (long)l * D_ * ACTLD;
        const float*  g_l     = ln_gamma + (long)l * D_;

        // attention block (layer 0's LN produced by concat_ln)
        if (l > 0) ln_kernel<<<ROWS / 8, 256>>>(tok, g_l, hbuf);
        hg(hbuf, wqkvT_l, qkvbuf, nullptr, ROWS, 3 * D_, D_, D_, D_, 3 * D_, 1.0f, true);
        flash_kernel<<<dim3(17, 1, B_ * H_), 128, SM_FLASH>>>(qkvbuf, aobuf);
        hg(aobuf, woT_l, tok, tok, ROWS, D_, D_, D_, D_, D_, 1.0f, false, D_);

        // feed-forward block: FF1 + GEGLU fused, FF2 (+fp16 residual)
        ln_kernel<<<ROWS / 8, 256>>>(tok, g_l, hbuf);
        hgemm<true, true><<<dim3(2 * ACTLD / 128, (ROWS + 127) / 128, 1),
                            128, SM_H128>>>(
            hbuf, w1T_l, actbuf, nullptr,
            ROWS, 2 * ACTLD, D_, D_, D_, ACTLD, 1.0f, 0);
        hg(actbuf, w2T_l, tok, tok, ROWS, D_, FF_, ACTLD, ACTLD, D_, 1.0f, false, D_);
    }

    // --- final LN + attention pooling ---
    ln_kernel<<<ROWS / 8, 256>>>(tok, final_g, hbuf);

    gemm_kernel<64, 64, 16, 4, 4, false, float, float>
        <<<dim3(16, 1, 1), 256>>>(
        ret_tok, pool_wq, poolq, nullptr, 4, D_, D_, D_, D_, D_,
        0, 0, 0, 0, 0, 0, 1, scale, 0, 0);

    hg(hbuf, pkvT, kvbuf, nullptr, ROWS, 2 * D_, D_, D_, D_, 2 * D_, 1.0f, true);

    gemm_kernel<64, 64, 16, 4, 4, true, float, __half>
        <<<dim3((NTOK + 63) / 64, 1, B_ * H_), 256>>>(
        poolq, kvbuf, simbuf, nullptr,
        4, NTOK, DH_, D_, 2 * D_, NTOK,
        0L, DH_, sKVB, DH_,
        (long)H_ * 4 * NTOK, (long)4 * NTOK, H_,
        1.0f, 0, 0);

    softmax_pool_kernel<<<B_ * H_ * 4, 256>>>(simbuf);

    gemm_kernel<64, 64, 16, 4, 4, false, float, __half>
        <<<dim3(1, 1, B_ * H_), 256>>>(
        simbuf, kvbuf + D_, poolao, nullptr,
        4, DH_, NTOK, NTOK, 2 * D_, D_,
        (long)H_ * 4 * NTOK, (long)4 * NTOK,
        sKVB, DH_,
        (long)4 * D_, DH_, H_,
        1.0f, 0, 0);

    gemm_kernel<64, 64, 16, 4, 4, false, float, float>
        <<<dim3(16, 1, 1), 256>>>(
        poolao, pool_wo, out, ret_tok, B_ * 4, D_, D_, D_, D_, D_,
        0, 0, 0, 0, 0, 0, 1, 1.0f, /*resRowMod=*/4, /*ldres=*/D_);
}

// round 17
// speedup vs baseline: 1.2236x; 1.0165x over previous
#include <cuda_runtime.h>
#include <cuda_fp16.h>
#include <math.h>
#include <stdint.h>

// ---------------------------------------------------------------------------
// Problem constants
// ---------------------------------------------------------------------------
static constexpr int B_    = 4;
static constexpr int NTOK  = 1040;   // 512 + 512 + 16
static constexpr int D_    = 1024;
static constexpr int H_    = 16;
static constexpr int DH_   = 64;
static constexpr int L_    = 4;
static constexpr int FF_   = 2730;
static constexpr int FF2_  = 5460;
static constexpr int ROWS  = B_ * NTOK;   // 4160
static constexpr int ACTLD = 2752;        // act cols (43 blocks x 64), padded

// ---------------------------------------------------------------------------
// Device scratch
// ---------------------------------------------------------------------------
__device__ float  g_poolq [4 * D_];
__device__ float  g_poolao[B_ * 4 * D_];
__device__ __half h_tok   [ROWS * D_];            // fp16 residual stream
__device__ __half h_h     [ROWS * D_];
__device__ __half h_qkv   [ROWS * 3 * D_];
__device__ __half h_kv    [ROWS * 2 * D_];        // pool kv
__device__ __half h_ao    [ROWS * D_];
__device__ __half h_act   [(long long)ROWS * ACTLD];
// transposed fp16 weights
__device__ __half h_wqkvT[(long long)L_ * 3 * D_ * D_];
__device__ __half h_woT  [L_ * D_ * D_];
__device__ __half h_ff1T [(long long)L_ * FF2_ * D_];
__device__ __half h_ff2T [(long long)L_ * D_ * ACTLD];   // pad rows stay zero
__device__ __half h_pkvT [2 * D_ * D_];

// ---------------------------------------------------------------------------
// Helpers
// ---------------------------------------------------------------------------
__device__ __forceinline__ uint32_t smem_u32(const void* p) {
    uint32_t a;
    asm("{ .reg .u64 t; cvta.to.shared.u64 t, %1; cvt.u32.u64 %0, t; }"
        : "=r"(a) : "l"(p));
    return a;
}

__device__ __forceinline__ void mma_f16(float* c, const uint32_t* a, const uint32_t* b) {
    asm volatile(
        "mma.sync.aligned.m16n8k16.row.col.f32.f16.f16.f32 "
        "{%0,%1,%2,%3}, {%4,%5,%6,%7}, {%8,%9}, {%0,%1,%2,%3};"
        : "+f"(c[0]), "+f"(c[1]), "+f"(c[2]), "+f"(c[3])
        : "r"(a[0]), "r"(a[1]), "r"(a[2]), "r"(a[3]), "r"(b[0]), "r"(b[1]));
}

#define LDSM4(d, addr)                                                         \
    asm volatile("ldmatrix.sync.aligned.m8n8.x4.shared.b16 {%0,%1,%2,%3}, [%4];" \
        : "=r"((d)[0]), "=r"((d)[1]), "=r"((d)[2]), "=r"((d)[3]) : "r"(addr))
#define LDSM4T(d, addr)                                                        \
    asm volatile("ldmatrix.sync.aligned.m8n8.x4.trans.shared.b16 {%0,%1,%2,%3}, [%4];" \
        : "=r"((d)[0]), "=r"((d)[1]), "=r"((d)[2]), "=r"((d)[3]) : "r"(addr))

__device__ __forceinline__ void cp16h(uint32_t dst, const __half* src, int bytes) {
    asm volatile("cp.async.cg.shared.global [%0], [%1], 16, %2;"
                 :: "r"(dst), "l"(src), "r"(bytes));
}
#define CP_COMMIT() asm volatile("cp.async.commit_group;" ::: "memory")
#define CP_WAIT1()  asm volatile("cp.async.wait_group 1;" ::: "memory")
#define CP_WAIT0()  asm volatile("cp.async.wait_group 0;" ::: "memory")

__device__ __forceinline__ uint32_t packh2(float x, float y) {
    __half2 h = __floats2half2_rn(x, y);
    return *(uint32_t*)&h;
}
__device__ __forceinline__ float gelu_exact(float g) {
    return 0.5f * g * (1.0f + erff(g * 0.70710678118654752f));
}

// ---------------------------------------------------------------------------
// Flash attention (block-masked), plain-sum softmax.  (R15 exact)
// ---------------------------------------------------------------------------
__global__ void __launch_bounds__(128, 2)
flash_kernel(const __half* __restrict__ qkv, __half* __restrict__ ao) {
    constexpr int LDS_ = 72;
    constexpr int QOFF = 0;
    constexpr int KOFF = 64 * LDS_;
    constexpr int VOFF = KOFF + 2 * 128 * LDS_;
    extern __shared__ __half sm[];
    const uint32_t sb = smem_u32(sm);

    const int tid = threadIdx.x;
    const int w = tid >> 5, lane = tid & 31;
    const int g = lane >> 2, t4 = lane & 3;
    const int q8 = lane >> 3, r8 = lane & 7;

    const int bh = blockIdx.z;
    const int b = bh >> 4, h = bh & 15;
    const int qb = blockIdx.x;
    int q0, c0, clen, qrows;
    if (qb < 16) { q0 = qb * 64; c0 = (qb < 8) ? 0 : 512; clen = 512; qrows = 64; }
    else         { q0 = 1024;  c0 = 0;  clen = NTOK;  qrows = 16; }

    const __half* qb_g = qkv + ((long)b * NTOK) * 3072 + h * 64;
    const __half* kb_g = qkv + ((long)b * NTOK) * 3072 + 1024 + h * 64;
    const __half* vb_g = qkv + ((long)b * NTOK) * 3072 + 2048 + h * 64;

    {
        int row = tid >> 1;
        int gr = q0 + row;
        int bytes = (row < qrows) ? 16 : 0;
        const __half* src = qb_g + (long)(bytes ? gr : 0) * 3072 + (tid & 1) * 32;
        uint32_t dst = sb + (QOFF + row * LDS_ + (tid & 1) * 32) * 2;
        #pragma unroll
        for (int e = 0; e < 4; e++)
            cp16h(dst + e * 16, src + e * 8, bytes);
    }

    const int T = (clen + 127) >> 7;
    int issued = 0;
    auto issueKV = [&](int t) {
        int buf = t & 1;
        int j = c0 + t * 128 + tid;
        int bytes = (j < c0 + clen) ? 16 : 0;
        const __half* ks = kb_g + (long)(bytes ? j : 0) * 3072;
        const __half* vs = vb_g + (long)(bytes ? j : 0) * 3072;
        uint32_t kd = sb + (KOFF + buf * 128 * LDS_ + tid * LDS_) * 2;
        uint32_t vd = sb + (VOFF + buf * 128 * LDS_ + tid * LDS_) * 2;
        #pragma unroll
        for (int ch = 0; ch < 8; ch++) cp16h(kd + ch * 16, ks + ch * 8, bytes);
        #pragma unroll
        for (int ch = 0; ch < 8; ch++) cp16h(vd + ch * 16, vs + ch * 8, bytes);
        CP_COMMIT();
        issued++;
    };
    issueKV(0);
    if (T > 1) issueKV(1);

    float l0 = 0.f, l1 = 0.f;
    float o[8][4];
    #pragma unroll
    for (int i = 0; i < 8; i++)
        #pragma unroll
        for (int q = 0; q < 4; q++) o[i][q] = 0.f;

    const int aIdx = (w * 16 + (q8 & 1) * 8 + r8) * LDS_ + (q8 >> 1) * 8;
    const int kIdx = ((q8 >> 1) * 8 + r8) * LDS_ + (q8 & 1) * 8;
    const int vIdx = ((q8 & 1) * 8 + r8) * LDS_ + (q8 >> 1) * 8;

    for (int t = 0; t < T; t++) {
        if (issued - (t + 1) >= 1) { CP_WAIT1(); } else { CP_WAIT0(); }
        __syncthreads();

        const uint32_t kb_s = sb + (KOFF + (t & 1) * 128 * LDS_) * 2;
        const uint32_t vb_s = sb + (VOFF + (t & 1) * 128 * LDS_) * 2;
        const uint32_t qs = sb + QOFF * 2;

        float s[16][4];
        #pragma unroll
        for (int i = 0; i < 16; i++)
            #pragma unroll
            for (int q = 0; q < 4; q++) s[i][q] = 0.f;

        #pragma unroll
        for (int ks = 0; ks < 4; ks++) {
            uint32_t af[4];
            LDSM4(af, qs + (aIdx + ks * 16) * 2);
            #pragma unroll
            for (int p = 0; p < 8; p++) {
                uint32_t d[4];
                LDSM4(d, kb_s + (kIdx + p * 16 * LDS_ + ks * 16) * 2);
                mma_f16(s[2 * p], af, d);
                mma_f16(s[2 * p + 1], af, d + 2);
            }
        }

        int lim = clen - t * 128;
        if (lim < 128) {
            #pragma unroll
            for (int nt = 0; nt < 16; nt++) {
                int cc = nt * 8 + 2 * t4;
                if (cc >= lim)     { s[nt][0] = -1e30f; s[nt][2] = -1e30f; }
                if (cc + 1 >= lim) { s[nt][1] = -1e30f; s[nt][3] = -1e30f; }
            }
        }

        uint32_t pf[16][2];
        #pragma unroll
        for (int nt = 0; nt < 16; nt++) {
            float p0 = __expf(s[nt][0]);
            float p1 = __expf(s[nt][1]);
            float p2 = __expf(s[nt][2]);
            float p3 = __expf(s[nt][3]);
            l0 += p0 + p1; l1 += p2 + p3;
            pf[nt][0] = packh2(p0, p1);
            pf[nt][1] = packh2(p2, p3);
        }

        #pragma unroll
        for (int kv = 0; kv < 8; kv++) {
            uint32_t a[4] = { pf[2 * kv][0], pf[2 * kv][1],
                              pf[2 * kv + 1][0], pf[2 * kv + 1][1] };
            #pragma unroll
            for (int p = 0; p < 4; p++) {
                uint32_t d[4];
                LDSM4T(d, vb_s + (vIdx + kv * 16 * LDS_ + p * 16) * 2);
                mma_f16(o[2 * p], a, d);
                mma_f16(o[2 * p + 1], a, d + 2);
            }
        }

        __syncthreads();
        if (t + 2 < T) issueKV(t + 2);
    }

    l0 += __shfl_xor_sync(0xffffffffu, l0, 1);
    l0 += __shfl_xor_sync(0xffffffffu, l0, 2);
    l1 += __shfl_xor_sync(0xffffffffu, l1, 1);
    l1 += __shfl_xor_sync(0xffffffffu, l1, 2);
    float inv0 = 1.0f / l0, inv1 = 1.0f / l1;

    int lr0 = w * 16 + g, lr1 = lr0 + 8;
    __half* aob = ao + ((long)b * NTOK) * 1024 + h * 64;
    if (lr0 < qrows) {
        __half* rp = aob + (long)(q0 + lr0) * 1024 + 2 * t4;
        #pragma unroll
        for (int nt = 0; nt < 8; nt++)
            *(__half2*)(rp + nt * 8) = __floats2half2_rn(o[nt][0] * inv0, o[nt][1] * inv0);
    }
    if (lr1 < qrows) {
        __half* rp = aob + (long)(q0 + lr1) * 1024 + 2 * t4;
        #pragma unroll
        for (int nt = 0; nt < 8; nt++)
            *(__half2*)(rp + nt * 8) = __floats2half2_rn(o[nt][2] * inv1, o[nt][3] * inv1);
    }
}

// ---------------------------------------------------------------------------
// fp16 mma.sync GEMM (R16 exact): BM=128, BN=128, BK=32, warp tile 64x64,
// 128 threads, 2 CTAs/SM, 3-stage cp.async + ldmatrix. fp16 residual.
// ---------------------------------------------------------------------------
template<bool OUTH, bool GEGLU>
__global__ void __launch_bounds__(128, 2)
hgemm(const __half* __restrict__ A, const __half* __restrict__ Bm,
      __half* __restrict__ Cv, const __half* __restrict__ Res,
      int M, int N, int K, int lda, int ldb, int ldc,
      float alpha, int ldres) {
    constexpr int MT = 4;
    constexpr int NT = 8;
    constexpr int A_ST_H = 128 * 40;
    constexpr int B_ST_H = 128 * 40;
    constexpr int ST_H   = A_ST_H + B_ST_H;

    extern __shared__ __align__(16) __half smem[];
    const uint32_t sb = smem_u32(smem);

    const int tid = threadIdx.x;
    const int wid = tid >> 5, lane = tid & 31;
    const int g = lane >> 2, t4 = lane & 3;
    const int wm = wid >> 1, wn = wid & 1;
    const int q8 = lane >> 3, r8 = lane & 7;

    const int rowBase = blockIdx.y * 128;
    const int colBase = blockIdx.x * 128;
    const int KC = (K + 31) >> 5;

    const int chA = tid & 3;
    const __half* aSrc[4];
    uint32_t aOff[4];
    bool aOk[4];
    #pragma unroll
    for (int e = 0; e < 4; e++) {
        int m = (tid >> 2) + 32 * e;
        int gr = rowBase + m;
        aOk[e] = gr < M;
        aSrc[e] = A + (long)(aOk[e] ? gr : 0) * lda + chA * 8;
        aOff[e] = (uint32_t)((m * 40 + chA * 8) * 2);
    }
    const __half* bSrc[4];
    uint32_t bOff[4];
    int bOkA[4];
    #pragma unroll
    for (int e = 0; e < 4; e++) {
        int n = (tid >> 2) + 32 * e;
        int gn = colBase + n;
        int srcRow;
        if (GEGLU) {
            int j = gn >> 4, ww = gn & 15;
            int f8 = j * 8 + (ww & 7);
            bOkA[e] = (f8 < FF_) ? 1 : 0;
            srcRow = (ww < 8) ? f8 : (FF_ + f8);
        } else {
            bOkA[e] = (gn < N) ? 1 : 0;
            srcRow = gn;
        }
        bSrc[e] = Bm + (long)(bOkA[e] ? srcRow : 0) * ldb + chA * 8;
        bOff[e] = (uint32_t)((n * 40 + chA * 8) * 2);
    }

    auto issue = [&](int c, int st) {
        const uint32_t stb = sb + (uint32_t)(st * ST_H * 2);
        int krem = K - (c << 5);
        int kb = (krem - chA * 8) * 2;
        kb = kb < 0 ? 0 : (kb > 16 ? 16 : kb);
        #pragma unroll
        for (int e = 0; e < 4; e++) {
            int bytes = aOk[e] ? kb : 0;
            cp16h(stb + aOff[e], bytes ? aSrc[e] : A, bytes);
            aSrc[e] += 32;
        }
        const uint32_t bstb = stb + (uint32_t)(A_ST_H * 2);
        #pragma unroll
        for (int e = 0; e < 4; e++) {
            int bytes = bOkA[e] ? kb : 0;
            cp16h(bstb + bOff[e], bytes ? bSrc[e] : Bm, bytes);
            bSrc[e] += 32;
        }
        CP_COMMIT();
    };

    float acc[MT][NT][4];
    #pragma unroll
    for (int i = 0; i < MT; i++)
        #pragma unroll
        for (int j = 0; j < NT; j++)
            #pragma unroll
            for (int q = 0; q < 4; q++) acc[i][j][q] = 0.0f;

    const int aIdx0 = (wm * 64 + (q8 & 1) * 8 + r8) * 40 + (q8 >> 1) * 8;
    const int bIdx0 = (wn * 64 + (q8 >> 1) * 8 + r8) * 40 + (q8 & 1) * 8;

    issue(0, 0);
    issue(1, 1);

    int st = 0;
    for (int c = 0; c < KC; c++) {
        CP_WAIT1();
        __syncthreads();
        if (c + 2 < KC) issue(c + 2, (st + 2) % 3);
        else CP_COMMIT();

        const uint32_t aStB = sb + (uint32_t)(st * ST_H * 2);
        const uint32_t bStB = aStB + (uint32_t)(A_ST_H * 2);

        #pragma unroll
        for (int ks = 0; ks < 2; ks++) {
            uint32_t af[MT][4], bf[NT][2];
            #pragma unroll
            for (int mt = 0; mt < MT; mt++)
                LDSM4(af[mt], aStB + (uint32_t)((aIdx0 + mt * 16 * 40 + ks * 16) * 2));
            #pragma unroll
            for (int p = 0; p < NT / 2; p++) {
                uint32_t d[4];
                LDSM4(d, bStB + (uint32_t)((bIdx0 + p * 16 * 40 + ks * 16) * 2));
                bf[2 * p][0] = d[0]; bf[2 * p][1] = d[1];
                bf[2 * p + 1][0] = d[2]; bf[2 * p + 1][1] = d[3];
            }
            #pragma unroll
            for (int mt = 0; mt < MT; mt++)
                #pragma unroll
                for (int nt = 0; nt < NT; nt++)
                    mma_f16(acc[mt][nt], af[mt], bf[nt]);
        }
        st++; if (st == 3) st = 0;
    }

    if (GEGLU) {
        __half* act = Cv;
        const int actBase = (colBase >> 1) + wn * 32;
        #pragma unroll
        for (int mt = 0; mt < MT; mt++) {
            int r0 = rowBase + wm * 64 + mt * 16 + g;
            #pragma unroll
            for (int p = 0; p < NT / 2; p++) {
                int col = actBase + p * 8 + t4 * 2;
                #pragma unroll
                for (int hh = 0; hh < 2; hh++) {
                    int rr = r0 + hh * 8;
                    if (rr >= M) continue;
                    float v0 = acc[mt][2 * p][hh * 2];
                    float v1 = acc[mt][2 * p][hh * 2 + 1];
                    float g0 = acc[mt][2 * p + 1][hh * 2];
                    float g1 = acc[mt][2 * p + 1][hh * 2 + 1];
                    *(__half2*)(act + (long)rr * ldc + col) =
                        __floats2half2_rn(gelu_exact(g0) * v0, gelu_exact(g1) * v1);
                }
            }
        }
        return;
    }

    #pragma unroll
    for (int mt = 0; mt < MT; mt++) {
        int r0 = rowBase + wm * 64 + mt * 16 + g;
        #pragma unroll
        for (int nt = 0; nt < NT; nt++) {
            int col = colBase + wn * 64 + nt * 8 + t4 * 2;
            if (col >= N) continue;
            #pragma unroll
            for (int hh = 0; hh < 2; hh++) {
                int rr = r0 + hh * 8;
                if (rr >= M) continue;
                float vx = alpha * acc[mt][nt][hh * 2];
                float vy = alpha * acc[mt][nt][hh * 2 + 1];
                if (!OUTH) {
                    __half2 rv = *(const __half2*)(Res + (long)rr * ldres + col);
                    float2 r = __half22float2(rv);
                    vx += r.x; vy += r.y;
                }
                *(__half2*)(Cv + (long)rr * ldc + col) = __floats2half2_rn(vx, vy);
            }
        }
    }
}

// ---------------------------------------------------------------------------
// Weight transpose (vectorized, R13 exact)
// ---------------------------------------------------------------------------
__global__ void __launch_bounds__(256)
transpose_kernel(const float* __restrict__ src,
                 __half* __restrict__ dst,
                 int K, int N, int ldd,
                 long srcZ, long dstZ, float scale) {
    __shared__ float tile[32][129];
    const int k0 = blockIdx.y * 32, n0 = blockIdx.x * 128;
    const long zS = (long)blockIdx.z * srcZ;
    const long zD = (long)blockIdx.z * dstZ;
    const int tx = threadIdx.x, ty = threadIdx.y;   // 32 x 8
    const int tid = ty * 32 + tx;

    #pragma unroll
    for (int it = 0; it < 4; it++) {
        int k = k0 + ty + it * 8;
        int n = n0 + tx * 4;
        if (k < K && n + 3 < N) {
            float4 v = *(const float4*)(src + zS + (long)k * N + n);
            tile[ty + it * 8][tx * 4 + 0] = v.x;
            tile[ty + it * 8][tx * 4 + 1] = v.y;
            tile[ty + it * 8][tx * 4 + 2] = v.z;
            tile[ty + it * 8][tx * 4 + 3] = v.w;
        }
    }
    __syncthreads();

    const int kk = tid & 15;
    const int nr = tid >> 4;
    const int k = k0 + 2 * kk;
    if (k < K) {
        #pragma unroll
        for (int it = 0; it < 8; it++) {
            int n = n0 + nr + it * 16;
            if (n < N)
                *(__half2*)(dst + zD + (long)n * ldd + k) =
                    __floats2half2_rn(scale * tile[2 * kk][nr + it * 16],
                                      scale * tile[2 * kk + 1][nr + it * 16]);
        }
    }
}

// ---------------------------------------------------------------------------
// Small SIMT GEMM (poolq / final projection only)
// ---------------------------------------------------------------------------
template<int BM, int BN, int BK, int TM, int TN>
__global__ void __launch_bounds__((BM / TM) * (BN / TN))
gemm_small_kernel(const float* __restrict__ A, const float* __restrict__ Bm,
                  float* __restrict__ C, const float* __restrict__ Res,
                  int M, int Nn, int K, int lda, int ldb, int ldc,
                  float alpha, int resRowMod, int ldres) {
    constexpr int THREADS = (BM / TM) * (BN / TN);
    constexpr int AELEM = BM * BK / THREADS;
    constexpr int BELEM = BK * BN / THREADS;

    __shared__ __align__(16) float As[BK][BM + 4];
    __shared__ __align__(16) float Bs[BK][BN + 4];

    int tid = threadIdx.x;
    int tcol = tid % (BN / TN);
    int trow = tid / (BN / TN);
    int rowBase = blockIdx.y * BM;
    int colBase = blockIdx.x * BN;

    float acc[TM][TN] = {};

    for (int k0 = 0; k0 < K; k0 += BK) {
        #pragma unroll
        for (int e = 0; e < AELEM; e++) {
            int idx = tid + e * THREADS;
            int m = idx / BK, kk = idx % BK;
            int gr = rowBase + m, gc = k0 + kk;
            As[kk][m] = (gr < M && gc < K) ? A[(long)gr * lda + gc] : 0.0f;
        }
        #pragma unroll
        for (int e = 0; e < BELEM; e++) {
            int idx = tid + e * THREADS;
            int kk = idx / BN, n = idx % BN;
            int gc = colBase + n, gk = k0 + kk;
            Bs[kk][n] = (gc < Nn && gk < K) ? Bm[(long)gk * ldb + gc] : 0.0f;
        }
        __syncthreads();

        #pragma unroll
        for (int kk = 0; kk < BK; kk++) {
            float a[TM], bb[TN];
            #pragma unroll
            for (int i = 0; i < TM; i++) a[i] = As[kk][trow * TM + i];
            #pragma unroll
            for (int j = 0; j < TN; j++) bb[j] = Bs[kk][tcol * TN + j];
            #pragma unroll
            for (int i = 0; i < TM; i++)
                #pragma unroll
                for (int j = 0; j < TN; j++)
                    acc[i][j] += a[i] * bb[j];
        }
        __syncthreads();
    }

    #pragma unroll
    for (int i = 0; i < TM; i++) {
        int r = rowBase + trow * TM + i;
        if (r >= M) continue;
        #pragma unroll
        for (int j = 0; j < TN; j++) {
            int c = colBase + tcol * TN + j;
            if (c >= Nn) continue;
            float v = alpha * acc[i][j];
            if (Res) {
                int rr = resRowMod ? (r % resRowMod) : r;
                v += Res[(long)rr * ldres + c];
            }
            C[(long)r * ldc + c] = v;
        }
    }
}

// ---------------------------------------------------------------------------
// Reductions / elementwise
// ---------------------------------------------------------------------------
__device__ __forceinline__ float blk_reduce(float v, bool ismax) {
    __shared__ float red[9];
    #pragma unroll
    for (int o = 16; o; o >>= 1) {
        float u = __shfl_xor_sync(0xffffffffu, v, o);
        v = ismax ? fmaxf(v, u) : (v + u);
    }
    if ((threadIdx.x & 31) == 0) red[threadIdx.x >> 5] = v;
    __syncthreads();
    if (threadIdx.x == 0) {
        float r = red[0];
        int nw = blockDim.x >> 5;
        for (int w = 1; w < nw; w++) r = ismax ? fmaxf(r, red[w]) : (r + red[w]);
        red[8] = r;
    }
    __syncthreads();
    float r = red[8];
    __syncthreads();
    return r;
}

__device__ __forceinline__ int token_type(int j) {
    return j < 512 ? 0 : (j < 1024 ? 1 : 2);
}

// Fused concat + layer-0 LN: writes fp16 residual stream + gamma-scaled LN out.
__global__ void __launch_bounds__(256)
concat_ln_kernel(const float4* __restrict__ m0,
                 const float4* __restrict__ m1,
                 const float4* __restrict__ fus,
                 const float* __restrict__ gamma,
                 __half* __restrict__ tok,
                 __half* __restrict__ out) {
    const int lane = threadIdx.x & 31;
    const long row = (long)blockIdx.x * 8 + (threadIdx.x >> 5);
    const int t = (int)(row % NTOK);
    const int b = (int)(row / NTOK);

    const float4* src;
    if (t < 512)       src = m0 + ((long)b * 512 + t) * (D_ / 4);
    else if (t < 1024) src = m1 + ((long)b * 512 + (t - 512)) * (D_ / 4);
    else               src = fus + (long)(t - 1024) * (D_ / 4);

    float4 v[8];
    float s = 0.f, s2 = 0.f;
    #pragma unroll
    for (int e = 0; e < 8; e++) {
        v[e] = src[lane + e * 32];
        s  += v[e].x + v[e].y + v[e].z + v[e].w;
        s2 += v[e].x * v[e].x + v[e].y * v[e].y
            + v[e].z * v[e].z + v[e].w * v[e].w;
    }
    uint2* tr = (uint2*)(tok + row * D_);
    #pragma unroll
    for (int e = 0; e < 8; e++) {
        uint2 pk;
        pk.x = packh2(v[e].x, v[e].y);
        pk.y = packh2(v[e].z, v[e].w);
        tr[lane + e * 32] = pk;
    }

    #pragma unroll
    for (int o = 16; o; o >>= 1) {
        s  += __shfl_xor_sync(0xffffffffu, s,  o);
        s2 += __shfl_xor_sync(0xffffffffu, s2, o);
    }
    float mu  = s * (1.0f / D_);
    float var = s2 * (1.0f / D_) - mu * mu;
    float inv = rsqrtf(var + 1e-5f);

    uint2* o2 = (uint2*)(out + row * D_);
    const float4* gm = (const float4*)gamma;
    #pragma unroll
    for (int e = 0; e < 8; e++) {
        float4 g = gm[lane + e * 32];
        uint2 pk;
        pk.x = packh2((v[e].x - mu) * inv * g.x, (v[e].y - mu) * inv * g.y);
        pk.y = packh2((v[e].z - mu) * inv * g.z, (v[e].w - mu) * inv * g.w);
        o2[lane + e * 32] = pk;
    }
}

// Warp-per-row LayerNorm over fp16 residual stream (R16 exact).
__global__ void __launch_bounds__(256)
ln_kernel(const __half* __restrict__ x,
          const float* __restrict__ gamma,
          __half* __restrict__ out) {
    const int lane = threadIdx.x & 31;
    const long row = (long)blockIdx.x * 8 + (threadIdx.x >> 5);
    const uint4* xr = (const uint4*)(x + row * D_);

    float f[32];
    float s = 0.f, s2 = 0.f;
    #pragma unroll
    for (int e = 0; e < 4; e++) {
        uint4 v = xr[lane + e * 32];
        const __half2* hp = (const __half2*)&v;
        #pragma unroll
        for (int q = 0; q < 4; q++) {
            float2 t = __half22float2(hp[q]);
            f[e * 8 + 2 * q]     = t.x;
            f[e * 8 + 2 * q + 1] = t.y;
            s  += t.x + t.y;
            s2 += t.x * t.x + t.y * t.y;
        }
    }
    #pragma unroll
    for (int o = 16; o; o >>= 1) {
        s  += __shfl_xor_sync(0xffffffffu, s,  o);
        s2 += __shfl_xor_sync(0xffffffffu, s2, o);
    }
    float mu  = s * (1.0f / D_);
    float var = s2 * (1.0f / D_) - mu * mu;
    float inv = rsqrtf(var + 1e-5f);

    uint4* o4 = (uint4*)(out + row * D_);
    const float4* gm = (const float4*)gamma;
    #pragma unroll
    for (int e = 0; e < 4; e++) {
        float4 g0 = gm[(lane + e * 32) * 2];
        float4 g1 = gm[(lane + e * 32) * 2 + 1];
        uint4 pk;
        pk.x = packh2((f[e*8+0] - mu) * inv * g0.x, (f[e*8+1] - mu) * inv * g0.y);
        pk.y = packh2((f[e*8+2] - mu) * inv * g0.z, (f[e*8+3] - mu) * inv * g0.w);
        pk.z = packh2((f[e*8+4] - mu) * inv * g1.x, (f[e*8+5] - mu) * inv * g1.y);
        pk.w = packh2((f[e*8+6] - mu) * inv * g1.z, (f[e*8+7] - mu) * inv * g1.w);
        o4[lane + e * 32] = pk;
    }
}

// ---------------------------------------------------------------------------
// Fused pool attention: sim + masked softmax + PV, one kernel.
// grid = B*H (64 blocks), 256 threads.
// poolq fp32 [4][1024] (pre-scaled), kv fp16 [B*NTOK][2048], poolao fp32.
// PV phase: (d in 64) x (chunk in 4), 260 coalesced iterations each.
// ---------------------------------------------------------------------------
__global__ void __launch_bounds__(256)
pool_attn_kernel(const float* __restrict__ poolq,
                 const __half* __restrict__ kv,
                 float* __restrict__ poolao) {
    __shared__ float qs[4][64];
    __shared__ float sim[4][NTOK];
    __shared__ float pv[4][4][64];    // [r][chunk][d]

    const int bh = blockIdx.x;
    const int b = bh >> 4, h = bh & 15;
    const int tid = threadIdx.x;

    {
        int r = tid >> 6, d = tid & 63;
        qs[r][d] = poolq[r * D_ + h * 64 + d];
    }
    __syncthreads();

    const __half* kb = kv + (long)b * NTOK * 2048 + h * 64;
    const __half* vb = kb + 1024;

    // scores (each thread handles ~4 j's; per-thread K row read is contiguous)
    for (int j = tid; j < NTOK; j += 256) {
        const __half2* kj = (const __half2*)(kb + (long)j * 2048);
        float a0 = 0.f, a1 = 0.f, a2 = 0.f, a3 = 0.f;
        #pragma unroll
        for (int d2 = 0; d2 < 32; d2++) {
            float2 k2 = __half22float2(kj[d2]);
            a0 += qs[0][2 * d2] * k2.x + qs[0][2 * d2 + 1] * k2.y;
            a1 += qs[1][2 * d2] * k2.x + qs[1][2 * d2 + 1] * k2.y;
            a2 += qs[2][2 * d2] * k2.x + qs[2][2 * d2 + 1] * k2.y;
            a3 += qs[3][2 * d2] * k2.x + qs[3][2 * d2 + 1] * k2.y;
        }
        int tt = token_type(j);
        sim[0][j] = (tt == 0) ? a0 : -1e30f;
        sim[1][j] = (tt == 1) ? a1 : -1e30f;
        sim[2][j] = (tt == 2) ? a2 : -1e30f;
        sim[3][j] = a3;                        // GLOBAL attends all
    }
    __syncthreads();

    // softmax per row (max-subtract; 256-thread block reduce)
    #pragma unroll
    for (int r = 0; r < 4; r++) {
        float mx = -1e30f;
        for (int j = tid; j < NTOK; j += 256) mx = fmaxf(mx, sim[r][j]);
        mx = blk_reduce(mx, true);
        float sum = 0.f;
        for (int j = tid; j < NTOK; j += 256) {
            float e = __expf(sim[r][j] - mx);
            sim[r][j] = e;
            sum += e;
        }
        sum = blk_reduce(sum, false);
        float inv = 1.0f / sum;
        for (int j = tid; j < NTOK; j += 256) sim[r][j] *= inv;
    }
    __syncthreads();

    // PV: thread (d, c); 260 coalesced iterations; 4-way smem reduce
    {
        const int d = tid & 63, c = tid >> 6;
        float a0 = 0.f, a1 = 0.f, a2 = 0.f, a3 = 0.f;
        const __half* vcol = vb + d;
        const int j0 = c * 260;
        #pragma unroll 4
        for (int i = 0; i < 260; i++) {
            int j = j0 + i;
            float v = __half2float(vcol[(long)j * 2048]);
            a0 += sim[0][j] * v;
            a1 += sim[1][j] * v;
            a2 += sim[2][j] * v;
            a3 += sim[3][j] * v;
        }
        pv[0][c][d] = a0; pv[1][c][d] = a1;
        pv[2][c][d] = a2; pv[3][c][d] = a3;
    }
    __syncthreads();
    {
        const int d = tid & 63, r = tid >> 6;   // reuse 256 threads: one (r,d) each
        float s = pv[r][0][d] + pv[r][1][d] + pv[r][2][d] + pv[r][3][d];
        poolao[((long)b * 4 + r) * D_ + h * 64 + d] = s;
    }
}

// ---------------------------------------------------------------------------
// Host side
// ---------------------------------------------------------------------------
static constexpr int SM_H128  = 3 * (128 * 40 + 128 * 40) * 2;   // 61440
static constexpr int SM_FLASH = (64 * 72 + 4 * 128 * 72) * 2;    // 82944

static inline void hg(const __half* A, const __half* Bt, __half* C, const __half* Res,
                      int M, int Nn, int K, int lda, int ldbT, int ldc, float alpha,
                      bool outh, int ldres = 0) {
    dim3 grid((Nn + 127) / 128, (M + 127) / 128, 1);
    if (outh)
        hgemm<true, false><<<grid, 128, SM_H128>>>(
            A, Bt, C, Res, M, Nn, K, lda, ldbT, ldc, alpha, ldres);
    else
        hgemm<false, false><<<grid, 128, SM_H128>>>(
            A, Bt, C, Res, M, Nn, K, lda, ldbT, ldc, alpha, ldres);
}

extern "C" void kernel_launch(void* const* d_in, const int* in_sizes, int n_in,
                              void* d_out, int out_size) {
    const float* m0        = (const float*)d_in[0];
    const float* m1        = (const float*)d_in[1];
    const float* fusion    = (const float*)d_in[2];
    const float* ret_tok   = (const float*)d_in[3];
    const float* ln_gamma  = (const float*)d_in[4];
    const float* wq        = (const float*)d_in[5];
    const float* wkv       = (const float*)d_in[6];
    const float* wo        = (const float*)d_in[7];
    const float* ff_w1     = (const float*)d_in[8];
    const float* ff_w2     = (const float*)d_in[9];
    const float* pool_wq   = (const float*)d_in[10];
    const float* pool_wkv  = (const float*)d_in[11];
    const float* pool_wo   = (const float*)d_in[12];
    const float* final_g   = (const float*)d_in[13];
    float* out = (float*)d_out;

    cudaFuncSetAttribute(hgemm<true, false>,
                         cudaFuncAttributeMaxDynamicSharedMemorySize, SM_H128);
    cudaFuncSetAttribute(hgemm<false, false>,
                         cudaFuncAttributeMaxDynamicSharedMemorySize, SM_H128);
    cudaFuncSetAttribute(hgemm<true, true>,
                         cudaFuncAttributeMaxDynamicSharedMemorySize, SM_H128);
    cudaFuncSetAttribute(flash_kernel,
                         cudaFuncAttributeMaxDynamicSharedMemorySize, SM_FLASH);

    float *poolq, *poolao;
    __half *tok, *hbuf, *qkvbuf, *kvbuf, *aobuf, *actbuf;
    __half *wqkvT, *woT, *ff1T, *ff2T, *pkvT;
    cudaGetSymbolAddress((void**)&poolq,  g_poolq);
    cudaGetSymbolAddress((void**)&poolao, g_poolao);
    cudaGetSymbolAddress((void**)&tok,    h_tok);
    cudaGetSymbolAddress((void**)&hbuf,   h_h);
    cudaGetSymbolAddress((void**)&qkvbuf, h_qkv);
    cudaGetSymbolAddress((void**)&kvbuf,  h_kv);
    cudaGetSymbolAddress((void**)&aobuf,  h_ao);
    cudaGetSymbolAddress((void**)&actbuf, h_act);
    cudaGetSymbolAddress((void**)&wqkvT,  h_wqkvT);
    cudaGetSymbolAddress((void**)&woT,    h_woT);
    cudaGetSymbolAddress((void**)&ff1T,   h_ff1T);
    cudaGetSymbolAddress((void**)&ff2T,   h_ff2T);
    cudaGetSymbolAddress((void**)&pkvT,   h_pkvT);

    const float scale = 0.125f;

    // --- weight pre-transposes (fp32 -> fp16; q-scale folded into wq) ---
    {
        dim3 thr(32, 8);
        const long zq = (long)3 * D_ * D_;
        transpose_kernel<<<dim3(8, 32, 4),   thr>>>(wq,  wqkvT, 1024, 1024, 1024,
                                                    (long)D_ * D_, zq, scale);
        transpose_kernel<<<dim3(16, 32, 4),  thr>>>(wkv, wqkvT + (long)D_ * D_,
                                                    1024, 2048, 1024,
                                                    (long)2 * D_ * D_, zq, 1.0f);
        transpose_kernel<<<dim3(8, 32, 4),   thr>>>(wo, woT, 1024, 1024, 1024,
                                                    (long)D_ * D_, (long)D_ * D_, 1.0f);
        transpose_kernel<<<dim3(43, 32, 4),  thr>>>(ff_w1, ff1T, 1024, 5460, 1024,
                                                    (long)D_ * FF2_, (long)FF2_ * D_, 1.0f);
        transpose_kernel<<<dim3(8, 86, 4),   thr>>>(ff_w2, ff2T, 2730, 1024, ACTLD,
                                                    (long)FF_ * D_, (long)D_ * ACTLD, 1.0f);
        transpose_kernel<<<dim3(16, 32, 1),  thr>>>(pool_wkv, pkvT, 1024, 2048, 1024,
                                                    0, 0, 1.0f);
    }

    // concat fused with layer-0 attention LN (fp16 residual stream)
    concat_ln_kernel<<<ROWS / 8, 256>>>(
        (const float4*)m0, (const float4*)m1, (const float4*)fusion,
        ln_gamma, tok, hbuf);

    for (int l = 0; l < L_; l++) {
        const __half* wqkvT_l = wqkvT + (long)l * 3 * D_ * D_;
        const __half* woT_l   = woT   + (long)l * D_ * D_;
        const __half* w1T_l   = ff1T  + (long)l * FF2_ * D_;
        const __half* w2T_l   = ff2T  + (long)l * D_ * ACTLD;
        const float*  g_l     = ln_gamma + (long)l * D_;

        // attention block (layer 0's LN produced by concat_ln)
        if (l > 0) ln_kernel<<<ROWS / 8, 256>>>(tok, g_l, hbuf);
        hg(hbuf, wqkvT_l, qkvbuf, nullptr, ROWS, 3 * D_, D_, D_, D_, 3 * D_, 1.0f, true);
        flash_kernel<<<dim3(17, 1, B_ * H_), 128, SM_FLASH>>>(qkvbuf, aobuf);
        hg(aobuf, woT_l, tok, tok, ROWS, D_, D_, D_, D_, D_, 1.0f, false, D_);

        // feed-forward block: FF1 + GEGLU fused, FF2 (+fp16 residual)
        ln_kernel<<<ROWS / 8, 256>>>(tok, g_l, hbuf);
        hgemm<true, true><<<dim3(2 * ACTLD / 128, (ROWS + 127) / 128, 1),
                            128, SM_H128>>>(
            hbuf, w1T_l, actbuf, nullptr,
            ROWS, 2 * ACTLD, D_, D_, D_, ACTLD, 1.0f, 0);
        hg(actbuf, w2T_l, tok, tok, ROWS, D_, FF_, ACTLD, ACTLD, D_, 1.0f, false, D_);
    }

    // --- final LN + attention pooling (fused sim/softmax/PV) ---
    ln_kernel<<<ROWS / 8, 256>>>(tok, final_g, hbuf);

    gemm_small_kernel<64, 64, 16, 4, 4><<<dim3(16, 1, 1), 256>>>(
        ret_tok, pool_wq, poolq, nullptr, 4, D_, D_, D_, D_, D_, scale, 0, 0);

    hg(hbuf, pkvT, kvbuf, nullptr, ROWS, 2 * D_, D_, D_, D_, 2 * D_, 1.0f, true);

    pool_attn_kernel<<<B_ * H_, 256>>>(poolq, kvbuf, poolao);

    gemm_small_kernel<64, 64, 16, 4, 4><<<dim3(16, 1, 1), 256>>>(
        poolao, pool_wo, out, ret_tok, B_ * 4, D_, D_, D_, D_, D_, 1.0f,
        /*resRowMod=*/4, /*ldres=*/D_);
}